// round 2
// baseline (speedup 1.0000x reference)
#include <cuda_runtime.h>
#include <cuda_bf16.h>
#include <math.h>

// Problem dims (fixed by dataset)
#define Bb 64
#define Cc 64
#define Dd 512
#define Oo 256
#define NREG 8
#define Gg 8
#define Mrows (Bb*Cc)   // 4096

// Scratch (device globals; no allocation allowed)
__device__ float g_a [Mrows*Dd];
__device__ float g_bp[Mrows*Dd];
__device__ float g_m [Mrows*Dd];
__device__ float g_x1[Mrows*Dd];
__device__ float g_w [Bb*NREG*Gg*Gg];

// ---- packed f32x2 helpers (Blackwell FFMA2: 2 exact fp32 FMAs / instr) ----
__device__ __forceinline__ unsigned long long fma_f32x2(
    unsigned long long a, unsigned long long b, unsigned long long c)
{
    unsigned long long d;
    asm("fma.rn.f32x2 %0, %1, %2, %3;" : "=l"(d) : "l"(a), "l"(b), "l"(c));
    return d;
}
__device__ __forceinline__ float2 unpack2(unsigned long long v)
{
    float2 f;
    asm("mov.b64 {%0, %1}, %2;" : "=f"(f.x), "=f"(f.y) : "l"(v));
    return f;
}

// ---------------------------------------------------------------------------
// SGEMM: C[M,N] = epilogue(A[M,K] @ B[K,N] + bias[N])
// BM=128, BN=64, BK=16, 256 threads, 8x4 microtile via packed f32x2.
// Accumulators packed across row pairs; B duplicated in shared so packed-dup
// B operands are plain 64-bit LDS loads (no mov.b64 in the hot loop).
// MODE 0: + bias; MODE 1: leaky(0.2); MODE 2: 0.5*leaky(z)+0.5*res
// ---------------------------------------------------------------------------
template<int MODE>
__global__ __launch_bounds__(256, 2)
void sgemm_kernel(const float* __restrict__ A, const float* __restrict__ Bm,
                  const float* __restrict__ bias, const float* __restrict__ res,
                  float* __restrict__ C, int M, int N, int K)
{
    constexpr int BM = 128, BN = 64, BK = 16;
    __shared__ float As [BK][BM + 4];
    __shared__ float Bsd[BK][BN * 2];   // duplicated: [.., b,b, ..]

    const int tid = threadIdx.x;
    const int tx = tid & 15;   // col group (4 cols)
    const int ty = tid >> 4;   // row group (8 rows)
    const int row0 = blockIdx.y * BM;
    const int col0 = blockIdx.x * BN;

    // acc[p][j]: p = row pair (rows 2p,2p+1 of this thread), j = col 0..3
    unsigned long long acc[4][4];
    #pragma unroll
    for (int p = 0; p < 4; p++)
        #pragma unroll
        for (int j = 0; j < 4; j++) acc[p][j] = 0ull;

    for (int kt = 0; kt < K; kt += BK) {
        // A tile: 128x16 floats, transposed into As[k][row]
        #pragma unroll
        for (int i = 0; i < 2; i++) {
            int id = tid * 2 + i;
            int r  = id >> 2;
            int kk = (id & 3) << 2;
            float4 v = *(const float4*)(A + (size_t)(row0 + r) * K + kt + kk);
            As[kk + 0][r] = v.x;
            As[kk + 1][r] = v.y;
            As[kk + 2][r] = v.z;
            As[kk + 3][r] = v.w;
        }
        // B tile: 16x64 floats, stored duplicated (each value twice, adjacent)
        {
            int r = tid >> 4;
            int c = (tid & 15) << 2;
            float4 v = *(const float4*)(Bm + (size_t)(kt + r) * N + col0 + c);
            float4 d0 = make_float4(v.x, v.x, v.y, v.y);
            float4 d1 = make_float4(v.z, v.z, v.w, v.w);
            *(float4*)&Bsd[r][2 * c]     = d0;
            *(float4*)&Bsd[r][2 * c + 4] = d1;
        }
        __syncthreads();

        #pragma unroll
        for (int k = 0; k < BK; k++) {
            // packed A row pairs: 4 x 64-bit (rows ty*8 .. ty*8+7)
            ulonglong2 a01 = *(const ulonglong2*)&As[k][ty * 8];
            ulonglong2 a23 = *(const ulonglong2*)&As[k][ty * 8 + 4];
            unsigned long long ap[4] = {a01.x, a01.y, a23.x, a23.y};
            // packed-dup B: 4 x 64-bit (cols tx*4 .. tx*4+3, each dup'd)
            ulonglong2 b01 = *(const ulonglong2*)&Bsd[k][tx * 8];
            ulonglong2 b23 = *(const ulonglong2*)&Bsd[k][tx * 8 + 4];
            unsigned long long bd[4] = {b01.x, b01.y, b23.x, b23.y};
            #pragma unroll
            for (int p = 0; p < 4; p++)
                #pragma unroll
                for (int j = 0; j < 4; j++)
                    acc[p][j] = fma_f32x2(ap[p], bd[j], acc[p][j]);
        }
        __syncthreads();
    }

    // Epilogue: pair p -> rows (2p, 2p+1); lane lo/hi of each acc
    #pragma unroll
    for (int p = 0; p < 4; p++) {
        float2 u[4];
        #pragma unroll
        for (int j = 0; j < 4; j++) u[j] = unpack2(acc[p][j]);
        #pragma unroll
        for (int h = 0; h < 2; h++) {
            int r = row0 + ty * 8 + 2 * p + h;
            int cbase = col0 + tx * 4;
            float4 outv;
            float* o = &outv.x;
            #pragma unroll
            for (int j = 0; j < 4; j++) {
                float v = (h == 0) ? u[j].x : u[j].y;
                int c = cbase + j;
                if (bias) v += bias[c];
                if (MODE >= 1) v = (v >= 0.f) ? v : 0.2f * v;
                if (MODE == 2) v = 0.5f * v + 0.5f * res[(size_t)r * N + c];
                o[j] = v;
            }
            *(float4*)(C + (size_t)r * N + cbase) = outv;
        }
    }
}

// ---------------------------------------------------------------------------
// Attention: per (batch, region) block computes 8x8 masked softmax weights.
// ---------------------------------------------------------------------------
__global__ __launch_bounds__(256)
void attn_kernel(const float* __restrict__ a, const float* __restrict__ bp,
                 const float* __restrict__ W2, const float* __restrict__ b2,
                 const int* __restrict__ ridx, float* __restrict__ wout)
{
    __shared__ float sa[Gg][Dd];
    __shared__ float sb[Gg][Dd];
    __shared__ float sw2[Dd];
    __shared__ float ssc[Gg][Gg];
    __shared__ int   ch[Gg];

    const int tid  = threadIdx.x;
    const int blk  = blockIdx.x;
    const int b    = blk >> 3;
    const int r    = blk & 7;

    if (tid < Gg) ch[tid] = ridx[r * Gg + tid];
    __syncthreads();

    for (int d = tid; d < Dd; d += 256) sw2[d] = W2[d];
    #pragma unroll
    for (int j = 0; j < Gg; j++) {
        const float* arow = a  + (size_t)(b * Cc + ch[j]) * Dd;
        const float* brow = bp + (size_t)(b * Cc + ch[j]) * Dd;
        for (int d = tid; d < Dd; d += 256) {
            sa[j][d] = arow[d];
            sb[j][d] = brow[d];
        }
    }
    __syncthreads();

    const int wid  = tid >> 5;
    const int lane = tid & 31;
    float accq[Gg];
    #pragma unroll
    for (int q = 0; q < Gg; q++) accq[q] = 0.f;
    for (int t = lane; t < Dd; t += 32) {
        float av = sa[wid][t];
        float wv = sw2[t];
        #pragma unroll
        for (int q = 0; q < Gg; q++) {
            float v = av + sb[q][t];
            v = fmaxf(v, 0.f);
            accq[q] = fmaf(v, wv, accq[q]);
        }
    }
    #pragma unroll
    for (int q = 0; q < Gg; q++) {
        #pragma unroll
        for (int off = 16; off > 0; off >>= 1)
            accq[q] += __shfl_xor_sync(0xffffffffu, accq[q], off);
    }
    if (lane == 0) {
        float bb2 = b2[0];
        #pragma unroll
        for (int q = 0; q < Gg; q++) ssc[wid][q] = accq[q] + bb2;
    }
    __syncthreads();

    if (tid < Gg) {
        int i = tid;
        float mx = -1e30f;
        #pragma unroll
        for (int j = 0; j < Gg; j++)
            if (j != i) mx = fmaxf(mx, ssc[i][j]);
        float e[Gg]; float s = 0.f;
        #pragma unroll
        for (int j = 0; j < Gg; j++) {
            e[j] = (j == i) ? 0.f : __expf(ssc[i][j] - mx);
            s += e[j];
        }
        float inv = 1.f / s;
        float* wrow = wout + ((size_t)blk * Gg + i) * Gg;
        #pragma unroll
        for (int j = 0; j < Gg; j++) wrow[j] = e[j] * inv;
    }
}

// ---------------------------------------------------------------------------
// Aggregation: m[b, ch_i, :] = sum_j w[b,r,i,j] * xin[b, ch_j, :]
// ---------------------------------------------------------------------------
__global__ __launch_bounds__(256)
void agg_kernel(const float* __restrict__ w, const float* __restrict__ xin,
                const int* __restrict__ ridx, float* __restrict__ mout)
{
    __shared__ float xs[Gg][Dd];
    __shared__ float ww[Gg * Gg];
    __shared__ int   ch[Gg];

    const int tid = threadIdx.x;
    const int blk = blockIdx.x;
    const int b   = blk >> 3;
    const int r   = blk & 7;

    if (tid < Gg) ch[tid] = ridx[r * Gg + tid];
    if (tid >= 32 && tid < 96) ww[tid - 32] = w[(size_t)blk * 64 + (tid - 32)];
    __syncthreads();

    #pragma unroll
    for (int j = 0; j < Gg; j++) {
        const float* xrow = xin + (size_t)(b * Cc + ch[j]) * Dd;
        for (int d = tid; d < Dd; d += 256) xs[j][d] = xrow[d];
    }
    __syncthreads();

    #pragma unroll
    for (int i = 0; i < Gg; i++) {
        float* orow = mout + (size_t)(b * Cc + ch[i]) * Dd;
        float wi[Gg];
        #pragma unroll
        for (int j = 0; j < Gg; j++) wi[j] = ww[i * Gg + j];
        for (int d = tid; d < Dd; d += 256) {
            float accv = 0.f;
            #pragma unroll
            for (int j = 0; j < Gg; j++) accv = fmaf(wi[j], xs[j][d], accv);
            orow[d] = accv;
        }
    }
}

// ---------------------------------------------------------------------------
extern "C" void kernel_launch(void* const* d_in, const int* in_sizes, int n_in,
                              void* d_out, int out_size)
{
    const float* x    = (const float*)d_in[0];
    const float* W1   = (const float*)d_in[1];
    const float* b1   = (const float*)d_in[2];
    const float* W2   = (const float*)d_in[3];
    const float* b2   = (const float*)d_in[4];
    const float* Wg1  = (const float*)d_in[5];
    const float* bg1  = (const float*)d_in[6];
    const float* Wg2  = (const float*)d_in[7];
    const float* bg2  = (const float*)d_in[8];
    const int*   ridx = (const int*)d_in[9];
    float* out = (float*)d_out;

    float *ga, *gbp, *gm, *gx1, *gw;
    cudaGetSymbolAddress((void**)&ga,  g_a);
    cudaGetSymbolAddress((void**)&gbp, g_bp);
    cudaGetSymbolAddress((void**)&gm,  g_m);
    cudaGetSymbolAddress((void**)&gx1, g_x1);
    cudaGetSymbolAddress((void**)&gw,  g_w);

    dim3 blk(256);

    // G1a: a = x @ W1[:D]          (M=4096, N=512, K=512)
    {
        dim3 grid(Dd / 64, Mrows / 128);
        sgemm_kernel<0><<<grid, blk>>>(x, W1, nullptr, nullptr, ga, Mrows, Dd, Dd);
    }
    // G1b: bp = x @ W1[D:] + b1
    {
        dim3 grid(Dd / 64, Mrows / 128);
        sgemm_kernel<0><<<grid, blk>>>(x, W1 + (size_t)Dd * Dd, b1, nullptr, gbp, Mrows, Dd, Dd);
    }
    // Attention weights
    attn_kernel<<<Bb * NREG, blk>>>(ga, gbp, W2, b2, ridx, gw);
    // m1 = adj @ x
    agg_kernel<<<Bb * NREG, blk>>>(gw, x, ridx, gm);
    // x1 = 0.5*leaky(m1 @ Wg1 + bg1) + 0.5*x
    {
        dim3 grid(Dd / 64, Mrows / 128);
        sgemm_kernel<2><<<grid, blk>>>(gm, Wg1, bg1, x, gx1, Mrows, Dd, Dd);
    }
    // m2 = adj @ x1
    agg_kernel<<<Bb * NREG, blk>>>(gw, gx1, ridx, gm);
    // out = leaky(m2 @ Wg2 + bg2)   (N=256)
    {
        dim3 grid(Oo / 64, Mrows / 128);
        sgemm_kernel<1><<<grid, blk>>>(gm, Wg2, bg2, nullptr, out, Mrows, Oo, Dd);
    }
}

// round 3
// speedup vs baseline: 2.1148x; 2.1148x over previous
#include <cuda_runtime.h>
#include <cuda_bf16.h>
#include <math.h>

// Problem dims (fixed by dataset)
#define Bb 64
#define Cc 64
#define Dd 512
#define Oo 256
#define NREG 8
#define Gg 8
#define Mrows (Bb*Cc)   // 4096

typedef __nv_bfloat16 bf16;

// ---------------- Scratch (device globals) ----------------
__device__ float g_a [Mrows*Dd];        // x @ W1a (fp32, attn input)
__device__ float g_bp[Mrows*Dd];        // x @ W1b + b1
__device__ float g_x1[Mrows*Dd];        // x1 fp32
__device__ float g_w [Bb*NREG*Gg*Gg];   // adj weights

__device__ bf16 g_xhi[Mrows*Dd], g_xlo[Mrows*Dd];   // x split
__device__ bf16 g_mhi[Mrows*Dd], g_mlo[Mrows*Dd];   // agg output split (m1 then m2)
// Transposed+split weights: Wt[N][K]
__device__ bf16 g_w1t_hi[2*Dd*Dd], g_w1t_lo[2*Dd*Dd];   // [0..]: W1a^T, [Dd*Dd..]: W1b^T
__device__ bf16 g_wg1t_hi[Dd*Dd],  g_wg1t_lo[Dd*Dd];
__device__ bf16 g_wg2t_hi[Oo*Dd],  g_wg2t_lo[Oo*Dd];

// ---------------- Conversion kernels ----------------
__global__ void split_kernel(const float* __restrict__ src,
                             bf16* __restrict__ dhi, bf16* __restrict__ dlo, int n)
{
    int i = blockIdx.x * blockDim.x + threadIdx.x;
    int stride = gridDim.x * blockDim.x;
    for (; i < n; i += stride) {
        float v = src[i];
        bf16 h = __float2bfloat16_rn(v);
        float r = v - __bfloat162float(h);
        dhi[i] = h;
        dlo[i] = __float2bfloat16_rn(r);
    }
}

// src [K][N] fp32 row-major -> dst [N][K] bf16 hi/lo
__global__ void splitT_kernel(const float* __restrict__ src,
                              bf16* __restrict__ dhi, bf16* __restrict__ dlo,
                              int K, int N)
{
    int i = blockIdx.x * blockDim.x + threadIdx.x;
    int n = K * N;
    int stride = gridDim.x * blockDim.x;
    for (; i < n; i += stride) {
        int k = i / N, nn = i - k * N;
        float v = src[i];
        bf16 h = __float2bfloat16_rn(v);
        float r = v - __bfloat162float(h);
        dhi[(size_t)nn * K + k] = h;
        dlo[(size_t)nn * K + k] = __float2bfloat16_rn(r);
    }
}

// ---------------- split-bf16 tensor-core GEMM ----------------
// C[M,N] = epi(Ahi/lo[M,K] @ (Bt hi/lo[N,K])^T + bias[N])
// MODE 0: +bias; MODE 1: leaky(0.2); MODE 2: 0.5*leaky(z)+0.5*res
__device__ __forceinline__ void mma_bf16(float c[4],
    unsigned a0, unsigned a1, unsigned a2, unsigned a3,
    unsigned b0, unsigned b1)
{
    asm volatile(
        "mma.sync.aligned.m16n8k16.row.col.f32.bf16.bf16.f32 "
        "{%0,%1,%2,%3}, {%4,%5,%6,%7}, {%8,%9}, {%0,%1,%2,%3};\n"
        : "+f"(c[0]), "+f"(c[1]), "+f"(c[2]), "+f"(c[3])
        : "r"(a0), "r"(a1), "r"(a2), "r"(a3), "r"(b0), "r"(b1));
}

template<int MODE>
__global__ __launch_bounds__(256, 2)
void mgemm_kernel(const bf16* __restrict__ Ahi, const bf16* __restrict__ Alo,
                  const bf16* __restrict__ Bth, const bf16* __restrict__ Btl,
                  const float* __restrict__ bias, const float* __restrict__ res,
                  float* __restrict__ C, int M, int N, int K)
{
    constexpr int BM = 128, BN = 64, BK = 32;
    constexpr int LDS = 40;  // bf16 units (stride 80B = 20 words: conflict-free)
    __shared__ bf16 sAh[BM][LDS], sAl[BM][LDS];
    __shared__ bf16 sBh[BN][LDS], sBl[BN][LDS];

    const int tid  = threadIdx.x;
    const int wid  = tid >> 5;
    const int lane = tid & 31;
    const int wm   = wid & 3;        // 4 warp-rows
    const int wn   = wid >> 2;       // 2 warp-cols
    const int row0 = blockIdx.y * BM;
    const int col0 = blockIdx.x * BN;
    const int g = lane >> 2;
    const int t = lane & 3;

    float acc[2][4][4];
    #pragma unroll
    for (int mt = 0; mt < 2; mt++)
        #pragma unroll
        for (int nt = 0; nt < 4; nt++)
            #pragma unroll
            for (int q = 0; q < 4; q++) acc[mt][nt][q] = 0.f;

    for (int kt = 0; kt < K; kt += BK) {
        // A tile: 128 x 32 bf16, 16B chunks (2 per thread) for hi and lo
        #pragma unroll
        for (int i = 0; i < 2; i++) {
            int id  = tid * 2 + i;
            int r   = id >> 2;
            int c16 = (id & 3) * 8;
            size_t goff = (size_t)(row0 + r) * K + kt + c16;
            *(uint4*)&sAh[r][c16] = *(const uint4*)(Ahi + goff);
            *(uint4*)&sAl[r][c16] = *(const uint4*)(Alo + goff);
        }
        // B tile: 64 x 32 bf16 (already transposed in global: [N][K])
        {
            int r   = tid >> 2;
            int c16 = (tid & 3) * 8;
            size_t goff = (size_t)(col0 + r) * K + kt + c16;
            *(uint4*)&sBh[r][c16] = *(const uint4*)(Bth + goff);
            *(uint4*)&sBl[r][c16] = *(const uint4*)(Btl + goff);
        }
        __syncthreads();

        #pragma unroll
        for (int kk = 0; kk < BK; kk += 16) {
            unsigned ah[2][4], al[2][4], bh[4][2], bl[4][2];
            #pragma unroll
            for (int mt = 0; mt < 2; mt++) {
                int r = wm * 32 + mt * 16 + g;
                ah[mt][0] = *(const unsigned*)&sAh[r    ][kk + 2*t];
                ah[mt][1] = *(const unsigned*)&sAh[r + 8][kk + 2*t];
                ah[mt][2] = *(const unsigned*)&sAh[r    ][kk + 2*t + 8];
                ah[mt][3] = *(const unsigned*)&sAh[r + 8][kk + 2*t + 8];
                al[mt][0] = *(const unsigned*)&sAl[r    ][kk + 2*t];
                al[mt][1] = *(const unsigned*)&sAl[r + 8][kk + 2*t];
                al[mt][2] = *(const unsigned*)&sAl[r    ][kk + 2*t + 8];
                al[mt][3] = *(const unsigned*)&sAl[r + 8][kk + 2*t + 8];
            }
            #pragma unroll
            for (int nt = 0; nt < 4; nt++) {
                int c = wn * 32 + nt * 8 + g;
                bh[nt][0] = *(const unsigned*)&sBh[c][kk + 2*t];
                bh[nt][1] = *(const unsigned*)&sBh[c][kk + 2*t + 8];
                bl[nt][0] = *(const unsigned*)&sBl[c][kk + 2*t];
                bl[nt][1] = *(const unsigned*)&sBl[c][kk + 2*t + 8];
            }
            #pragma unroll
            for (int mt = 0; mt < 2; mt++)
                #pragma unroll
                for (int nt = 0; nt < 4; nt++) {
                    mma_bf16(acc[mt][nt], ah[mt][0], ah[mt][1], ah[mt][2], ah[mt][3],
                             bh[nt][0], bh[nt][1]);
                    mma_bf16(acc[mt][nt], ah[mt][0], ah[mt][1], ah[mt][2], ah[mt][3],
                             bl[nt][0], bl[nt][1]);
                    mma_bf16(acc[mt][nt], al[mt][0], al[mt][1], al[mt][2], al[mt][3],
                             bh[nt][0], bh[nt][1]);
                }
        }
        __syncthreads();
    }

    // Epilogue
    #pragma unroll
    for (int mt = 0; mt < 2; mt++) {
        int rbase = row0 + wm * 32 + mt * 16;
        #pragma unroll
        for (int nt = 0; nt < 4; nt++) {
            int cb = col0 + wn * 32 + nt * 8 + 2 * t;
            float bia0 = bias ? bias[cb]     : 0.f;
            float bia1 = bias ? bias[cb + 1] : 0.f;
            #pragma unroll
            for (int h = 0; h < 2; h++) {
                int r = rbase + g + 8 * h;
                float v0 = acc[mt][nt][2*h]     + bia0;
                float v1 = acc[mt][nt][2*h + 1] + bia1;
                if (MODE >= 1) {
                    v0 = (v0 >= 0.f) ? v0 : 0.2f * v0;
                    v1 = (v1 >= 0.f) ? v1 : 0.2f * v1;
                }
                if (MODE == 2) {
                    const float* rr = res + (size_t)r * N + cb;
                    v0 = 0.5f * v0 + 0.5f * rr[0];
                    v1 = 0.5f * v1 + 0.5f * rr[1];
                }
                *(float2*)(C + (size_t)r * N + cb) = make_float2(v0, v1);
            }
        }
    }
}

// ---------------------------------------------------------------------------
// Attention: per (batch, region) block computes 8x8 masked softmax weights.
// ---------------------------------------------------------------------------
__global__ __launch_bounds__(256)
void attn_kernel(const float* __restrict__ a, const float* __restrict__ bp,
                 const float* __restrict__ W2, const float* __restrict__ b2,
                 const int* __restrict__ ridx, float* __restrict__ wout)
{
    __shared__ float sa[Gg][Dd];
    __shared__ float sb[Gg][Dd];
    __shared__ float sw2[Dd];
    __shared__ float ssc[Gg][Gg];
    __shared__ int   ch[Gg];

    const int tid  = threadIdx.x;
    const int blk  = blockIdx.x;
    const int b    = blk >> 3;
    const int r    = blk & 7;

    if (tid < Gg) ch[tid] = ridx[r * Gg + tid];
    __syncthreads();

    for (int d = tid; d < Dd; d += 256) sw2[d] = W2[d];
    #pragma unroll
    for (int j = 0; j < Gg; j++) {
        const float* arow = a  + (size_t)(b * Cc + ch[j]) * Dd;
        const float* brow = bp + (size_t)(b * Cc + ch[j]) * Dd;
        for (int d = tid; d < Dd; d += 256) {
            sa[j][d] = arow[d];
            sb[j][d] = brow[d];
        }
    }
    __syncthreads();

    const int wid  = tid >> 5;
    const int lane = tid & 31;
    float accq[Gg];
    #pragma unroll
    for (int q = 0; q < Gg; q++) accq[q] = 0.f;
    for (int t = lane; t < Dd; t += 32) {
        float av = sa[wid][t];
        float wv = sw2[t];
        #pragma unroll
        for (int q = 0; q < Gg; q++) {
            float v = av + sb[q][t];
            v = fmaxf(v, 0.f);
            accq[q] = fmaf(v, wv, accq[q]);
        }
    }
    #pragma unroll
    for (int q = 0; q < Gg; q++) {
        #pragma unroll
        for (int off = 16; off > 0; off >>= 1)
            accq[q] += __shfl_xor_sync(0xffffffffu, accq[q], off);
    }
    if (lane == 0) {
        float bb2 = b2[0];
        #pragma unroll
        for (int q = 0; q < Gg; q++) ssc[wid][q] = accq[q] + bb2;
    }
    __syncthreads();

    if (tid < Gg) {
        int i = tid;
        float mx = -1e30f;
        #pragma unroll
        for (int j = 0; j < Gg; j++)
            if (j != i) mx = fmaxf(mx, ssc[i][j]);
        float e[Gg]; float s = 0.f;
        #pragma unroll
        for (int j = 0; j < Gg; j++) {
            e[j] = (j == i) ? 0.f : __expf(ssc[i][j] - mx);
            s += e[j];
        }
        float inv = 1.f / s;
        float* wrow = wout + ((size_t)blk * Gg + i) * Gg;
        #pragma unroll
        for (int j = 0; j < Gg; j++) wrow[j] = e[j] * inv;
    }
}

// ---------------------------------------------------------------------------
// Aggregation: m[b, ch_i, :] = sum_j w[b,r,i,j]*xin[b, ch_j, :]; writes hi/lo bf16
// ---------------------------------------------------------------------------
__global__ __launch_bounds__(256)
void agg_kernel(const float* __restrict__ w, const float* __restrict__ xin,
                const int* __restrict__ ridx,
                bf16* __restrict__ mhi, bf16* __restrict__ mlo)
{
    __shared__ float xs[Gg][Dd];
    __shared__ float ww[Gg * Gg];
    __shared__ int   ch[Gg];

    const int tid = threadIdx.x;
    const int blk = blockIdx.x;
    const int b   = blk >> 3;
    const int r   = blk & 7;

    if (tid < Gg) ch[tid] = ridx[r * Gg + tid];
    if (tid >= 32 && tid < 96) ww[tid - 32] = w[(size_t)blk * 64 + (tid - 32)];
    __syncthreads();

    #pragma unroll
    for (int j = 0; j < Gg; j++) {
        const float* xrow = xin + (size_t)(b * Cc + ch[j]) * Dd;
        for (int d = tid; d < Dd; d += 256) xs[j][d] = xrow[d];
    }
    __syncthreads();

    #pragma unroll
    for (int i = 0; i < Gg; i++) {
        size_t obase = (size_t)(b * Cc + ch[i]) * Dd;
        float wi[Gg];
        #pragma unroll
        for (int j = 0; j < Gg; j++) wi[j] = ww[i * Gg + j];
        for (int d = tid; d < Dd; d += 256) {
            float accv = 0.f;
            #pragma unroll
            for (int j = 0; j < Gg; j++) accv = fmaf(wi[j], xs[j][d], accv);
            bf16 h = __float2bfloat16_rn(accv);
            mhi[obase + d] = h;
            mlo[obase + d] = __float2bfloat16_rn(accv - __bfloat162float(h));
        }
    }
}

// ---------------------------------------------------------------------------
extern "C" void kernel_launch(void* const* d_in, const int* in_sizes, int n_in,
                              void* d_out, int out_size)
{
    const float* x    = (const float*)d_in[0];
    const float* W1   = (const float*)d_in[1];
    const float* b1   = (const float*)d_in[2];
    const float* W2   = (const float*)d_in[3];
    const float* b2   = (const float*)d_in[4];
    const float* Wg1  = (const float*)d_in[5];
    const float* bg1  = (const float*)d_in[6];
    const float* Wg2  = (const float*)d_in[7];
    const float* bg2  = (const float*)d_in[8];
    const int*   ridx = (const int*)d_in[9];
    float* out = (float*)d_out;

    float *ga, *gbp, *gx1, *gw;
    bf16 *xhi, *xlo, *mhi, *mlo;
    bf16 *w1th, *w1tl, *wg1th, *wg1tl, *wg2th, *wg2tl;
    cudaGetSymbolAddress((void**)&ga,   g_a);
    cudaGetSymbolAddress((void**)&gbp,  g_bp);
    cudaGetSymbolAddress((void**)&gx1,  g_x1);
    cudaGetSymbolAddress((void**)&gw,   g_w);
    cudaGetSymbolAddress((void**)&xhi,  g_xhi);
    cudaGetSymbolAddress((void**)&xlo,  g_xlo);
    cudaGetSymbolAddress((void**)&mhi,  g_mhi);
    cudaGetSymbolAddress((void**)&mlo,  g_mlo);
    cudaGetSymbolAddress((void**)&w1th, g_w1t_hi);
    cudaGetSymbolAddress((void**)&w1tl, g_w1t_lo);
    cudaGetSymbolAddress((void**)&wg1th, g_wg1t_hi);
    cudaGetSymbolAddress((void**)&wg1tl, g_wg1t_lo);
    cudaGetSymbolAddress((void**)&wg2th, g_wg2t_hi);
    cudaGetSymbolAddress((void**)&wg2tl, g_wg2t_lo);

    dim3 blk(256);

    // Conversions
    split_kernel<<<512, 256>>>(x, xhi, xlo, Mrows * Dd);
    splitT_kernel<<<256, 256>>>(W1,                   w1th,          w1tl,          Dd, Dd); // W1a^T
    splitT_kernel<<<256, 256>>>(W1 + (size_t)Dd * Dd, w1th + Dd*Dd,  w1tl + Dd*Dd,  Dd, Dd); // W1b^T
    splitT_kernel<<<256, 256>>>(Wg1, wg1th, wg1tl, Dd, Dd);
    splitT_kernel<<<128, 256>>>(Wg2, wg2th, wg2tl, Dd, Oo);

    // G1a: a = x @ W1a
    {
        dim3 grid(Dd / 64, Mrows / 128);
        mgemm_kernel<0><<<grid, blk>>>(xhi, xlo, w1th, w1tl, nullptr, nullptr, ga, Mrows, Dd, Dd);
    }
    // G1b: bp = x @ W1b + b1
    {
        dim3 grid(Dd / 64, Mrows / 128);
        mgemm_kernel<0><<<grid, blk>>>(xhi, xlo, w1th + (size_t)Dd*Dd, w1tl + (size_t)Dd*Dd, b1, nullptr, gbp, Mrows, Dd, Dd);
    }
    // Attention weights
    attn_kernel<<<Bb * NREG, blk>>>(ga, gbp, W2, b2, ridx, gw);
    // m1 = adj @ x  (hi/lo)
    agg_kernel<<<Bb * NREG, blk>>>(gw, x, ridx, mhi, mlo);
    // x1 = 0.5*leaky(m1 @ Wg1 + bg1) + 0.5*x   (fp32)
    {
        dim3 grid(Dd / 64, Mrows / 128);
        mgemm_kernel<2><<<grid, blk>>>(mhi, mlo, wg1th, wg1tl, bg1, x, gx1, Mrows, Dd, Dd);
    }
    // m2 = adj @ x1  (hi/lo)
    agg_kernel<<<Bb * NREG, blk>>>(gw, gx1, ridx, mhi, mlo);
    // out = leaky(m2 @ Wg2 + bg2)   (N=256)
    {
        dim3 grid(Oo / 64, Mrows / 128);
        mgemm_kernel<1><<<grid, blk>>>(mhi, mlo, wg2th, wg2tl, bg2, nullptr, out, Mrows, Oo, Dd);
    }
}

// round 4
// speedup vs baseline: 2.5466x; 1.2042x over previous
#include <cuda_runtime.h>
#include <cuda_bf16.h>
#include <math.h>

#define Bb 64
#define Cc 64
#define Dd 512
#define Oo 256
#define NREG 8
#define Gg 8
#define Mrows (Bb*Cc)   // 4096

typedef __nv_bfloat16 bf16;

// ---------------- Scratch (device globals) ----------------
__device__ float g_a [Mrows*Dd];
__device__ float g_bp[Mrows*Dd];
__device__ float g_x1[Mrows*Dd];
__device__ float g_w [Bb*NREG*Gg*Gg];

__device__ bf16 g_xhi[Mrows*Dd], g_xlo[Mrows*Dd];
__device__ bf16 g_mhi[Mrows*Dd], g_mlo[Mrows*Dd];
__device__ bf16 g_w1t_hi[2*Dd*Dd], g_w1t_lo[2*Dd*Dd];   // W1a^T then W1b^T, [n][k]
__device__ bf16 g_wg1t_hi[Dd*Dd],  g_wg1t_lo[Dd*Dd];
__device__ bf16 g_wg2t_hi[Oo*Dd],  g_wg2t_lo[Oo*Dd];

// ---------------- cp.async helpers ----------------
__device__ __forceinline__ void cpasync16(void* smem, const void* g)
{
    unsigned sa = (unsigned)__cvta_generic_to_shared(smem);
    asm volatile("cp.async.cg.shared.global [%0], [%1], 16;" :: "r"(sa), "l"(g));
}
__device__ __forceinline__ void cp_commit() { asm volatile("cp.async.commit_group;"); }
template<int N> __device__ __forceinline__ void cp_wait()
{
    asm volatile("cp.async.wait_group %0;" :: "n"(N));
}

// ---------------- Conversion kernels ----------------
// x -> hi/lo, vectorized (float4 in, bf16x2 packed out)
__global__ void split_kernel(const float4* __restrict__ src,
                             uint2* __restrict__ dhi, uint2* __restrict__ dlo, int n4)
{
    int i = blockIdx.x * blockDim.x + threadIdx.x;
    int stride = gridDim.x * blockDim.x;
    for (; i < n4; i += stride) {
        float4 v = src[i];
        bf16 h0 = __float2bfloat16_rn(v.x), h1 = __float2bfloat16_rn(v.y);
        bf16 h2 = __float2bfloat16_rn(v.z), h3 = __float2bfloat16_rn(v.w);
        bf16 l0 = __float2bfloat16_rn(v.x - __bfloat162float(h0));
        bf16 l1 = __float2bfloat16_rn(v.y - __bfloat162float(h1));
        bf16 l2 = __float2bfloat16_rn(v.z - __bfloat162float(h2));
        bf16 l3 = __float2bfloat16_rn(v.w - __bfloat162float(h3));
        __nv_bfloat162 ph0 = __halves2bfloat162(h0, h1), ph1 = __halves2bfloat162(h2, h3);
        __nv_bfloat162 pl0 = __halves2bfloat162(l0, l1), pl1 = __halves2bfloat162(l2, l3);
        dhi[i] = make_uint2(*(unsigned*)&ph0, *(unsigned*)&ph1);
        dlo[i] = make_uint2(*(unsigned*)&pl0, *(unsigned*)&pl1);
    }
}

// src [K][N] fp32 row-major -> dst [N][K] bf16 hi/lo; 32x32 shared tiles
__global__ __launch_bounds__(256)
void splitT_kernel(const float* __restrict__ src,
                   bf16* __restrict__ dhi, bf16* __restrict__ dlo, int K, int N)
{
    __shared__ float tile[32][33];
    const int tid = threadIdx.x;
    const int k0 = blockIdx.y * 32;
    const int n0 = blockIdx.x * 32;
    const int tx = tid & 31, ty = tid >> 5;   // 32 cols x 8 rows per pass
    #pragma unroll
    for (int i = 0; i < 4; i++)
        tile[ty + 8 * i][tx] = src[(size_t)(k0 + ty + 8 * i) * N + n0 + tx];
    __syncthreads();
    // write transposed: 16 (tid>>4) rows x 16 pairs, two passes
    const int nr = tid >> 4;         // 0..15
    const int kp = tid & 15;         // pair index
    #pragma unroll
    for (int i = 0; i < 2; i++) {
        int n = n0 + nr + 16 * i;
        float v0 = tile[2 * kp    ][nr + 16 * i];
        float v1 = tile[2 * kp + 1][nr + 16 * i];
        bf16 h0 = __float2bfloat16_rn(v0), h1 = __float2bfloat16_rn(v1);
        bf16 l0 = __float2bfloat16_rn(v0 - __bfloat162float(h0));
        bf16 l1 = __float2bfloat16_rn(v1 - __bfloat162float(h1));
        __nv_bfloat162 ph = __halves2bfloat162(h0, h1);
        __nv_bfloat162 pl = __halves2bfloat162(l0, l1);
        *(__nv_bfloat162*)&dhi[(size_t)n * K + k0 + 2 * kp] = ph;
        *(__nv_bfloat162*)&dlo[(size_t)n * K + k0 + 2 * kp] = pl;
    }
}

// ---------------- split-bf16 tensor-core GEMM, double-buffered cp.async ----
__device__ __forceinline__ void mma_bf16(float c[4],
    unsigned a0, unsigned a1, unsigned a2, unsigned a3,
    unsigned b0, unsigned b1)
{
    asm volatile(
        "mma.sync.aligned.m16n8k16.row.col.f32.bf16.bf16.f32 "
        "{%0,%1,%2,%3}, {%4,%5,%6,%7}, {%8,%9}, {%0,%1,%2,%3};\n"
        : "+f"(c[0]), "+f"(c[1]), "+f"(c[2]), "+f"(c[3])
        : "r"(a0), "r"(a1), "r"(a2), "r"(a3), "r"(b0), "r"(b1));
}

// MODE 0: +bias
// MODE 1: leaky(0.2)+bias
// MODE 2: 0.5*leaky(z+bias)+0.5*res
// MODE 3: dual output: n<Dd -> C; n>=Dd -> C2 with bias[n-Dd]
template<int MODE>
__global__ __launch_bounds__(256, 2)
void mgemm_kernel(const bf16* __restrict__ Ahi, const bf16* __restrict__ Alo,
                  const bf16* __restrict__ Bth, const bf16* __restrict__ Btl,
                  const float* __restrict__ bias, const float* __restrict__ res,
                  float* __restrict__ C, float* __restrict__ C2,
                  int M, int N, int K)
{
    constexpr int BM = 128, BN = 64, BK = 16;
    constexpr int LDT = 24;  // bf16 stride: conflict-free fragment LDS
    __shared__ bf16 sAh[2][BM][LDT], sAl[2][BM][LDT];
    __shared__ bf16 sBh[2][BN][LDT], sBl[2][BN][LDT];

    const int tid  = threadIdx.x;
    const int wid  = tid >> 5;
    const int lane = tid & 31;
    const int wm   = wid & 3;
    const int wn   = wid >> 2;
    const int row0 = blockIdx.y * BM;
    const int col0 = blockIdx.x * BN;
    const int g = lane >> 2;
    const int t = lane & 3;

    // load indices
    const int ar = tid >> 1, ac = (tid & 1) * 8;          // A: 128 rows x 2 chunks
    const int br = (tid & 127) >> 1, bc = (tid & 1) * 8;  // B: 64 rows x 2 chunks
    const bool bhi = (tid < 128);

    float acc[2][4][4];
    #pragma unroll
    for (int mt = 0; mt < 2; mt++)
        #pragma unroll
        for (int nt = 0; nt < 4; nt++)
            #pragma unroll
            for (int q = 0; q < 4; q++) acc[mt][nt][q] = 0.f;

    auto load_stage = [&](int st, int kt) {
        cpasync16(&sAh[st][ar][ac], Ahi + (size_t)(row0 + ar) * K + kt + ac);
        cpasync16(&sAl[st][ar][ac], Alo + (size_t)(row0 + ar) * K + kt + ac);
        if (bhi) cpasync16(&sBh[st][br][bc], Bth + (size_t)(col0 + br) * K + kt + bc);
        else     cpasync16(&sBl[st][br][bc], Btl + (size_t)(col0 + br) * K + kt + bc);
    };

    const int nk = K / BK;
    load_stage(0, 0);
    cp_commit();

    for (int s = 0; s < nk; s++) {
        if (s + 1 < nk) {
            load_stage((s + 1) & 1, (s + 1) * BK);
            cp_commit();
            cp_wait<1>();
        } else {
            cp_wait<0>();
        }
        __syncthreads();

        const int st = s & 1;
        unsigned ah[2][4], al[2][4], bh[4][2], bl[4][2];
        #pragma unroll
        for (int mt = 0; mt < 2; mt++) {
            int r = wm * 32 + mt * 16 + g;
            ah[mt][0] = *(const unsigned*)&sAh[st][r    ][2*t];
            ah[mt][1] = *(const unsigned*)&sAh[st][r + 8][2*t];
            ah[mt][2] = *(const unsigned*)&sAh[st][r    ][2*t + 8];
            ah[mt][3] = *(const unsigned*)&sAh[st][r + 8][2*t + 8];
            al[mt][0] = *(const unsigned*)&sAl[st][r    ][2*t];
            al[mt][1] = *(const unsigned*)&sAl[st][r + 8][2*t];
            al[mt][2] = *(const unsigned*)&sAl[st][r    ][2*t + 8];
            al[mt][3] = *(const unsigned*)&sAl[st][r + 8][2*t + 8];
        }
        #pragma unroll
        for (int nt = 0; nt < 4; nt++) {
            int c = wn * 32 + nt * 8 + g;
            bh[nt][0] = *(const unsigned*)&sBh[st][c][2*t];
            bh[nt][1] = *(const unsigned*)&sBh[st][c][2*t + 8];
            bl[nt][0] = *(const unsigned*)&sBl[st][c][2*t];
            bl[nt][1] = *(const unsigned*)&sBl[st][c][2*t + 8];
        }
        #pragma unroll
        for (int mt = 0; mt < 2; mt++)
            #pragma unroll
            for (int nt = 0; nt < 4; nt++) {
                mma_bf16(acc[mt][nt], ah[mt][0], ah[mt][1], ah[mt][2], ah[mt][3],
                         bh[nt][0], bh[nt][1]);
                mma_bf16(acc[mt][nt], ah[mt][0], ah[mt][1], ah[mt][2], ah[mt][3],
                         bl[nt][0], bl[nt][1]);
                mma_bf16(acc[mt][nt], al[mt][0], al[mt][1], al[mt][2], al[mt][3],
                         bh[nt][0], bh[nt][1]);
            }
        __syncthreads();
    }

    // Epilogue
    #pragma unroll
    for (int mt = 0; mt < 2; mt++) {
        int rbase = row0 + wm * 32 + mt * 16;
        #pragma unroll
        for (int nt = 0; nt < 4; nt++) {
            int cb = col0 + wn * 32 + nt * 8 + 2 * t;
            #pragma unroll
            for (int h = 0; h < 2; h++) {
                int r = rbase + g + 8 * h;
                float v0 = acc[mt][nt][2*h];
                float v1 = acc[mt][nt][2*h + 1];
                if (MODE == 3) {
                    if (cb < Dd) {
                        *(float2*)(C + (size_t)r * Dd + cb) = make_float2(v0, v1);
                    } else {
                        int c2 = cb - Dd;
                        v0 += bias[c2]; v1 += bias[c2 + 1];
                        *(float2*)(C2 + (size_t)r * Dd + c2) = make_float2(v0, v1);
                    }
                } else {
                    if (bias) { v0 += bias[cb]; v1 += bias[cb + 1]; }
                    if (MODE >= 1) {
                        v0 = (v0 >= 0.f) ? v0 : 0.2f * v0;
                        v1 = (v1 >= 0.f) ? v1 : 0.2f * v1;
                    }
                    if (MODE == 2) {
                        const float* rr = res + (size_t)r * N + cb;
                        v0 = 0.5f * v0 + 0.5f * rr[0];
                        v1 = 0.5f * v1 + 0.5f * rr[1];
                    }
                    *(float2*)(C + (size_t)r * N + cb) = make_float2(v0, v1);
                }
            }
        }
    }
}

// ---------------------------------------------------------------------------
// Attention: per (batch, region) block computes 8x8 masked softmax weights.
// ---------------------------------------------------------------------------
__global__ __launch_bounds__(256)
void attn_kernel(const float* __restrict__ a, const float* __restrict__ bp,
                 const float* __restrict__ W2, const float* __restrict__ b2,
                 const int* __restrict__ ridx, float* __restrict__ wout)
{
    __shared__ float sa[Gg][Dd];
    __shared__ float sb[Gg][Dd];
    __shared__ float sw2[Dd];
    __shared__ float ssc[Gg][Gg];
    __shared__ int   ch[Gg];

    const int tid  = threadIdx.x;
    const int blk  = blockIdx.x;
    const int b    = blk >> 3;
    const int r    = blk & 7;

    if (tid < Gg) ch[tid] = ridx[r * Gg + tid];
    __syncthreads();

    for (int d = tid; d < Dd; d += 256) sw2[d] = W2[d];
    #pragma unroll
    for (int j = 0; j < Gg; j++) {
        const float* arow = a  + (size_t)(b * Cc + ch[j]) * Dd;
        const float* brow = bp + (size_t)(b * Cc + ch[j]) * Dd;
        for (int d = tid; d < Dd; d += 256) {
            sa[j][d] = arow[d];
            sb[j][d] = brow[d];
        }
    }
    __syncthreads();

    const int wid  = tid >> 5;
    const int lane = tid & 31;
    float accq[Gg];
    #pragma unroll
    for (int q = 0; q < Gg; q++) accq[q] = 0.f;
    for (int t = lane; t < Dd; t += 32) {
        float av = sa[wid][t];
        float wv = sw2[t];
        #pragma unroll
        for (int q = 0; q < Gg; q++) {
            float v = av + sb[q][t];
            v = fmaxf(v, 0.f);
            accq[q] = fmaf(v, wv, accq[q]);
        }
    }
    #pragma unroll
    for (int q = 0; q < Gg; q++) {
        #pragma unroll
        for (int off = 16; off > 0; off >>= 1)
            accq[q] += __shfl_xor_sync(0xffffffffu, accq[q], off);
    }
    if (lane == 0) {
        float bb2 = b2[0];
        #pragma unroll
        for (int q = 0; q < Gg; q++) ssc[wid][q] = accq[q] + bb2;
    }
    __syncthreads();

    if (tid < Gg) {
        int i = tid;
        float mx = -1e30f;
        #pragma unroll
        for (int j = 0; j < Gg; j++)
            if (j != i) mx = fmaxf(mx, ssc[i][j]);
        float e[Gg]; float s = 0.f;
        #pragma unroll
        for (int j = 0; j < Gg; j++) {
            e[j] = (j == i) ? 0.f : __expf(ssc[i][j] - mx);
            s += e[j];
        }
        float inv = 1.f / s;
        float* wrow = wout + ((size_t)blk * Gg + i) * Gg;
        #pragma unroll
        for (int j = 0; j < Gg; j++) wrow[j] = e[j] * inv;
    }
}

// ---------------------------------------------------------------------------
// Aggregation: m[b, ch_i, dbase+tid] = sum_j w[b,r,i,j]*xin[b, ch_j, dbase+tid]
// grid (512, Dd/256); writes hi/lo bf16
// ---------------------------------------------------------------------------
__global__ __launch_bounds__(256)
void agg_kernel(const float* __restrict__ w, const float* __restrict__ xin,
                const int* __restrict__ ridx,
                bf16* __restrict__ mhi, bf16* __restrict__ mlo)
{
    __shared__ float xs[Gg][256];
    __shared__ float ww[Gg * Gg];
    __shared__ int   ch[Gg];

    const int tid = threadIdx.x;
    const int blk = blockIdx.x;
    const int b   = blk >> 3;
    const int r   = blk & 7;
    const int dbase = blockIdx.y * 256;

    if (tid < Gg) ch[tid] = ridx[r * Gg + tid];
    if (tid >= 32 && tid < 96) ww[tid - 32] = w[(size_t)blk * 64 + (tid - 32)];
    __syncthreads();

    #pragma unroll
    for (int j = 0; j < Gg; j++)
        xs[j][tid] = xin[(size_t)(b * Cc + ch[j]) * Dd + dbase + tid];
    __syncthreads();

    #pragma unroll
    for (int i = 0; i < Gg; i++) {
        size_t o = (size_t)(b * Cc + ch[i]) * Dd + dbase + tid;
        float accv = 0.f;
        #pragma unroll
        for (int j = 0; j < Gg; j++) accv = fmaf(ww[i * Gg + j], xs[j][tid], accv);
        bf16 h = __float2bfloat16_rn(accv);
        mhi[o] = h;
        mlo[o] = __float2bfloat16_rn(accv - __bfloat162float(h));
    }
}

// ---------------------------------------------------------------------------
extern "C" void kernel_launch(void* const* d_in, const int* in_sizes, int n_in,
                              void* d_out, int out_size)
{
    const float* x    = (const float*)d_in[0];
    const float* W1   = (const float*)d_in[1];
    const float* b1   = (const float*)d_in[2];
    const float* W2   = (const float*)d_in[3];
    const float* b2   = (const float*)d_in[4];
    const float* Wg1  = (const float*)d_in[5];
    const float* bg1  = (const float*)d_in[6];
    const float* Wg2  = (const float*)d_in[7];
    const float* bg2  = (const float*)d_in[8];
    const int*   ridx = (const int*)d_in[9];
    float* out = (float*)d_out;

    float *ga, *gbp, *gx1, *gw;
    bf16 *xhi, *xlo, *mhi, *mlo;
    bf16 *w1th, *w1tl, *wg1th, *wg1tl, *wg2th, *wg2tl;
    cudaGetSymbolAddress((void**)&ga,   g_a);
    cudaGetSymbolAddress((void**)&gbp,  g_bp);
    cudaGetSymbolAddress((void**)&gx1,  g_x1);
    cudaGetSymbolAddress((void**)&gw,   g_w);
    cudaGetSymbolAddress((void**)&xhi,  g_xhi);
    cudaGetSymbolAddress((void**)&xlo,  g_xlo);
    cudaGetSymbolAddress((void**)&mhi,  g_mhi);
    cudaGetSymbolAddress((void**)&mlo,  g_mlo);
    cudaGetSymbolAddress((void**)&w1th, g_w1t_hi);
    cudaGetSymbolAddress((void**)&w1tl, g_w1t_lo);
    cudaGetSymbolAddress((void**)&wg1th, g_wg1t_hi);
    cudaGetSymbolAddress((void**)&wg1tl, g_wg1t_lo);
    cudaGetSymbolAddress((void**)&wg2th, g_wg2t_hi);
    cudaGetSymbolAddress((void**)&wg2tl, g_wg2t_lo);

    dim3 blk(256);

    // Conversions
    split_kernel<<<512, 256>>>((const float4*)x, (uint2*)xhi, (uint2*)xlo, Mrows * Dd / 4);
    {
        dim3 g512(Dd / 32, Dd / 32);   // (N/32, K/32)
        splitT_kernel<<<g512, blk>>>(W1,                   w1th,                 w1tl,                 Dd, Dd);
        splitT_kernel<<<g512, blk>>>(W1 + (size_t)Dd * Dd, w1th + (size_t)Dd*Dd, w1tl + (size_t)Dd*Dd, Dd, Dd);
        splitT_kernel<<<g512, blk>>>(Wg1, wg1th, wg1tl, Dd, Dd);
        dim3 g256(Oo / 32, Dd / 32);
        splitT_kernel<<<g256, blk>>>(Wg2, wg2th, wg2tl, Dd, Oo);
    }

    // Merged G1: [a | bp] = x @ [W1a | W1b], N=1024, dual output, bias on bp
    {
        dim3 grid(2 * Dd / 64, Mrows / 128);
        mgemm_kernel<3><<<grid, blk>>>(xhi, xlo, w1th, w1tl, b1, nullptr,
                                       ga, gbp, Mrows, 2 * Dd, Dd);
    }
    // Attention weights
    attn_kernel<<<Bb * NREG, blk>>>(ga, gbp, W2, b2, ridx, gw);
    // m1 = adj @ x  (hi/lo)
    {
        dim3 grid(Bb * NREG, Dd / 256);
        agg_kernel<<<grid, blk>>>(gw, x, ridx, mhi, mlo);
    }
    // x1 = 0.5*leaky(m1 @ Wg1 + bg1) + 0.5*x
    {
        dim3 grid(Dd / 64, Mrows / 128);
        mgemm_kernel<2><<<grid, blk>>>(mhi, mlo, wg1th, wg1tl, bg1, x,
                                       gx1, nullptr, Mrows, Dd, Dd);
    }
    // m2 = adj @ x1
    {
        dim3 grid(Bb * NREG, Dd / 256);
        agg_kernel<<<grid, blk>>>(gw, gx1, ridx, mhi, mlo);
    }
    // out = leaky(m2 @ Wg2 + bg2)
    {
        dim3 grid(Oo / 64, Mrows / 128);
        mgemm_kernel<1><<<grid, blk>>>(mhi, mlo, wg2th, wg2tl, bg2, nullptr,
                                       out, nullptr, Mrows, Oo, Dd);
    }
}

// round 5
// speedup vs baseline: 2.7994x; 1.0993x over previous
#include <cuda_runtime.h>
#include <cuda_bf16.h>
#include <math.h>

#define Bb 64
#define Cc 64
#define Dd 512
#define Oo 256
#define NREG 8
#define Gg 8
#define Mrows (Bb*Cc)   // 4096

typedef __nv_bfloat16 bf16;

// ---------------- Scratch (device globals) ----------------
__device__ float g_a [Mrows*Dd];
__device__ float g_bp[Mrows*Dd];
__device__ float g_x1[Mrows*Dd];
__device__ float g_w [Bb*NREG*Gg*Gg];

__device__ bf16 g_xhi[Mrows*Dd], g_xlo[Mrows*Dd];
__device__ bf16 g_mhi[Mrows*Dd], g_mlo[Mrows*Dd];
__device__ bf16 g_w1t_hi[2*Dd*Dd], g_w1t_lo[2*Dd*Dd];   // W1a^T then W1b^T, [n][k]
__device__ bf16 g_wg1t_hi[Dd*Dd],  g_wg1t_lo[Dd*Dd];
__device__ bf16 g_wg2t_hi[Oo*Dd],  g_wg2t_lo[Oo*Dd];

// ---------------- async / ldmatrix helpers ----------------
__device__ __forceinline__ void cpasync16(void* smem, const void* g)
{
    unsigned sa = (unsigned)__cvta_generic_to_shared(smem);
    asm volatile("cp.async.cg.shared.global [%0], [%1], 16;" :: "r"(sa), "l"(g));
}
__device__ __forceinline__ void cp_commit() { asm volatile("cp.async.commit_group;"); }
template<int N> __device__ __forceinline__ void cp_wait()
{
    asm volatile("cp.async.wait_group %0;" :: "n"(N));
}
__device__ __forceinline__ void ldmx4(unsigned& r0, unsigned& r1, unsigned& r2,
                                      unsigned& r3, const void* p)
{
    unsigned a = (unsigned)__cvta_generic_to_shared(p);
    asm volatile("ldmatrix.sync.aligned.m8n8.x4.shared.b16 {%0,%1,%2,%3}, [%4];"
        : "=r"(r0), "=r"(r1), "=r"(r2), "=r"(r3) : "r"(a));
}
__device__ __forceinline__ void mma_bf16(float c[4],
    unsigned a0, unsigned a1, unsigned a2, unsigned a3,
    unsigned b0, unsigned b1)
{
    asm volatile(
        "mma.sync.aligned.m16n8k16.row.col.f32.bf16.bf16.f32 "
        "{%0,%1,%2,%3}, {%4,%5,%6,%7}, {%8,%9}, {%0,%1,%2,%3};\n"
        : "+f"(c[0]), "+f"(c[1]), "+f"(c[2]), "+f"(c[3])
        : "r"(a0), "r"(a1), "r"(a2), "r"(a3), "r"(b0), "r"(b1));
}

// ---------------- Combined prep kernel ----------------
// Blocks [0,256): W1a^T  [256,512): W1b^T  [512,768): Wg1^T
// [768,896): Wg2^T  [896,1024): x split
__device__ __forceinline__ void transpose_tile(
    const float* __restrict__ src, bf16* __restrict__ dhi, bf16* __restrict__ dlo,
    int K, int N, int tn, int tk)
{
    __shared__ float tile[32][33];
    const int tid = threadIdx.x;
    const int k0 = tk * 32, n0 = tn * 32;
    const int tx = tid & 31, ty = tid >> 5;
    #pragma unroll
    for (int i = 0; i < 4; i++)
        tile[ty + 8 * i][tx] = src[(size_t)(k0 + ty + 8 * i) * N + n0 + tx];
    __syncthreads();
    const int nr = tid >> 4;
    const int kp = tid & 15;
    #pragma unroll
    for (int i = 0; i < 2; i++) {
        int n = n0 + nr + 16 * i;
        float v0 = tile[2 * kp    ][nr + 16 * i];
        float v1 = tile[2 * kp + 1][nr + 16 * i];
        bf16 h0 = __float2bfloat16_rn(v0), h1 = __float2bfloat16_rn(v1);
        bf16 l0 = __float2bfloat16_rn(v0 - __bfloat162float(h0));
        bf16 l1 = __float2bfloat16_rn(v1 - __bfloat162float(h1));
        __nv_bfloat162 ph = __halves2bfloat162(h0, h1);
        __nv_bfloat162 pl = __halves2bfloat162(l0, l1);
        *(__nv_bfloat162*)&dhi[(size_t)n * K + k0 + 2 * kp] = ph;
        *(__nv_bfloat162*)&dlo[(size_t)n * K + k0 + 2 * kp] = pl;
    }
}

__global__ __launch_bounds__(256)
void prep_kernel(const float* __restrict__ x, const float* __restrict__ W1,
                 const float* __restrict__ Wg1, const float* __restrict__ Wg2,
                 bf16* __restrict__ xhi, bf16* __restrict__ xlo,
                 bf16* __restrict__ w1th, bf16* __restrict__ w1tl,
                 bf16* __restrict__ wg1th, bf16* __restrict__ wg1tl,
                 bf16* __restrict__ wg2th, bf16* __restrict__ wg2tl)
{
    int b = blockIdx.x;
    if (b < 256) {
        transpose_tile(W1, w1th, w1tl, Dd, Dd, b & 15, b >> 4);
    } else if (b < 512) {
        b -= 256;
        transpose_tile(W1 + (size_t)Dd * Dd, w1th + (size_t)Dd * Dd,
                       w1tl + (size_t)Dd * Dd, Dd, Dd, b & 15, b >> 4);
    } else if (b < 768) {
        b -= 512;
        transpose_tile(Wg1, wg1th, wg1tl, Dd, Dd, b & 15, b >> 4);
    } else if (b < 896) {
        b -= 768;
        transpose_tile(Wg2, wg2th, wg2tl, Dd, Oo, b & 7, b >> 3);
    } else {
        b -= 896;   // 128 blocks: x split, float4-vectorized
        const float4* src = (const float4*)x;
        uint2* dh = (uint2*)xhi;
        uint2* dl = (uint2*)xlo;
        const int n4 = Mrows * Dd / 4;
        for (int i = b * 256 + threadIdx.x; i < n4; i += 128 * 256) {
            float4 v = src[i];
            bf16 h0 = __float2bfloat16_rn(v.x), h1 = __float2bfloat16_rn(v.y);
            bf16 h2 = __float2bfloat16_rn(v.z), h3 = __float2bfloat16_rn(v.w);
            bf16 l0 = __float2bfloat16_rn(v.x - __bfloat162float(h0));
            bf16 l1 = __float2bfloat16_rn(v.y - __bfloat162float(h1));
            bf16 l2 = __float2bfloat16_rn(v.z - __bfloat162float(h2));
            bf16 l3 = __float2bfloat16_rn(v.w - __bfloat162float(h3));
            __nv_bfloat162 ph0 = __halves2bfloat162(h0, h1), ph1 = __halves2bfloat162(h2, h3);
            __nv_bfloat162 pl0 = __halves2bfloat162(l0, l1), pl1 = __halves2bfloat162(l2, l3);
            dh[i] = make_uint2(*(unsigned*)&ph0, *(unsigned*)&ph1);
            dl[i] = make_uint2(*(unsigned*)&pl0, *(unsigned*)&pl1);
        }
    }
}

// ---------------- split-bf16 tensor-core GEMM ----------------
// BM=128, BN=64, BK=32, 3-stage cp.async, ldmatrix fragments.
// MODE 0: +bias; 1: leaky(0.2)+bias; 2: 0.5*leaky(z+bias)+0.5*res;
// MODE 3: dual output (n<Dd -> C raw; n>=Dd -> C2 + bias)
template<int MODE>
__global__ __launch_bounds__(256, 2)
void mgemm_kernel(const bf16* __restrict__ Ahi, const bf16* __restrict__ Alo,
                  const bf16* __restrict__ Bth, const bf16* __restrict__ Btl,
                  const float* __restrict__ bias, const float* __restrict__ res,
                  float* __restrict__ C, float* __restrict__ C2,
                  int M, int N, int K)
{
    constexpr int BM = 128, BN = 64, BK = 32, LDT = 40, STAGES = 3;
    constexpr int A_SZ = BM * LDT;              // elements
    constexpr int B_SZ = BN * LDT;
    constexpr int STG  = 2 * A_SZ + 2 * B_SZ;   // per-stage elements
    extern __shared__ bf16 dsm[];

    const int tid  = threadIdx.x;
    const int wid  = tid >> 5;
    const int lane = tid & 31;
    const int wm   = wid & 3;
    const int wn   = wid >> 2;
    const int row0 = blockIdx.y * BM;
    const int col0 = blockIdx.x * BN;
    const int g = lane >> 2;
    const int t = lane & 3;
    // ldmatrix lane addressing
    const int lq = lane >> 3, li = lane & 7;
    const int fr_off = (lq & 1) * 8 + li;   // row within 16-row frag
    const int fk_off = (lq >> 1) * 8;       // k half

    float acc[2][4][4];
    #pragma unroll
    for (int mt = 0; mt < 2; mt++)
        #pragma unroll
        for (int nt = 0; nt < 4; nt++)
            #pragma unroll
            for (int q = 0; q < 4; q++) acc[mt][nt][q] = 0.f;

    auto load_stage = [&](int st, int kt) {
        bf16* sAh = dsm + st * STG;
        bf16* sAl = sAh + A_SZ;
        bf16* sBh = sAl + A_SZ;
        bf16* sBl = sBh + B_SZ;
        #pragma unroll
        for (int i = 0; i < 2; i++) {
            int id = tid * 2 + i;
            int r = id >> 2, c = (id & 3) * 8;
            size_t go = (size_t)(row0 + r) * K + kt + c;
            cpasync16(sAh + r * LDT + c, Ahi + go);
            cpasync16(sAl + r * LDT + c, Alo + go);
        }
        {
            int r = tid >> 2, c = (tid & 3) * 8;
            size_t go = (size_t)(col0 + r) * K + kt + c;
            cpasync16(sBh + r * LDT + c, Bth + go);
            cpasync16(sBl + r * LDT + c, Btl + go);
        }
    };

    const int nk = K / BK;
    load_stage(0, 0); cp_commit();
    load_stage(1, BK); cp_commit();

    for (int s = 0; s < nk; s++) {
        if (s + 2 < nk) { load_stage((s + 2) % STAGES, (s + 2) * BK); cp_commit(); cp_wait<2>(); }
        else if (s + 1 < nk) { cp_wait<1>(); }
        else { cp_wait<0>(); }
        __syncthreads();

        const int st = s % STAGES;
        bf16* sAh = dsm + st * STG;
        bf16* sAl = sAh + A_SZ;
        bf16* sBh = sAl + A_SZ;
        bf16* sBl = sBh + B_SZ;

        #pragma unroll
        for (int kk = 0; kk < BK; kk += 16) {
            unsigned ah[2][4], al[2][4], bhv[2][4], blv[2][4];
            #pragma unroll
            for (int mt = 0; mt < 2; mt++) {
                const bf16* pa = sAh + (wm * 32 + mt * 16 + fr_off) * LDT + kk + fk_off;
                ldmx4(ah[mt][0], ah[mt][1], ah[mt][2], ah[mt][3], pa);
                const bf16* pl = sAl + (wm * 32 + mt * 16 + fr_off) * LDT + kk + fk_off;
                ldmx4(al[mt][0], al[mt][1], al[mt][2], al[mt][3], pl);
            }
            #pragma unroll
            for (int p = 0; p < 2; p++) {
                const bf16* pb = sBh + (wn * 32 + p * 16 + fr_off) * LDT + kk + fk_off;
                ldmx4(bhv[p][0], bhv[p][1], bhv[p][2], bhv[p][3], pb);
                const bf16* pc = sBl + (wn * 32 + p * 16 + fr_off) * LDT + kk + fk_off;
                ldmx4(blv[p][0], blv[p][1], blv[p][2], blv[p][3], pc);
            }
            #pragma unroll
            for (int mt = 0; mt < 2; mt++)
                #pragma unroll
                for (int nt = 0; nt < 4; nt++) {
                    const int p = nt >> 1, o = nt & 1;
                    unsigned b0h = bhv[p][o], b1h = bhv[p][2 + o];
                    unsigned b0l = blv[p][o], b1l = blv[p][2 + o];
                    mma_bf16(acc[mt][nt], ah[mt][0], ah[mt][1], ah[mt][2], ah[mt][3], b0h, b1h);
                    mma_bf16(acc[mt][nt], ah[mt][0], ah[mt][1], ah[mt][2], ah[mt][3], b0l, b1l);
                    mma_bf16(acc[mt][nt], al[mt][0], al[mt][1], al[mt][2], al[mt][3], b0h, b1h);
                }
        }
        __syncthreads();
    }

    // Epilogue
    #pragma unroll
    for (int mt = 0; mt < 2; mt++) {
        int rbase = row0 + wm * 32 + mt * 16;
        #pragma unroll
        for (int nt = 0; nt < 4; nt++) {
            int cb = col0 + wn * 32 + nt * 8 + 2 * t;
            #pragma unroll
            for (int h = 0; h < 2; h++) {
                int r = rbase + g + 8 * h;
                float v0 = acc[mt][nt][2*h];
                float v1 = acc[mt][nt][2*h + 1];
                if (MODE == 3) {
                    if (cb < Dd) {
                        *(float2*)(C + (size_t)r * Dd + cb) = make_float2(v0, v1);
                    } else {
                        int c2 = cb - Dd;
                        v0 += bias[c2]; v1 += bias[c2 + 1];
                        *(float2*)(C2 + (size_t)r * Dd + c2) = make_float2(v0, v1);
                    }
                } else {
                    if (bias) { v0 += bias[cb]; v1 += bias[cb + 1]; }
                    if (MODE >= 1) {
                        v0 = (v0 >= 0.f) ? v0 : 0.2f * v0;
                        v1 = (v1 >= 0.f) ? v1 : 0.2f * v1;
                    }
                    if (MODE == 2) {
                        const float* rr = res + (size_t)r * N + cb;
                        v0 = 0.5f * v0 + 0.5f * rr[0];
                        v1 = 0.5f * v1 + 0.5f * rr[1];
                    }
                    *(float2*)(C + (size_t)r * N + cb) = make_float2(v0, v1);
                }
            }
        }
    }
}

// ---------------------------------------------------------------------------
// Attention: per (batch, region) block computes 8x8 masked softmax weights.
// ---------------------------------------------------------------------------
__global__ __launch_bounds__(256)
void attn_kernel(const float* __restrict__ a, const float* __restrict__ bp,
                 const float* __restrict__ W2, const float* __restrict__ b2,
                 const int* __restrict__ ridx, float* __restrict__ wout)
{
    __shared__ float sa[Gg][Dd];
    __shared__ float sb[Gg][Dd];
    __shared__ float sw2[Dd];
    __shared__ float ssc[Gg][Gg];
    __shared__ int   ch[Gg];

    const int tid  = threadIdx.x;
    const int blk  = blockIdx.x;
    const int b    = blk >> 3;
    const int r    = blk & 7;

    if (tid < Gg) ch[tid] = ridx[r * Gg + tid];
    __syncthreads();

    for (int d = tid; d < Dd; d += 256) sw2[d] = W2[d];
    #pragma unroll
    for (int j = 0; j < Gg; j++) {
        const float* arow = a  + (size_t)(b * Cc + ch[j]) * Dd;
        const float* brow = bp + (size_t)(b * Cc + ch[j]) * Dd;
        for (int d = tid; d < Dd; d += 256) {
            sa[j][d] = arow[d];
            sb[j][d] = brow[d];
        }
    }
    __syncthreads();

    const int wid  = tid >> 5;
    const int lane = tid & 31;
    float accq[Gg];
    #pragma unroll
    for (int q = 0; q < Gg; q++) accq[q] = 0.f;
    for (int t = lane; t < Dd; t += 32) {
        float av = sa[wid][t];
        float wv = sw2[t];
        #pragma unroll
        for (int q = 0; q < Gg; q++) {
            float v = av + sb[q][t];
            v = fmaxf(v, 0.f);
            accq[q] = fmaf(v, wv, accq[q]);
        }
    }
    #pragma unroll
    for (int q = 0; q < Gg; q++) {
        #pragma unroll
        for (int off = 16; off > 0; off >>= 1)
            accq[q] += __shfl_xor_sync(0xffffffffu, accq[q], off);
    }
    if (lane == 0) {
        float bb2 = b2[0];
        #pragma unroll
        for (int q = 0; q < Gg; q++) ssc[wid][q] = accq[q] + bb2;
    }
    __syncthreads();

    if (tid < Gg) {
        int i = tid;
        float mx = -1e30f;
        #pragma unroll
        for (int j = 0; j < Gg; j++)
            if (j != i) mx = fmaxf(mx, ssc[i][j]);
        float e[Gg]; float s = 0.f;
        #pragma unroll
        for (int j = 0; j < Gg; j++) {
            e[j] = (j == i) ? 0.f : __expf(ssc[i][j] - mx);
            s += e[j];
        }
        float inv = 1.f / s;
        float* wrow = wout + ((size_t)blk * Gg + i) * Gg;
        #pragma unroll
        for (int j = 0; j < Gg; j++) wrow[j] = e[j] * inv;
    }
}

// ---------------------------------------------------------------------------
// Aggregation: m[b, ch_i, dbase+tid] = sum_j w[b,r,i,j]*xin[b, ch_j, dbase+tid]
// ---------------------------------------------------------------------------
__global__ __launch_bounds__(256)
void agg_kernel(const float* __restrict__ w, const float* __restrict__ xin,
                const int* __restrict__ ridx,
                bf16* __restrict__ mhi, bf16* __restrict__ mlo)
{
    __shared__ float xs[Gg][256];
    __shared__ float ww[Gg * Gg];
    __shared__ int   ch[Gg];

    const int tid = threadIdx.x;
    const int blk = blockIdx.x;
    const int b   = blk >> 3;
    const int r   = blk & 7;
    const int dbase = blockIdx.y * 256;

    if (tid < Gg) ch[tid] = ridx[r * Gg + tid];
    if (tid >= 32 && tid < 96) ww[tid - 32] = w[(size_t)blk * 64 + (tid - 32)];
    __syncthreads();

    #pragma unroll
    for (int j = 0; j < Gg; j++)
        xs[j][tid] = xin[(size_t)(b * Cc + ch[j]) * Dd + dbase + tid];
    __syncthreads();

    #pragma unroll
    for (int i = 0; i < Gg; i++) {
        size_t o = (size_t)(b * Cc + ch[i]) * Dd + dbase + tid;
        float accv = 0.f;
        #pragma unroll
        for (int j = 0; j < Gg; j++) accv = fmaf(ww[i * Gg + j], xs[j][tid], accv);
        bf16 h = __float2bfloat16_rn(accv);
        mhi[o] = h;
        mlo[o] = __float2bfloat16_rn(accv - __bfloat162float(h));
    }
}

// ---------------------------------------------------------------------------
extern "C" void kernel_launch(void* const* d_in, const int* in_sizes, int n_in,
                              void* d_out, int out_size)
{
    const float* x    = (const float*)d_in[0];
    const float* W1   = (const float*)d_in[1];
    const float* b1   = (const float*)d_in[2];
    const float* W2   = (const float*)d_in[3];
    const float* b2   = (const float*)d_in[4];
    const float* Wg1  = (const float*)d_in[5];
    const float* bg1  = (const float*)d_in[6];
    const float* Wg2  = (const float*)d_in[7];
    const float* bg2  = (const float*)d_in[8];
    const int*   ridx = (const int*)d_in[9];
    float* out = (float*)d_out;

    float *ga, *gbp, *gx1, *gw;
    bf16 *xhi, *xlo, *mhi, *mlo;
    bf16 *w1th, *w1tl, *wg1th, *wg1tl, *wg2th, *wg2tl;
    cudaGetSymbolAddress((void**)&ga,   g_a);
    cudaGetSymbolAddress((void**)&gbp,  g_bp);
    cudaGetSymbolAddress((void**)&gx1,  g_x1);
    cudaGetSymbolAddress((void**)&gw,   g_w);
    cudaGetSymbolAddress((void**)&xhi,  g_xhi);
    cudaGetSymbolAddress((void**)&xlo,  g_xlo);
    cudaGetSymbolAddress((void**)&mhi,  g_mhi);
    cudaGetSymbolAddress((void**)&mlo,  g_mlo);
    cudaGetSymbolAddress((void**)&w1th, g_w1t_hi);
    cudaGetSymbolAddress((void**)&w1tl, g_w1t_lo);
    cudaGetSymbolAddress((void**)&wg1th, g_wg1t_hi);
    cudaGetSymbolAddress((void**)&wg1tl, g_wg1t_lo);
    cudaGetSymbolAddress((void**)&wg2th, g_wg2t_hi);
    cudaGetSymbolAddress((void**)&wg2tl, g_wg2t_lo);

    const int SMEM = 3 * (2 * 128 * 40 + 2 * 64 * 40) * (int)sizeof(bf16);  // 92160
    cudaFuncSetAttribute(mgemm_kernel<3>, cudaFuncAttributeMaxDynamicSharedMemorySize, SMEM);
    cudaFuncSetAttribute(mgemm_kernel<2>, cudaFuncAttributeMaxDynamicSharedMemorySize, SMEM);
    cudaFuncSetAttribute(mgemm_kernel<1>, cudaFuncAttributeMaxDynamicSharedMemorySize, SMEM);

    dim3 blk(256);

    // Single prep: all weight transposes + x split
    prep_kernel<<<1024, blk>>>(x, W1, Wg1, Wg2, xhi, xlo,
                               w1th, w1tl, wg1th, wg1tl, wg2th, wg2tl);

    // Merged G1: [a | bp] = x @ [W1a | W1b], N=1024, dual output
    {
        dim3 grid(2 * Dd / 64, Mrows / 128);
        mgemm_kernel<3><<<grid, blk, SMEM>>>(xhi, xlo, w1th, w1tl, b1, nullptr,
                                             ga, gbp, Mrows, 2 * Dd, Dd);
    }
    attn_kernel<<<Bb * NREG, blk>>>(ga, gbp, W2, b2, ridx, gw);
    {
        dim3 grid(Bb * NREG, Dd / 256);
        agg_kernel<<<grid, blk>>>(gw, x, ridx, mhi, mlo);
    }
    {
        dim3 grid(Dd / 64, Mrows / 128);
        mgemm_kernel<2><<<grid, blk, SMEM>>>(mhi, mlo, wg1th, wg1tl, bg1, x,
                                             gx1, nullptr, Mrows, Dd, Dd);
    }
    {
        dim3 grid(Bb * NREG, Dd / 256);
        agg_kernel<<<grid, blk>>>(gw, gx1, ridx, mhi, mlo);
    }
    {
        dim3 grid(Oo / 64, Mrows / 128);
        mgemm_kernel<1><<<grid, blk, SMEM>>>(mhi, mlo, wg2th, wg2tl, bg2, nullptr,
                                             out, nullptr, Mrows, Oo, Dd);
    }
}

// round 6
// speedup vs baseline: 2.9318x; 1.0473x over previous
#include <cuda_runtime.h>
#include <cuda_bf16.h>
#include <math.h>

#define Bb 64
#define Cc 64
#define Dd 512
#define Oo 256
#define NREG 8
#define Gg 8
#define Mrows (Bb*Cc)   // 4096

typedef __nv_bfloat16 bf16;

// ---------------- Scratch (device globals) ----------------
__device__ float g_a [Mrows*Dd];
__device__ float g_bp[Mrows*Dd];
__device__ float g_x1[Mrows*Dd];
__device__ float g_w [Bb*NREG*Gg*Gg];

__device__ bf16 g_xhi[Mrows*Dd], g_xlo[Mrows*Dd];
__device__ bf16 g_mhi[Mrows*Dd], g_mlo[Mrows*Dd];
__device__ bf16 g_w1t_hi[2*Dd*Dd], g_w1t_lo[2*Dd*Dd];
__device__ bf16 g_wg1t_hi[Dd*Dd],  g_wg1t_lo[Dd*Dd];
__device__ bf16 g_wg2t_hi[Oo*Dd],  g_wg2t_lo[Oo*Dd];

// ---------------- async / ldmatrix helpers ----------------
__device__ __forceinline__ void cpasync16(void* smem, const void* g)
{
    unsigned sa = (unsigned)__cvta_generic_to_shared(smem);
    asm volatile("cp.async.cg.shared.global [%0], [%1], 16;" :: "r"(sa), "l"(g));
}
__device__ __forceinline__ void cp_commit() { asm volatile("cp.async.commit_group;"); }
template<int N> __device__ __forceinline__ void cp_wait()
{
    asm volatile("cp.async.wait_group %0;" :: "n"(N));
}
__device__ __forceinline__ void ldmx4(unsigned& r0, unsigned& r1, unsigned& r2,
                                      unsigned& r3, const void* p)
{
    unsigned a = (unsigned)__cvta_generic_to_shared(p);
    asm volatile("ldmatrix.sync.aligned.m8n8.x4.shared.b16 {%0,%1,%2,%3}, [%4];"
        : "=r"(r0), "=r"(r1), "=r"(r2), "=r"(r3) : "r"(a));
}
__device__ __forceinline__ void mma_bf16(float c[4],
    unsigned a0, unsigned a1, unsigned a2, unsigned a3,
    unsigned b0, unsigned b1)
{
    asm volatile(
        "mma.sync.aligned.m16n8k16.row.col.f32.bf16.bf16.f32 "
        "{%0,%1,%2,%3}, {%4,%5,%6,%7}, {%8,%9}, {%0,%1,%2,%3};\n"
        : "+f"(c[0]), "+f"(c[1]), "+f"(c[2]), "+f"(c[3])
        : "r"(a0), "r"(a1), "r"(a2), "r"(a3), "r"(b0), "r"(b1));
}

// ---------------- Combined prep kernel ----------------
__device__ __forceinline__ void transpose_tile(
    const float* __restrict__ src, bf16* __restrict__ dhi, bf16* __restrict__ dlo,
    int K, int N, int tn, int tk)
{
    __shared__ float tile[32][33];
    const int tid = threadIdx.x;
    const int k0 = tk * 32, n0 = tn * 32;
    const int tx = tid & 31, ty = tid >> 5;
    #pragma unroll
    for (int i = 0; i < 4; i++)
        tile[ty + 8 * i][tx] = src[(size_t)(k0 + ty + 8 * i) * N + n0 + tx];
    __syncthreads();
    const int nr = tid >> 4;
    const int kp = tid & 15;
    #pragma unroll
    for (int i = 0; i < 2; i++) {
        int n = n0 + nr + 16 * i;
        float v0 = tile[2 * kp    ][nr + 16 * i];
        float v1 = tile[2 * kp + 1][nr + 16 * i];
        bf16 h0 = __float2bfloat16_rn(v0), h1 = __float2bfloat16_rn(v1);
        bf16 l0 = __float2bfloat16_rn(v0 - __bfloat162float(h0));
        bf16 l1 = __float2bfloat16_rn(v1 - __bfloat162float(h1));
        __nv_bfloat162 ph = __halves2bfloat162(h0, h1);
        __nv_bfloat162 pl = __halves2bfloat162(l0, l1);
        *(__nv_bfloat162*)&dhi[(size_t)n * K + k0 + 2 * kp] = ph;
        *(__nv_bfloat162*)&dlo[(size_t)n * K + k0 + 2 * kp] = pl;
    }
}

__global__ __launch_bounds__(256)
void prep_kernel(const float* __restrict__ x, const float* __restrict__ W1,
                 const float* __restrict__ Wg1, const float* __restrict__ Wg2,
                 bf16* __restrict__ xhi, bf16* __restrict__ xlo,
                 bf16* __restrict__ w1th, bf16* __restrict__ w1tl,
                 bf16* __restrict__ wg1th, bf16* __restrict__ wg1tl,
                 bf16* __restrict__ wg2th, bf16* __restrict__ wg2tl)
{
    int b = blockIdx.x;
    if (b < 256) {
        transpose_tile(W1, w1th, w1tl, Dd, Dd, b & 15, b >> 4);
    } else if (b < 512) {
        b -= 256;
        transpose_tile(W1 + (size_t)Dd * Dd, w1th + (size_t)Dd * Dd,
                       w1tl + (size_t)Dd * Dd, Dd, Dd, b & 15, b >> 4);
    } else if (b < 768) {
        b -= 512;
        transpose_tile(Wg1, wg1th, wg1tl, Dd, Dd, b & 15, b >> 4);
    } else if (b < 896) {
        b -= 768;
        transpose_tile(Wg2, wg2th, wg2tl, Dd, Oo, b & 7, b >> 3);
    } else {
        b -= 896;
        const float4* src = (const float4*)x;
        uint2* dh = (uint2*)xhi;
        uint2* dl = (uint2*)xlo;
        const int n4 = Mrows * Dd / 4;
        for (int i = b * 256 + threadIdx.x; i < n4; i += 128 * 256) {
            float4 v = src[i];
            bf16 h0 = __float2bfloat16_rn(v.x), h1 = __float2bfloat16_rn(v.y);
            bf16 h2 = __float2bfloat16_rn(v.z), h3 = __float2bfloat16_rn(v.w);
            bf16 l0 = __float2bfloat16_rn(v.x - __bfloat162float(h0));
            bf16 l1 = __float2bfloat16_rn(v.y - __bfloat162float(h1));
            bf16 l2 = __float2bfloat16_rn(v.z - __bfloat162float(h2));
            bf16 l3 = __float2bfloat16_rn(v.w - __bfloat162float(h3));
            __nv_bfloat162 ph0 = __halves2bfloat162(h0, h1), ph1 = __halves2bfloat162(h2, h3);
            __nv_bfloat162 pl0 = __halves2bfloat162(l0, l1), pl1 = __halves2bfloat162(l2, l3);
            dh[i] = make_uint2(*(unsigned*)&ph0, *(unsigned*)&ph1);
            dl[i] = make_uint2(*(unsigned*)&pl0, *(unsigned*)&pl1);
        }
    }
}

// ---------------- split-bf16 tensor-core GEMM ----------------
// BN=64, BK=32, 3-stage cp.async, ldmatrix. Template BM in {128, 64}.
// MODE 0: +bias; 1: leaky(0.2)+bias; 2: 0.5*leaky(z+bias)+0.5*res;
// MODE 3: dual output (n<Dd -> C raw; n>=Dd -> C2 + bias)
template<int MODE, int BM>
__global__ __launch_bounds__(256, 2)
void mgemm_kernel(const bf16* __restrict__ Ahi, const bf16* __restrict__ Alo,
                  const bf16* __restrict__ Bth, const bf16* __restrict__ Btl,
                  const float* __restrict__ bias, const float* __restrict__ res,
                  float* __restrict__ C, float* __restrict__ C2,
                  int M, int N, int K)
{
    constexpr int BN = 64, BK = 32, LDT = 40, STAGES = 3;
    constexpr int WROWS = BM / 32;          // warps along M: 4 or 2
    constexpr int NT = WROWS;               // n-subtiles per warp (8 cols each)
    constexpr int P  = WROWS / 2 ? WROWS / 2 : 1;  // B ldmatrix count (2 or 1)
    constexpr int WCOLS = 8 * NT;           // warp tile N: 32 or 16
    constexpr int A_SZ = BM * LDT;
    constexpr int B_SZ = BN * LDT;
    constexpr int STG  = 2 * A_SZ + 2 * B_SZ;
    constexpr int ACH  = BM / 64;           // A 16B-chunks per thread (2 or 1)
    extern __shared__ bf16 dsm[];

    const int tid  = threadIdx.x;
    const int wid  = tid >> 5;
    const int lane = tid & 31;
    const int wm   = wid % WROWS;
    const int wn   = wid / WROWS;
    const int row0 = blockIdx.y * BM;
    const int col0 = blockIdx.x * BN;
    const int g = lane >> 2;
    const int t = lane & 3;
    const int lq = lane >> 3, li = lane & 7;
    const int fr_off = (lq & 1) * 8 + li;
    const int fk_off = (lq >> 1) * 8;

    float acc[2][NT][4];
    #pragma unroll
    for (int mt = 0; mt < 2; mt++)
        #pragma unroll
        for (int nt = 0; nt < NT; nt++)
            #pragma unroll
            for (int q = 0; q < 4; q++) acc[mt][nt][q] = 0.f;

    auto load_stage = [&](int st, int kt) {
        bf16* sAh = dsm + st * STG;
        bf16* sAl = sAh + A_SZ;
        bf16* sBh = sAl + A_SZ;
        bf16* sBl = sBh + B_SZ;
        #pragma unroll
        for (int i = 0; i < ACH; i++) {
            int id = tid * ACH + i;
            int r = id >> 2, c = (id & 3) * 8;
            size_t go = (size_t)(row0 + r) * K + kt + c;
            cpasync16(sAh + r * LDT + c, Ahi + go);
            cpasync16(sAl + r * LDT + c, Alo + go);
        }
        {
            int r = tid >> 2, c = (tid & 3) * 8;
            size_t go = (size_t)(col0 + r) * K + kt + c;
            cpasync16(sBh + r * LDT + c, Bth + go);
            cpasync16(sBl + r * LDT + c, Btl + go);
        }
    };

    const int nk = K / BK;
    load_stage(0, 0); cp_commit();
    load_stage(1, BK); cp_commit();

    for (int s = 0; s < nk; s++) {
        if (s + 2 < nk) { load_stage((s + 2) % STAGES, (s + 2) * BK); cp_commit(); cp_wait<2>(); }
        else if (s + 1 < nk) { cp_wait<1>(); }
        else { cp_wait<0>(); }
        __syncthreads();

        const int st = s % STAGES;
        bf16* sAh = dsm + st * STG;
        bf16* sAl = sAh + A_SZ;
        bf16* sBh = sAl + A_SZ;
        bf16* sBl = sBh + B_SZ;

        #pragma unroll
        for (int kk = 0; kk < BK; kk += 16) {
            unsigned ah[2][4], al[2][4], bhv[P][4], blv[P][4];
            #pragma unroll
            for (int mt = 0; mt < 2; mt++) {
                const bf16* pa = sAh + (wm * 32 + mt * 16 + fr_off) * LDT + kk + fk_off;
                ldmx4(ah[mt][0], ah[mt][1], ah[mt][2], ah[mt][3], pa);
                const bf16* pl = sAl + (wm * 32 + mt * 16 + fr_off) * LDT + kk + fk_off;
                ldmx4(al[mt][0], al[mt][1], al[mt][2], al[mt][3], pl);
            }
            #pragma unroll
            for (int p = 0; p < P; p++) {
                const bf16* pb = sBh + (wn * WCOLS + p * 16 + fr_off) * LDT + kk + fk_off;
                ldmx4(bhv[p][0], bhv[p][1], bhv[p][2], bhv[p][3], pb);
                const bf16* pc = sBl + (wn * WCOLS + p * 16 + fr_off) * LDT + kk + fk_off;
                ldmx4(blv[p][0], blv[p][1], blv[p][2], blv[p][3], pc);
            }
            #pragma unroll
            for (int mt = 0; mt < 2; mt++)
                #pragma unroll
                for (int nt = 0; nt < NT; nt++) {
                    const int p = nt >> 1, o = nt & 1;
                    unsigned b0h = bhv[p][o], b1h = bhv[p][2 + o];
                    unsigned b0l = blv[p][o], b1l = blv[p][2 + o];
                    mma_bf16(acc[mt][nt], ah[mt][0], ah[mt][1], ah[mt][2], ah[mt][3], b0h, b1h);
                    mma_bf16(acc[mt][nt], ah[mt][0], ah[mt][1], ah[mt][2], ah[mt][3], b0l, b1l);
                    mma_bf16(acc[mt][nt], al[mt][0], al[mt][1], al[mt][2], al[mt][3], b0h, b1h);
                }
        }
        __syncthreads();
    }

    #pragma unroll
    for (int mt = 0; mt < 2; mt++) {
        int rbase = row0 + wm * 32 + mt * 16;
        #pragma unroll
        for (int nt = 0; nt < NT; nt++) {
            int cb = col0 + wn * WCOLS + nt * 8 + 2 * t;
            #pragma unroll
            for (int h = 0; h < 2; h++) {
                int r = rbase + g + 8 * h;
                float v0 = acc[mt][nt][2*h];
                float v1 = acc[mt][nt][2*h + 1];
                if (MODE == 3) {
                    if (cb < Dd) {
                        *(float2*)(C + (size_t)r * Dd + cb) = make_float2(v0, v1);
                    } else {
                        int c2 = cb - Dd;
                        v0 += bias[c2]; v1 += bias[c2 + 1];
                        *(float2*)(C2 + (size_t)r * Dd + c2) = make_float2(v0, v1);
                    }
                } else {
                    if (bias) { v0 += bias[cb]; v1 += bias[cb + 1]; }
                    if (MODE >= 1) {
                        v0 = (v0 >= 0.f) ? v0 : 0.2f * v0;
                        v1 = (v1 >= 0.f) ? v1 : 0.2f * v1;
                    }
                    if (MODE == 2) {
                        const float* rr = res + (size_t)r * N + cb;
                        v0 = 0.5f * v0 + 0.5f * rr[0];
                        v1 = 0.5f * v1 + 0.5f * rr[1];
                    }
                    *(float2*)(C + (size_t)r * N + cb) = make_float2(v0, v1);
                }
            }
        }
    }
}

// ---------------------------------------------------------------------------
// Attention
// ---------------------------------------------------------------------------
__global__ __launch_bounds__(256)
void attn_kernel(const float* __restrict__ a, const float* __restrict__ bp,
                 const float* __restrict__ W2, const float* __restrict__ b2,
                 const int* __restrict__ ridx, float* __restrict__ wout)
{
    __shared__ float sa[Gg][Dd];
    __shared__ float sb[Gg][Dd];
    __shared__ float sw2[Dd];
    __shared__ float ssc[Gg][Gg];
    __shared__ int   ch[Gg];

    const int tid  = threadIdx.x;
    const int blk  = blockIdx.x;
    const int b    = blk >> 3;
    const int r    = blk & 7;

    if (tid < Gg) ch[tid] = ridx[r * Gg + tid];
    __syncthreads();

    for (int d = tid; d < Dd; d += 256) sw2[d] = W2[d];
    #pragma unroll
    for (int j = 0; j < Gg; j++) {
        const float* arow = a  + (size_t)(b * Cc + ch[j]) * Dd;
        const float* brow = bp + (size_t)(b * Cc + ch[j]) * Dd;
        for (int d = tid; d < Dd; d += 256) {
            sa[j][d] = arow[d];
            sb[j][d] = brow[d];
        }
    }
    __syncthreads();

    const int wid  = tid >> 5;
    const int lane = tid & 31;
    float accq[Gg];
    #pragma unroll
    for (int q = 0; q < Gg; q++) accq[q] = 0.f;
    for (int t = lane; t < Dd; t += 32) {
        float av = sa[wid][t];
        float wv = sw2[t];
        #pragma unroll
        for (int q = 0; q < Gg; q++) {
            float v = av + sb[q][t];
            v = fmaxf(v, 0.f);
            accq[q] = fmaf(v, wv, accq[q]);
        }
    }
    #pragma unroll
    for (int q = 0; q < Gg; q++) {
        #pragma unroll
        for (int off = 16; off > 0; off >>= 1)
            accq[q] += __shfl_xor_sync(0xffffffffu, accq[q], off);
    }
    if (lane == 0) {
        float bb2 = b2[0];
        #pragma unroll
        for (int q = 0; q < Gg; q++) ssc[wid][q] = accq[q] + bb2;
    }
    __syncthreads();

    if (tid < Gg) {
        int i = tid;
        float mx = -1e30f;
        #pragma unroll
        for (int j = 0; j < Gg; j++)
            if (j != i) mx = fmaxf(mx, ssc[i][j]);
        float e[Gg]; float s = 0.f;
        #pragma unroll
        for (int j = 0; j < Gg; j++) {
            e[j] = (j == i) ? 0.f : __expf(ssc[i][j] - mx);
            s += e[j];
        }
        float inv = 1.f / s;
        float* wrow = wout + ((size_t)blk * Gg + i) * Gg;
        #pragma unroll
        for (int j = 0; j < Gg; j++) wrow[j] = e[j] * inv;
    }
}

// ---------------------------------------------------------------------------
// Aggregation: vectorized. Block = (b, r); 256 threads handle 8 rows x 128 f4.
// ---------------------------------------------------------------------------
__global__ __launch_bounds__(256)
void agg_kernel(const float* __restrict__ w, const float* __restrict__ xin,
                const int* __restrict__ ridx,
                bf16* __restrict__ mhi, bf16* __restrict__ mlo)
{
    __shared__ float4 xs[Gg][Dd / 4];   // 16 KB
    __shared__ float  ww[Gg * Gg];
    __shared__ int    ch[Gg];

    const int tid = threadIdx.x;
    const int blk = blockIdx.x;
    const int b   = blk >> 3;
    const int r   = blk & 7;

    if (tid < Gg) ch[tid] = ridx[r * Gg + tid];
    if (tid >= 64 && tid < 128) ww[tid - 64] = w[(size_t)blk * 64 + (tid - 64)];
    __syncthreads();

    // Load 8 rows x 128 float4 (4 per thread)
    #pragma unroll
    for (int u = 0; u < 4; u++) {
        int id = tid + 256 * u;
        int j = id >> 7, d4 = id & 127;
        xs[j][d4] = ((const float4*)(xin + (size_t)(b * Cc + ch[j]) * Dd))[d4];
    }
    __syncthreads();

    // Compute 8 rows x 128 float4 out (4 per thread), packed bf16x4 stores
    #pragma unroll
    for (int u = 0; u < 4; u++) {
        int id = tid + 256 * u;
        int i = id >> 7, d4 = id & 127;
        float wi[Gg];
        #pragma unroll
        for (int j = 0; j < Gg; j++) wi[j] = ww[i * Gg + j];
        float4 acc = make_float4(0.f, 0.f, 0.f, 0.f);
        #pragma unroll
        for (int j = 0; j < Gg; j++) {
            float4 xv = xs[j][d4];
            acc.x = fmaf(wi[j], xv.x, acc.x);
            acc.y = fmaf(wi[j], xv.y, acc.y);
            acc.z = fmaf(wi[j], xv.z, acc.z);
            acc.w = fmaf(wi[j], xv.w, acc.w);
        }
        bf16 h0 = __float2bfloat16_rn(acc.x), h1 = __float2bfloat16_rn(acc.y);
        bf16 h2 = __float2bfloat16_rn(acc.z), h3 = __float2bfloat16_rn(acc.w);
        bf16 l0 = __float2bfloat16_rn(acc.x - __bfloat162float(h0));
        bf16 l1 = __float2bfloat16_rn(acc.y - __bfloat162float(h1));
        bf16 l2 = __float2bfloat16_rn(acc.z - __bfloat162float(h2));
        bf16 l3 = __float2bfloat16_rn(acc.w - __bfloat162float(h3));
        __nv_bfloat162 ph0 = __halves2bfloat162(h0, h1), ph1 = __halves2bfloat162(h2, h3);
        __nv_bfloat162 pl0 = __halves2bfloat162(l0, l1), pl1 = __halves2bfloat162(l2, l3);
        size_t rowoff = (size_t)(b * Cc + ch[i]) * Dd;
        ((uint2*)(mhi + rowoff))[d4] = make_uint2(*(unsigned*)&ph0, *(unsigned*)&ph1);
        ((uint2*)(mlo + rowoff))[d4] = make_uint2(*(unsigned*)&pl0, *(unsigned*)&pl1);
    }
}

// ---------------------------------------------------------------------------
extern "C" void kernel_launch(void* const* d_in, const int* in_sizes, int n_in,
                              void* d_out, int out_size)
{
    const float* x    = (const float*)d_in[0];
    const float* W1   = (const float*)d_in[1];
    const float* b1   = (const float*)d_in[2];
    const float* W2   = (const float*)d_in[3];
    const float* b2   = (const float*)d_in[4];
    const float* Wg1  = (const float*)d_in[5];
    const float* bg1  = (const float*)d_in[6];
    const float* Wg2  = (const float*)d_in[7];
    const float* bg2  = (const float*)d_in[8];
    const int*   ridx = (const int*)d_in[9];
    float* out = (float*)d_out;

    float *ga, *gbp, *gx1, *gw;
    bf16 *xhi, *xlo, *mhi, *mlo;
    bf16 *w1th, *w1tl, *wg1th, *wg1tl, *wg2th, *wg2tl;
    cudaGetSymbolAddress((void**)&ga,   g_a);
    cudaGetSymbolAddress((void**)&gbp,  g_bp);
    cudaGetSymbolAddress((void**)&gx1,  g_x1);
    cudaGetSymbolAddress((void**)&gw,   g_w);
    cudaGetSymbolAddress((void**)&xhi,  g_xhi);
    cudaGetSymbolAddress((void**)&xlo,  g_xlo);
    cudaGetSymbolAddress((void**)&mhi,  g_mhi);
    cudaGetSymbolAddress((void**)&mlo,  g_mlo);
    cudaGetSymbolAddress((void**)&w1th, g_w1t_hi);
    cudaGetSymbolAddress((void**)&w1tl, g_w1t_lo);
    cudaGetSymbolAddress((void**)&wg1th, g_wg1t_hi);
    cudaGetSymbolAddress((void**)&wg1tl, g_wg1t_lo);
    cudaGetSymbolAddress((void**)&wg2th, g_wg2t_hi);
    cudaGetSymbolAddress((void**)&wg2tl, g_wg2t_lo);

    const int SMEM128 = 3 * (2 * 128 * 40 + 2 * 64 * 40) * (int)sizeof(bf16);  // 92160
    const int SMEM64  = 3 * (2 *  64 * 40 + 2 * 64 * 40) * (int)sizeof(bf16);  // 61440
    cudaFuncSetAttribute(mgemm_kernel<3,128>, cudaFuncAttributeMaxDynamicSharedMemorySize, SMEM128);
    cudaFuncSetAttribute(mgemm_kernel<2,128>, cudaFuncAttributeMaxDynamicSharedMemorySize, SMEM128);
    cudaFuncSetAttribute(mgemm_kernel<1,64>,  cudaFuncAttributeMaxDynamicSharedMemorySize, SMEM64);

    dim3 blk(256);

    prep_kernel<<<1024, blk>>>(x, W1, Wg1, Wg2, xhi, xlo,
                               w1th, w1tl, wg1th, wg1tl, wg2th, wg2tl);

    // Merged G1: [a | bp] = x @ [W1a | W1b], N=1024
    {
        dim3 grid(2 * Dd / 64, Mrows / 128);
        mgemm_kernel<3,128><<<grid, blk, SMEM128>>>(xhi, xlo, w1th, w1tl, b1, nullptr,
                                                    ga, gbp, Mrows, 2 * Dd, Dd);
    }
    attn_kernel<<<Bb * NREG, blk>>>(ga, gbp, W2, b2, ridx, gw);
    agg_kernel<<<Bb * NREG, blk>>>(gw, x, ridx, mhi, mlo);
    {
        dim3 grid(Dd / 64, Mrows / 128);
        mgemm_kernel<2,128><<<grid, blk, SMEM128>>>(mhi, mlo, wg1th, wg1tl, bg1, x,
                                                    gx1, nullptr, Mrows, Dd, Dd);
    }
    agg_kernel<<<Bb * NREG, blk>>>(gw, gx1, ridx, mhi, mlo);
    {
        dim3 grid(Oo / 64, Mrows / 64);   // 4 x 64 = 256 CTAs (full chip)
        mgemm_kernel<1,64><<<grid, blk, SMEM64>>>(mhi, mlo, wg2th, wg2tl, bg2, nullptr,
                                                  out, nullptr, Mrows, Oo, Dd);
    }
}

// round 8
// speedup vs baseline: 3.0220x; 1.0308x over previous
#include <cuda_runtime.h>
#include <cuda_bf16.h>
#include <math.h>

#define Bb 64
#define Cc 64
#define Dd 512
#define Oo 256
#define NREG 8
#define Gg 8
#define Mrows (Bb*Cc)   // 4096

typedef __nv_bfloat16 bf16;

// ---------------- Scratch (device globals) ----------------
__device__ float g_a [Mrows*Dd];        // x @ W1a
__device__ float g_bp[Mrows*Dd];        // x @ W1b + b1
__device__ float g_y1[Mrows*Dd];        // x @ Wg1
__device__ float g_t [Mrows*Oo];        // x1 @ Wg2
__device__ float g_w [Bb*NREG*Gg*Gg];

__device__ bf16 g_xhi[Mrows*Dd],  g_xlo[Mrows*Dd];
__device__ bf16 g_x1hi[Mrows*Dd], g_x1lo[Mrows*Dd];
__device__ bf16 g_wbt_hi[3*Dd*Dd], g_wbt_lo[3*Dd*Dd];  // [W1a^T; W1b^T; Wg1^T] stacked [n][k]
__device__ bf16 g_wg2t_hi[Oo*Dd],  g_wg2t_lo[Oo*Dd];

// ---------------- async / ldmatrix helpers ----------------
__device__ __forceinline__ void cpasync16(void* smem, const void* g)
{
    unsigned sa = (unsigned)__cvta_generic_to_shared(smem);
    asm volatile("cp.async.cg.shared.global [%0], [%1], 16;" :: "r"(sa), "l"(g));
}
__device__ __forceinline__ void cp_commit() { asm volatile("cp.async.commit_group;"); }
template<int N> __device__ __forceinline__ void cp_wait()
{
    asm volatile("cp.async.wait_group %0;" :: "n"(N));
}
__device__ __forceinline__ void ldmx4(unsigned& r0, unsigned& r1, unsigned& r2,
                                      unsigned& r3, const void* p)
{
    unsigned a = (unsigned)__cvta_generic_to_shared(p);
    asm volatile("ldmatrix.sync.aligned.m8n8.x4.shared.b16 {%0,%1,%2,%3}, [%4];"
        : "=r"(r0), "=r"(r1), "=r"(r2), "=r"(r3) : "r"(a));
}
__device__ __forceinline__ void mma_bf16(float c[4],
    unsigned a0, unsigned a1, unsigned a2, unsigned a3,
    unsigned b0, unsigned b1)
{
    asm volatile(
        "mma.sync.aligned.m16n8k16.row.col.f32.bf16.bf16.f32 "
        "{%0,%1,%2,%3}, {%4,%5,%6,%7}, {%8,%9}, {%0,%1,%2,%3};\n"
        : "+f"(c[0]), "+f"(c[1]), "+f"(c[2]), "+f"(c[3])
        : "r"(a0), "r"(a1), "r"(a2), "r"(a3), "r"(b0), "r"(b1));
}

// ---------------- Combined prep kernel ----------------
__device__ __forceinline__ void transpose_tile(
    const float* __restrict__ src, bf16* __restrict__ dhi, bf16* __restrict__ dlo,
    int K, int N, int tn, int tk)
{
    __shared__ float tile[32][33];
    const int tid = threadIdx.x;
    const int k0 = tk * 32, n0 = tn * 32;
    const int tx = tid & 31, ty = tid >> 5;
    #pragma unroll
    for (int i = 0; i < 4; i++)
        tile[ty + 8 * i][tx] = src[(size_t)(k0 + ty + 8 * i) * N + n0 + tx];
    __syncthreads();
    const int nr = tid >> 4;
    const int kp = tid & 15;
    #pragma unroll
    for (int i = 0; i < 2; i++) {
        int n = n0 + nr + 16 * i;
        float v0 = tile[2 * kp    ][nr + 16 * i];
        float v1 = tile[2 * kp + 1][nr + 16 * i];
        bf16 h0 = __float2bfloat16_rn(v0), h1 = __float2bfloat16_rn(v1);
        bf16 l0 = __float2bfloat16_rn(v0 - __bfloat162float(h0));
        bf16 l1 = __float2bfloat16_rn(v1 - __bfloat162float(h1));
        __nv_bfloat162 ph = __halves2bfloat162(h0, h1);
        __nv_bfloat162 pl = __halves2bfloat162(l0, l1);
        *(__nv_bfloat162*)&dhi[(size_t)n * K + k0 + 2 * kp] = ph;
        *(__nv_bfloat162*)&dlo[(size_t)n * K + k0 + 2 * kp] = pl;
    }
}

__global__ __launch_bounds__(256)
void prep_kernel(const float* __restrict__ x, const float* __restrict__ W1,
                 const float* __restrict__ Wg1, const float* __restrict__ Wg2,
                 bf16* __restrict__ xhi, bf16* __restrict__ xlo,
                 bf16* __restrict__ wbth, bf16* __restrict__ wbtl,
                 bf16* __restrict__ wg2th, bf16* __restrict__ wg2tl)
{
    int b = blockIdx.x;
    if (b < 256) {
        transpose_tile(W1, wbth, wbtl, Dd, Dd, b & 15, b >> 4);
    } else if (b < 512) {
        b -= 256;
        transpose_tile(W1 + (size_t)Dd * Dd, wbth + (size_t)Dd * Dd,
                       wbtl + (size_t)Dd * Dd, Dd, Dd, b & 15, b >> 4);
    } else if (b < 768) {
        b -= 512;
        transpose_tile(Wg1, wbth + 2 * (size_t)Dd * Dd,
                       wbtl + 2 * (size_t)Dd * Dd, Dd, Dd, b & 15, b >> 4);
    } else if (b < 896) {
        b -= 768;
        transpose_tile(Wg2, wg2th, wg2tl, Dd, Oo, b & 7, b >> 3);
    } else {
        b -= 896;
        const float4* src = (const float4*)x;
        uint2* dh = (uint2*)xhi;
        uint2* dl = (uint2*)xlo;
        const int n4 = Mrows * Dd / 4;
        for (int i = b * 256 + threadIdx.x; i < n4; i += 128 * 256) {
            float4 v = src[i];
            bf16 h0 = __float2bfloat16_rn(v.x), h1 = __float2bfloat16_rn(v.y);
            bf16 h2 = __float2bfloat16_rn(v.z), h3 = __float2bfloat16_rn(v.w);
            bf16 l0 = __float2bfloat16_rn(v.x - __bfloat162float(h0));
            bf16 l1 = __float2bfloat16_rn(v.y - __bfloat162float(h1));
            bf16 l2 = __float2bfloat16_rn(v.z - __bfloat162float(h2));
            bf16 l3 = __float2bfloat16_rn(v.w - __bfloat162float(h3));
            __nv_bfloat162 ph0 = __halves2bfloat162(h0, h1), ph1 = __halves2bfloat162(h2, h3);
            __nv_bfloat162 pl0 = __halves2bfloat162(l0, l1), pl1 = __halves2bfloat162(l2, l3);
            dh[i] = make_uint2(*(unsigned*)&ph0, *(unsigned*)&ph1);
            dl[i] = make_uint2(*(unsigned*)&pl0, *(unsigned*)&pl1);
        }
    }
}

// ---------------- split-bf16 tensor-core GEMM ----------------
// BN=64, BK=32, 3-stage cp.async, ldmatrix. Template BM in {128, 64}.
// MODE 0: raw (+bias if non-null)
// MODE 4: triple route: col<512 -> C raw; 512..1023 -> C2 + bias; >=1024 -> C3 raw
template<int MODE, int BM>
__global__ __launch_bounds__(256, 2)
void mgemm_kernel(const bf16* __restrict__ Ahi, const bf16* __restrict__ Alo,
                  const bf16* __restrict__ Bth, const bf16* __restrict__ Btl,
                  const float* __restrict__ bias,
                  float* __restrict__ C, float* __restrict__ C2,
                  float* __restrict__ C3, int N, int K)
{
    constexpr int BN = 64, BK = 32, LDT = 40, STAGES = 3;
    constexpr int WROWS = BM / 32;
    constexpr int NT = WROWS;
    constexpr int P  = (WROWS / 2) ? WROWS / 2 : 1;
    constexpr int WCOLS = 8 * NT;
    constexpr int A_SZ = BM * LDT;
    constexpr int B_SZ = BN * LDT;
    constexpr int STG  = 2 * A_SZ + 2 * B_SZ;
    constexpr int ACH  = BM / 64;
    extern __shared__ bf16 dsm[];

    const int tid  = threadIdx.x;
    const int wid  = tid >> 5;
    const int lane = tid & 31;
    const int wm   = wid % WROWS;
    const int wn   = wid / WROWS;
    const int row0 = blockIdx.y * BM;
    const int col0 = blockIdx.x * BN;
    const int g = lane >> 2;
    const int t = lane & 3;
    const int lq = lane >> 3, li = lane & 7;
    const int fr_off = (lq & 1) * 8 + li;
    const int fk_off = (lq >> 1) * 8;

    float acc[2][NT][4];
    #pragma unroll
    for (int mt = 0; mt < 2; mt++)
        #pragma unroll
        for (int nt = 0; nt < NT; nt++)
            #pragma unroll
            for (int q = 0; q < 4; q++) acc[mt][nt][q] = 0.f;

    auto load_stage = [&](int st, int kt) {
        bf16* sAh = dsm + st * STG;
        bf16* sAl = sAh + A_SZ;
        bf16* sBh = sAl + A_SZ;
        bf16* sBl = sBh + B_SZ;
        #pragma unroll
        for (int i = 0; i < ACH; i++) {
            int id = tid * ACH + i;
            int r = id >> 2, c = (id & 3) * 8;
            size_t go = (size_t)(row0 + r) * K + kt + c;
            cpasync16(sAh + r * LDT + c, Ahi + go);
            cpasync16(sAl + r * LDT + c, Alo + go);
        }
        {
            int r = tid >> 2, c = (tid & 3) * 8;
            size_t go = (size_t)(col0 + r) * K + kt + c;
            cpasync16(sBh + r * LDT + c, Bth + go);
            cpasync16(sBl + r * LDT + c, Btl + go);
        }
    };

    const int nk = K / BK;
    load_stage(0, 0); cp_commit();
    load_stage(1, BK); cp_commit();

    for (int s = 0; s < nk; s++) {
        if (s + 2 < nk) { load_stage((s + 2) % STAGES, (s + 2) * BK); cp_commit(); cp_wait<2>(); }
        else if (s + 1 < nk) { cp_wait<1>(); }
        else { cp_wait<0>(); }
        __syncthreads();

        const int st = s % STAGES;
        bf16* sAh = dsm + st * STG;
        bf16* sAl = sAh + A_SZ;
        bf16* sBh = sAl + A_SZ;
        bf16* sBl = sBh + B_SZ;

        #pragma unroll
        for (int kk = 0; kk < BK; kk += 16) {
            unsigned ah[2][4], al[2][4], bhv[P][4], blv[P][4];
            #pragma unroll
            for (int mt = 0; mt < 2; mt++) {
                const bf16* pa = sAh + (wm * 32 + mt * 16 + fr_off) * LDT + kk + fk_off;
                ldmx4(ah[mt][0], ah[mt][1], ah[mt][2], ah[mt][3], pa);
                const bf16* pl = sAl + (wm * 32 + mt * 16 + fr_off) * LDT + kk + fk_off;
                ldmx4(al[mt][0], al[mt][1], al[mt][2], al[mt][3], pl);
            }
            #pragma unroll
            for (int p = 0; p < P; p++) {
                const bf16* pb = sBh + (wn * WCOLS + p * 16 + fr_off) * LDT + kk + fk_off;
                ldmx4(bhv[p][0], bhv[p][1], bhv[p][2], bhv[p][3], pb);
                const bf16* pc = sBl + (wn * WCOLS + p * 16 + fr_off) * LDT + kk + fk_off;
                ldmx4(blv[p][0], blv[p][1], blv[p][2], blv[p][3], pc);
            }
            #pragma unroll
            for (int mt = 0; mt < 2; mt++)
                #pragma unroll
                for (int nt = 0; nt < NT; nt++) {
                    const int p = nt >> 1, o = nt & 1;
                    unsigned b0h = bhv[p][o], b1h = bhv[p][2 + o];
                    unsigned b0l = blv[p][o], b1l = blv[p][2 + o];
                    mma_bf16(acc[mt][nt], ah[mt][0], ah[mt][1], ah[mt][2], ah[mt][3], b0h, b1h);
                    mma_bf16(acc[mt][nt], ah[mt][0], ah[mt][1], ah[mt][2], ah[mt][3], b0l, b1l);
                    mma_bf16(acc[mt][nt], al[mt][0], al[mt][1], al[mt][2], al[mt][3], b0h, b1h);
                }
        }
        __syncthreads();
    }

    #pragma unroll
    for (int mt = 0; mt < 2; mt++) {
        int rbase = row0 + wm * 32 + mt * 16;
        #pragma unroll
        for (int nt = 0; nt < NT; nt++) {
            int cb = col0 + wn * WCOLS + nt * 8 + 2 * t;
            #pragma unroll
            for (int h = 0; h < 2; h++) {
                int r = rbase + g + 8 * h;
                float v0 = acc[mt][nt][2*h];
                float v1 = acc[mt][nt][2*h + 1];
                if (MODE == 4) {
                    if (cb < Dd) {
                        *(float2*)(C + (size_t)r * Dd + cb) = make_float2(v0, v1);
                    } else if (cb < 2 * Dd) {
                        int c2 = cb - Dd;
                        v0 += bias[c2]; v1 += bias[c2 + 1];
                        *(float2*)(C2 + (size_t)r * Dd + c2) = make_float2(v0, v1);
                    } else {
                        int c3 = cb - 2 * Dd;
                        *(float2*)(C3 + (size_t)r * Dd + c3) = make_float2(v0, v1);
                    }
                } else {
                    if (bias) { v0 += bias[cb]; v1 += bias[cb + 1]; }
                    *(float2*)(C + (size_t)r * N + cb) = make_float2(v0, v1);
                }
            }
        }
    }
}

// ---------------------------------------------------------------------------
// Attention
// ---------------------------------------------------------------------------
__global__ __launch_bounds__(256)
void attn_kernel(const float* __restrict__ a, const float* __restrict__ bp,
                 const float* __restrict__ W2, const float* __restrict__ b2,
                 const int* __restrict__ ridx, float* __restrict__ wout)
{
    __shared__ float sa[Gg][Dd];
    __shared__ float sb[Gg][Dd];
    __shared__ float sw2[Dd];
    __shared__ float ssc[Gg][Gg];
    __shared__ int   ch[Gg];

    const int tid  = threadIdx.x;
    const int blk  = blockIdx.x;
    const int b    = blk >> 3;
    const int r    = blk & 7;

    if (tid < Gg) ch[tid] = ridx[r * Gg + tid];
    __syncthreads();

    for (int d = tid; d < Dd; d += 256) sw2[d] = W2[d];
    #pragma unroll
    for (int j = 0; j < Gg; j++) {
        const float* arow = a  + (size_t)(b * Cc + ch[j]) * Dd;
        const float* brow = bp + (size_t)(b * Cc + ch[j]) * Dd;
        for (int d = tid; d < Dd; d += 256) {
            sa[j][d] = arow[d];
            sb[j][d] = brow[d];
        }
    }
    __syncthreads();

    const int wid  = tid >> 5;
    const int lane = tid & 31;
    float accq[Gg];
    #pragma unroll
    for (int q = 0; q < Gg; q++) accq[q] = 0.f;
    for (int t = lane; t < Dd; t += 32) {
        float av = sa[wid][t];
        float wv = sw2[t];
        #pragma unroll
        for (int q = 0; q < Gg; q++) {
            float v = av + sb[q][t];
            v = fmaxf(v, 0.f);
            accq[q] = fmaf(v, wv, accq[q]);
        }
    }
    #pragma unroll
    for (int q = 0; q < Gg; q++) {
        #pragma unroll
        for (int off = 16; off > 0; off >>= 1)
            accq[q] += __shfl_xor_sync(0xffffffffu, accq[q], off);
    }
    if (lane == 0) {
        float bb2 = b2[0];
        #pragma unroll
        for (int q = 0; q < Gg; q++) ssc[wid][q] = accq[q] + bb2;
    }
    __syncthreads();

    if (tid < Gg) {
        int i = tid;
        float mx = -1e30f;
        #pragma unroll
        for (int j = 0; j < Gg; j++)
            if (j != i) mx = fmaxf(mx, ssc[i][j]);
        float e[Gg]; float s = 0.f;
        #pragma unroll
        for (int j = 0; j < Gg; j++) {
            e[j] = (j == i) ? 0.f : __expf(ssc[i][j] - mx);
            s += e[j];
        }
        float inv = 1.f / s;
        float* wrow = wout + ((size_t)blk * Gg + i) * Gg;
        #pragma unroll
        for (int j = 0; j < Gg; j++) wrow[j] = e[j] * inv;
    }
}

// ---------------------------------------------------------------------------
// agg1x: x1 = 0.5*leaky(adj @ y1 + bg1) + 0.5*x  -> write hi/lo bf16 only
// ---------------------------------------------------------------------------
__global__ __launch_bounds__(256)
void agg1x_kernel(const float* __restrict__ w, const float* __restrict__ y1,
                  const float* __restrict__ x, const float* __restrict__ bg1,
                  const int* __restrict__ ridx,
                  bf16* __restrict__ x1hi, bf16* __restrict__ x1lo)
{
    __shared__ float4 ys[Gg][Dd / 4];   // 16 KB
    __shared__ float  ww[Gg * Gg];
    __shared__ int    ch[Gg];

    const int tid = threadIdx.x;
    const int blk = blockIdx.x;
    const int b   = blk >> 3;
    const int r   = blk & 7;

    if (tid < Gg) ch[tid] = ridx[r * Gg + tid];
    if (tid >= 64 && tid < 128) ww[tid - 64] = w[(size_t)blk * 64 + (tid - 64)];
    __syncthreads();

    #pragma unroll
    for (int u = 0; u < 4; u++) {
        int id = tid + 256 * u;
        int j = id >> 7, d4 = id & 127;
        ys[j][d4] = ((const float4*)(y1 + (size_t)(b * Cc + ch[j]) * Dd))[d4];
    }
    __syncthreads();

    #pragma unroll
    for (int u = 0; u < 4; u++) {
        int id = tid + 256 * u;
        int i = id >> 7, d4 = id & 127;
        float wi[Gg];
        #pragma unroll
        for (int j = 0; j < Gg; j++) wi[j] = ww[i * Gg + j];
        float4 acc = make_float4(0.f, 0.f, 0.f, 0.f);
        #pragma unroll
        for (int j = 0; j < Gg; j++) {
            float4 yv = ys[j][d4];
            acc.x = fmaf(wi[j], yv.x, acc.x);
            acc.y = fmaf(wi[j], yv.y, acc.y);
            acc.z = fmaf(wi[j], yv.z, acc.z);
            acc.w = fmaf(wi[j], yv.w, acc.w);
        }
        size_t rowoff = (size_t)(b * Cc + ch[i]) * Dd;
        float4 bv = ((const float4*)bg1)[d4];
        float4 xv = ((const float4*)(x + rowoff))[d4];
        float z0 = acc.x + bv.x, z1 = acc.y + bv.y, z2 = acc.z + bv.z, z3 = acc.w + bv.w;
        z0 = (z0 >= 0.f) ? z0 : 0.2f * z0;
        z1 = (z1 >= 0.f) ? z1 : 0.2f * z1;
        z2 = (z2 >= 0.f) ? z2 : 0.2f * z2;
        z3 = (z3 >= 0.f) ? z3 : 0.2f * z3;
        float v0 = 0.5f * z0 + 0.5f * xv.x;
        float v1 = 0.5f * z1 + 0.5f * xv.y;
        float v2 = 0.5f * z2 + 0.5f * xv.z;
        float v3 = 0.5f * z3 + 0.5f * xv.w;
        bf16 h0 = __float2bfloat16_rn(v0), h1 = __float2bfloat16_rn(v1);
        bf16 h2 = __float2bfloat16_rn(v2), h3 = __float2bfloat16_rn(v3);
        bf16 l0 = __float2bfloat16_rn(v0 - __bfloat162float(h0));
        bf16 l1 = __float2bfloat16_rn(v1 - __bfloat162float(h1));
        bf16 l2 = __float2bfloat16_rn(v2 - __bfloat162float(h2));
        bf16 l3 = __float2bfloat16_rn(v3 - __bfloat162float(h3));
        __nv_bfloat162 ph0 = __halves2bfloat162(h0, h1), ph1 = __halves2bfloat162(h2, h3);
        __nv_bfloat162 pl0 = __halves2bfloat162(l0, l1), pl1 = __halves2bfloat162(l2, l3);
        ((uint2*)(x1hi + rowoff))[d4] = make_uint2(*(unsigned*)&ph0, *(unsigned*)&ph1);
        ((uint2*)(x1lo + rowoff))[d4] = make_uint2(*(unsigned*)&pl0, *(unsigned*)&pl1);
    }
}

// ---------------------------------------------------------------------------
// agg2x: out = leaky(adj @ t + bg2)   (t: [Mrows, Oo] fp32) -> out fp32
// ---------------------------------------------------------------------------
__global__ __launch_bounds__(256)
void agg2x_kernel(const float* __restrict__ w, const float* __restrict__ t,
                  const float* __restrict__ bg2, const int* __restrict__ ridx,
                  float* __restrict__ out)
{
    __shared__ float4 ts[Gg][Oo / 4];   // 8 KB
    __shared__ float  ww[Gg * Gg];
    __shared__ int    ch[Gg];

    const int tid = threadIdx.x;
    const int blk = blockIdx.x;
    const int b   = blk >> 3;
    const int r   = blk & 7;

    if (tid < Gg) ch[tid] = ridx[r * Gg + tid];
    if (tid >= 64 && tid < 128) ww[tid - 64] = w[(size_t)blk * 64 + (tid - 64)];
    __syncthreads();

    #pragma unroll
    for (int u = 0; u < 2; u++) {
        int id = tid + 256 * u;
        int j = id >> 6, d4 = id & 63;
        ts[j][d4] = ((const float4*)(t + (size_t)(b * Cc + ch[j]) * Oo))[d4];
    }
    __syncthreads();

    #pragma unroll
    for (int u = 0; u < 2; u++) {
        int id = tid + 256 * u;
        int i = id >> 6, d4 = id & 63;
        float wi[Gg];
        #pragma unroll
        for (int j = 0; j < Gg; j++) wi[j] = ww[i * Gg + j];
        float4 acc = make_float4(0.f, 0.f, 0.f, 0.f);
        #pragma unroll
        for (int j = 0; j < Gg; j++) {
            float4 tv = ts[j][d4];
            acc.x = fmaf(wi[j], tv.x, acc.x);
            acc.y = fmaf(wi[j], tv.y, acc.y);
            acc.z = fmaf(wi[j], tv.z, acc.z);
            acc.w = fmaf(wi[j], tv.w, acc.w);
        }
        float4 bv = ((const float4*)bg2)[d4];
        float v0 = acc.x + bv.x, v1 = acc.y + bv.y;
        float v2 = acc.z + bv.z, v3 = acc.w + bv.w;
        v0 = (v0 >= 0.f) ? v0 : 0.2f * v0;
        v1 = (v1 >= 0.f) ? v1 : 0.2f * v1;
        v2 = (v2 >= 0.f) ? v2 : 0.2f * v2;
        v3 = (v3 >= 0.f) ? v3 : 0.2f * v3;
        ((float4*)(out + (size_t)(b * Cc + ch[i]) * Oo))[d4] = make_float4(v0, v1, v2, v3);
    }
}

// ---------------------------------------------------------------------------
extern "C" void kernel_launch(void* const* d_in, const int* in_sizes, int n_in,
                              void* d_out, int out_size)
{
    const float* x    = (const float*)d_in[0];
    const float* W1   = (const float*)d_in[1];
    const float* b1   = (const float*)d_in[2];
    const float* W2   = (const float*)d_in[3];
    const float* b2   = (const float*)d_in[4];
    const float* Wg1  = (const float*)d_in[5];
    const float* bg1  = (const float*)d_in[6];
    const float* Wg2  = (const float*)d_in[7];
    const float* bg2  = (const float*)d_in[8];
    const int*   ridx = (const int*)d_in[9];
    float* out = (float*)d_out;

    float *ga, *gbp, *gy1, *gt, *gw;
    bf16 *xhi, *xlo, *x1hi, *x1lo;
    bf16 *wbth, *wbtl, *wg2th, *wg2tl;
    cudaGetSymbolAddress((void**)&ga,   g_a);
    cudaGetSymbolAddress((void**)&gbp,  g_bp);
    cudaGetSymbolAddress((void**)&gy1,  g_y1);
    cudaGetSymbolAddress((void**)&gt,   g_t);
    cudaGetSymbolAddress((void**)&gw,   g_w);
    cudaGetSymbolAddress((void**)&xhi,  g_xhi);
    cudaGetSymbolAddress((void**)&xlo,  g_xlo);
    cudaGetSymbolAddress((void**)&x1hi, g_x1hi);
    cudaGetSymbolAddress((void**)&x1lo, g_x1lo);
    cudaGetSymbolAddress((void**)&wbth, g_wbt_hi);
    cudaGetSymbolAddress((void**)&wbtl, g_wbt_lo);
    cudaGetSymbolAddress((void**)&wg2th, g_wg2t_hi);
    cudaGetSymbolAddress((void**)&wg2tl, g_wg2t_lo);

    const int SMEM128 = 3 * (2 * 128 * 40 + 2 * 64 * 40) * (int)sizeof(bf16);  // 92160
    const int SMEM64  = 3 * (2 *  64 * 40 + 2 * 64 * 40) * (int)sizeof(bf16);  // 61440
    cudaFuncSetAttribute(mgemm_kernel<4,128>, cudaFuncAttributeMaxDynamicSharedMemorySize, SMEM128);
    cudaFuncSetAttribute(mgemm_kernel<0,64>,  cudaFuncAttributeMaxDynamicSharedMemorySize, SMEM64);

    prep_kernel<<<1024, 256>>>(x, W1, Wg1, Wg2, xhi, xlo,
                               wbth, wbtl, wg2th, wg2tl);

    // G1': [a | bp | y1] = x @ [W1a | W1b | Wg1]  (N=1536)
    {
        dim3 grid(3 * Dd / 64, Mrows / 128);   // 24 x 32 = 768 CTAs
        mgemm_kernel<4,128><<<grid, 256, SMEM128>>>(xhi, xlo, wbth, wbtl, b1,
                                                    ga, gbp, gy1, 3 * Dd, Dd);
    }
    attn_kernel<<<Bb * NREG, 256>>>(ga, gbp, W2, b2, ridx, gw);
    // x1 = 0.5*leaky(adj@y1 + bg1) + 0.5*x  (hi/lo only)
    agg1x_kernel<<<Bb * NREG, 256>>>(gw, gy1, x, bg1, ridx, x1hi, x1lo);
    // G3': t = x1 @ Wg2  (raw)
    {
        dim3 grid(Oo / 64, Mrows / 64);        // 4 x 64 = 256 CTAs
        mgemm_kernel<0,64><<<grid, 256, SMEM64>>>(x1hi, x1lo, wg2th, wg2tl, nullptr,
                                                  gt, nullptr, nullptr, Oo, Dd);
    }
    // out = leaky(adj@t + bg2)
    agg2x_kernel<<<Bb * NREG, 256>>>(gw, gt, bg2, ridx, out);
}

// round 9
// speedup vs baseline: 4.3902x; 1.4527x over previous
#include <cuda_runtime.h>
#include <cuda_fp16.h>
#include <math.h>

#define Bb 64
#define Cc 64
#define Dd 512
#define Oo 256
#define NREG 8
#define Gg 8
#define Mrows (Bb*Cc)   // 4096

// ---------------- Scratch (device globals) ----------------
__device__ float g_a [Mrows*Dd];        // x @ W1a
__device__ float g_bp[Mrows*Dd];        // x @ W1b + b1
__device__ float g_y1[Mrows*Dd];        // x @ Wg1
__device__ float g_t [Mrows*Oo];        // x1 @ Wg2
__device__ float g_w [Bb*NREG*Gg*Gg];

__device__ __half g_xh [Mrows*Dd];      // x  (single fp16)
__device__ __half g_x1h[Mrows*Dd];      // x1 (single fp16)
__device__ __half g_wbt_hi[3*Dd*Dd], g_wbt_lo[3*Dd*Dd];  // [W1a^T; W1b^T; Wg1^T] [n][k]
__device__ __half g_wg2t_hi[Oo*Dd],   g_wg2t_lo[Oo*Dd];

// ---------------- async / ldmatrix helpers ----------------
__device__ __forceinline__ void cpasync16(void* smem, const void* g)
{
    unsigned sa = (unsigned)__cvta_generic_to_shared(smem);
    asm volatile("cp.async.cg.shared.global [%0], [%1], 16;" :: "r"(sa), "l"(g));
}
__device__ __forceinline__ void cp_commit() { asm volatile("cp.async.commit_group;"); }
template<int N> __device__ __forceinline__ void cp_wait()
{
    asm volatile("cp.async.wait_group %0;" :: "n"(N));
}
__device__ __forceinline__ void ldmx4(unsigned& r0, unsigned& r1, unsigned& r2,
                                      unsigned& r3, const void* p)
{
    unsigned a = (unsigned)__cvta_generic_to_shared(p);
    asm volatile("ldmatrix.sync.aligned.m8n8.x4.shared.b16 {%0,%1,%2,%3}, [%4];"
        : "=r"(r0), "=r"(r1), "=r"(r2), "=r"(r3) : "r"(a));
}
__device__ __forceinline__ void mma_f16(float c[4],
    unsigned a0, unsigned a1, unsigned a2, unsigned a3,
    unsigned b0, unsigned b1)
{
    asm volatile(
        "mma.sync.aligned.m16n8k16.row.col.f32.f16.f16.f32 "
        "{%0,%1,%2,%3}, {%4,%5,%6,%7}, {%8,%9}, {%0,%1,%2,%3};\n"
        : "+f"(c[0]), "+f"(c[1]), "+f"(c[2]), "+f"(c[3])
        : "r"(a0), "r"(a1), "r"(a2), "r"(a3), "r"(b0), "r"(b1));
}
__device__ __forceinline__ unsigned pack_half2(float a, float b)
{
    __half2 h = __halves2half2(__float2half_rn(a), __float2half_rn(b));
    return *(unsigned*)&h;
}

// ---------------- Combined prep kernel ----------------
// Transpose fp32 [K][N] -> fp16 hi/lo [N][K]
__device__ __forceinline__ void transpose_tile(
    const float* __restrict__ src, __half* __restrict__ dhi, __half* __restrict__ dlo,
    int K, int N, int tn, int tk)
{
    __shared__ float tile[32][33];
    const int tid = threadIdx.x;
    const int k0 = tk * 32, n0 = tn * 32;
    const int tx = tid & 31, ty = tid >> 5;
    #pragma unroll
    for (int i = 0; i < 4; i++)
        tile[ty + 8 * i][tx] = src[(size_t)(k0 + ty + 8 * i) * N + n0 + tx];
    __syncthreads();
    const int nr = tid >> 4;
    const int kp = tid & 15;
    #pragma unroll
    for (int i = 0; i < 2; i++) {
        int n = n0 + nr + 16 * i;
        float v0 = tile[2 * kp    ][nr + 16 * i];
        float v1 = tile[2 * kp + 1][nr + 16 * i];
        __half h0 = __float2half_rn(v0), h1 = __float2half_rn(v1);
        __half l0 = __float2half_rn(v0 - __half2float(h0));
        __half l1 = __float2half_rn(v1 - __half2float(h1));
        __half2 ph = __halves2half2(h0, h1);
        __half2 pl = __halves2half2(l0, l1);
        *(__half2*)&dhi[(size_t)n * K + k0 + 2 * kp] = ph;
        *(__half2*)&dlo[(size_t)n * K + k0 + 2 * kp] = pl;
    }
}

__global__ __launch_bounds__(256)
void prep_kernel(const float* __restrict__ x, const float* __restrict__ W1,
                 const float* __restrict__ Wg1, const float* __restrict__ Wg2,
                 __half* __restrict__ xh,
                 __half* __restrict__ wbth, __half* __restrict__ wbtl,
                 __half* __restrict__ wg2th, __half* __restrict__ wg2tl)
{
    int b = blockIdx.x;
    if (b < 256) {
        transpose_tile(W1, wbth, wbtl, Dd, Dd, b & 15, b >> 4);
    } else if (b < 512) {
        b -= 256;
        transpose_tile(W1 + (size_t)Dd * Dd, wbth + (size_t)Dd * Dd,
                       wbtl + (size_t)Dd * Dd, Dd, Dd, b & 15, b >> 4);
    } else if (b < 768) {
        b -= 512;
        transpose_tile(Wg1, wbth + 2 * (size_t)Dd * Dd,
                       wbtl + 2 * (size_t)Dd * Dd, Dd, Dd, b & 15, b >> 4);
    } else if (b < 896) {
        b -= 768;
        transpose_tile(Wg2, wg2th, wg2tl, Dd, Oo, b & 7, b >> 3);
    } else {
        b -= 896;   // 128 blocks: x -> fp16 (single)
        const float4* src = (const float4*)x;
        uint2* dh = (uint2*)xh;
        const int n4 = Mrows * Dd / 4;
        for (int i = b * 256 + threadIdx.x; i < n4; i += 128 * 256) {
            float4 v = src[i];
            dh[i] = make_uint2(pack_half2(v.x, v.y), pack_half2(v.z, v.w));
        }
    }
}

// ---------------- fp16 2-term tensor-core GEMM ----------------
// A single fp16; B split hi/lo fp16 (weights exact). BN=64, BK=32, 3-stage.
// MODE 0: raw (+bias if non-null)
// MODE 4: triple route: col<512 -> C raw; 512..1023 -> C2 + bias; >=1024 -> C3 raw
template<int MODE, int BM>
__global__ __launch_bounds__(256, 2)
void mgemm_kernel(const __half* __restrict__ A,
                  const __half* __restrict__ Bth, const __half* __restrict__ Btl,
                  const float* __restrict__ bias,
                  float* __restrict__ C, float* __restrict__ C2,
                  float* __restrict__ C3, int N, int K)
{
    constexpr int BN = 64, BK = 32, LDT = 40, STAGES = 3;
    constexpr int WROWS = BM / 32;
    constexpr int NT = WROWS;
    constexpr int P  = (WROWS / 2) ? WROWS / 2 : 1;
    constexpr int WCOLS = 8 * NT;
    constexpr int A_SZ = BM * LDT;
    constexpr int B_SZ = BN * LDT;
    constexpr int STG  = A_SZ + 2 * B_SZ;
    constexpr int ACH  = BM / 64;       // A 16B-chunks per thread (2 or 1)
    extern __shared__ __half dsm[];

    const int tid  = threadIdx.x;
    const int wid  = tid >> 5;
    const int lane = tid & 31;
    const int wm   = wid % WROWS;
    const int wn   = wid / WROWS;
    const int row0 = blockIdx.y * BM;
    const int col0 = blockIdx.x * BN;
    const int g = lane >> 2;
    const int t = lane & 3;
    const int lq = lane >> 3, li = lane & 7;
    const int fr_off = (lq & 1) * 8 + li;
    const int fk_off = (lq >> 1) * 8;

    float acc[2][NT][4];
    #pragma unroll
    for (int mt = 0; mt < 2; mt++)
        #pragma unroll
        for (int nt = 0; nt < NT; nt++)
            #pragma unroll
            for (int q = 0; q < 4; q++) acc[mt][nt][q] = 0.f;

    auto load_stage = [&](int st, int kt) {
        __half* sA  = dsm + st * STG;
        __half* sBh = sA + A_SZ;
        __half* sBl = sBh + B_SZ;
        #pragma unroll
        for (int i = 0; i < ACH; i++) {
            int id = tid * ACH + i;
            int r = id >> 2, c = (id & 3) * 8;
            cpasync16(sA + r * LDT + c, A + (size_t)(row0 + r) * K + kt + c);
        }
        {
            int r = tid >> 2, c = (tid & 3) * 8;
            size_t go = (size_t)(col0 + r) * K + kt + c;
            cpasync16(sBh + r * LDT + c, Bth + go);
            cpasync16(sBl + r * LDT + c, Btl + go);
        }
    };

    const int nk = K / BK;
    load_stage(0, 0); cp_commit();
    load_stage(1, BK); cp_commit();

    for (int s = 0; s < nk; s++) {
        if (s + 2 < nk) { load_stage((s + 2) % STAGES, (s + 2) * BK); cp_commit(); cp_wait<2>(); }
        else if (s + 1 < nk) { cp_wait<1>(); }
        else { cp_wait<0>(); }
        __syncthreads();

        const int st = s % STAGES;
        __half* sA  = dsm + st * STG;
        __half* sBh = sA + A_SZ;
        __half* sBl = sBh + B_SZ;

        #pragma unroll
        for (int kk = 0; kk < BK; kk += 16) {
            unsigned ah[2][4], bhv[P][4], blv[P][4];
            #pragma unroll
            for (int mt = 0; mt < 2; mt++) {
                const __half* pa = sA + (wm * 32 + mt * 16 + fr_off) * LDT + kk + fk_off;
                ldmx4(ah[mt][0], ah[mt][1], ah[mt][2], ah[mt][3], pa);
            }
            #pragma unroll
            for (int p = 0; p < P; p++) {
                const __half* pb = sBh + (wn * WCOLS + p * 16 + fr_off) * LDT + kk + fk_off;
                ldmx4(bhv[p][0], bhv[p][1], bhv[p][2], bhv[p][3], pb);
                const __half* pc = sBl + (wn * WCOLS + p * 16 + fr_off) * LDT + kk + fk_off;
                ldmx4(blv[p][0], blv[p][1], blv[p][2], blv[p][3], pc);
            }
            #pragma unroll
            for (int mt = 0; mt < 2; mt++)
                #pragma unroll
                for (int nt = 0; nt < NT; nt++) {
                    const int p = nt >> 1, o = nt & 1;
                    mma_f16(acc[mt][nt], ah[mt][0], ah[mt][1], ah[mt][2], ah[mt][3],
                            bhv[p][o], bhv[p][2 + o]);
                    mma_f16(acc[mt][nt], ah[mt][0], ah[mt][1], ah[mt][2], ah[mt][3],
                            blv[p][o], blv[p][2 + o]);
                }
        }
        __syncthreads();
    }

    #pragma unroll
    for (int mt = 0; mt < 2; mt++) {
        int rbase = row0 + wm * 32 + mt * 16;
        #pragma unroll
        for (int nt = 0; nt < NT; nt++) {
            int cb = col0 + wn * WCOLS + nt * 8 + 2 * t;
            #pragma unroll
            for (int h = 0; h < 2; h++) {
                int r = rbase + g + 8 * h;
                float v0 = acc[mt][nt][2*h];
                float v1 = acc[mt][nt][2*h + 1];
                if (MODE == 4) {
                    if (cb < Dd) {
                        *(float2*)(C + (size_t)r * Dd + cb) = make_float2(v0, v1);
                    } else if (cb < 2 * Dd) {
                        int c2 = cb - Dd;
                        v0 += bias[c2]; v1 += bias[c2 + 1];
                        *(float2*)(C2 + (size_t)r * Dd + c2) = make_float2(v0, v1);
                    } else {
                        int c3 = cb - 2 * Dd;
                        *(float2*)(C3 + (size_t)r * Dd + c3) = make_float2(v0, v1);
                    }
                } else {
                    if (bias) { v0 += bias[cb]; v1 += bias[cb + 1]; }
                    *(float2*)(C + (size_t)r * N + cb) = make_float2(v0, v1);
                }
            }
        }
    }
}

// ---------------------------------------------------------------------------
// Attention
// ---------------------------------------------------------------------------
__global__ __launch_bounds__(256)
void attn_kernel(const float* __restrict__ a, const float* __restrict__ bp,
                 const float* __restrict__ W2, const float* __restrict__ b2,
                 const int* __restrict__ ridx, float* __restrict__ wout)
{
    __shared__ float sa[Gg][Dd];
    __shared__ float sb[Gg][Dd];
    __shared__ float sw2[Dd];
    __shared__ float ssc[Gg][Gg];
    __shared__ int   ch[Gg];

    const int tid  = threadIdx.x;
    const int blk  = blockIdx.x;
    const int b    = blk >> 3;
    const int r    = blk & 7;

    if (tid < Gg) ch[tid] = ridx[r * Gg + tid];
    __syncthreads();

    for (int d = tid; d < Dd; d += 256) sw2[d] = W2[d];
    #pragma unroll
    for (int j = 0; j < Gg; j++) {
        const float* arow = a  + (size_t)(b * Cc + ch[j]) * Dd;
        const float* brow = bp + (size_t)(b * Cc + ch[j]) * Dd;
        for (int d = tid; d < Dd; d += 256) {
            sa[j][d] = arow[d];
            sb[j][d] = brow[d];
        }
    }
    __syncthreads();

    const int wid  = tid >> 5;
    const int lane = tid & 31;
    float accq[Gg];
    #pragma unroll
    for (int q = 0; q < Gg; q++) accq[q] = 0.f;
    for (int t = lane; t < Dd; t += 32) {
        float av = sa[wid][t];
        float wv = sw2[t];
        #pragma unroll
        for (int q = 0; q < Gg; q++) {
            float v = av + sb[q][t];
            v = fmaxf(v, 0.f);
            accq[q] = fmaf(v, wv, accq[q]);
        }
    }
    #pragma unroll
    for (int q = 0; q < Gg; q++) {
        #pragma unroll
        for (int off = 16; off > 0; off >>= 1)
            accq[q] += __shfl_xor_sync(0xffffffffu, accq[q], off);
    }
    if (lane == 0) {
        float bb2 = b2[0];
        #pragma unroll
        for (int q = 0; q < Gg; q++) ssc[wid][q] = accq[q] + bb2;
    }
    __syncthreads();

    if (tid < Gg) {
        int i = tid;
        float mx = -1e30f;
        #pragma unroll
        for (int j = 0; j < Gg; j++)
            if (j != i) mx = fmaxf(mx, ssc[i][j]);
        float e[Gg]; float s = 0.f;
        #pragma unroll
        for (int j = 0; j < Gg; j++) {
            e[j] = (j == i) ? 0.f : __expf(ssc[i][j] - mx);
            s += e[j];
        }
        float inv = 1.f / s;
        float* wrow = wout + ((size_t)blk * Gg + i) * Gg;
        #pragma unroll
        for (int j = 0; j < Gg; j++) wrow[j] = e[j] * inv;
    }
}

// ---------------------------------------------------------------------------
// agg1x: x1 = 0.5*leaky(adj @ y1 + bg1) + 0.5*x  -> single fp16
// grid (512, 2): D split in halves for latency hiding
// ---------------------------------------------------------------------------
__global__ __launch_bounds__(256)
void agg1x_kernel(const float* __restrict__ w, const float* __restrict__ y1,
                  const float* __restrict__ x, const float* __restrict__ bg1,
                  const int* __restrict__ ridx, __half* __restrict__ x1h)
{
    __shared__ float4 ys[Gg][64];   // 8 KB (half of D)
    __shared__ float  ww[Gg * Gg];
    __shared__ int    ch[Gg];

    const int tid = threadIdx.x;
    const int blk = blockIdx.x;
    const int b   = blk >> 3;
    const int r   = blk & 7;
    const int d0  = blockIdx.y * 64;   // float4 offset

    if (tid < Gg) ch[tid] = ridx[r * Gg + tid];
    if (tid >= 64 && tid < 128) ww[tid - 64] = w[(size_t)blk * 64 + (tid - 64)];
    __syncthreads();

    #pragma unroll
    for (int u = 0; u < 2; u++) {
        int id = tid + 256 * u;
        int j = id >> 6, d4 = id & 63;
        ys[j][d4] = ((const float4*)(y1 + (size_t)(b * Cc + ch[j]) * Dd))[d0 + d4];
    }
    __syncthreads();

    #pragma unroll
    for (int u = 0; u < 2; u++) {
        int id = tid + 256 * u;
        int i = id >> 6, d4 = id & 63;
        float wi[Gg];
        #pragma unroll
        for (int j = 0; j < Gg; j++) wi[j] = ww[i * Gg + j];
        float4 acc = make_float4(0.f, 0.f, 0.f, 0.f);
        #pragma unroll
        for (int j = 0; j < Gg; j++) {
            float4 yv = ys[j][d4];
            acc.x = fmaf(wi[j], yv.x, acc.x);
            acc.y = fmaf(wi[j], yv.y, acc.y);
            acc.z = fmaf(wi[j], yv.z, acc.z);
            acc.w = fmaf(wi[j], yv.w, acc.w);
        }
        size_t rowoff = (size_t)(b * Cc + ch[i]) * Dd;
        float4 bv = ((const float4*)bg1)[d0 + d4];
        float4 xv = ((const float4*)(x + rowoff))[d0 + d4];
        float z0 = acc.x + bv.x, z1 = acc.y + bv.y, z2 = acc.z + bv.z, z3 = acc.w + bv.w;
        z0 = (z0 >= 0.f) ? z0 : 0.2f * z0;
        z1 = (z1 >= 0.f) ? z1 : 0.2f * z1;
        z2 = (z2 >= 0.f) ? z2 : 0.2f * z2;
        z3 = (z3 >= 0.f) ? z3 : 0.2f * z3;
        float v0 = 0.5f * z0 + 0.5f * xv.x;
        float v1 = 0.5f * z1 + 0.5f * xv.y;
        float v2 = 0.5f * z2 + 0.5f * xv.z;
        float v3 = 0.5f * z3 + 0.5f * xv.w;
        ((uint2*)(x1h + rowoff))[d0 + d4] =
            make_uint2(pack_half2(v0, v1), pack_half2(v2, v3));
    }
}

// ---------------------------------------------------------------------------
// agg2x: out = leaky(adj @ t + bg2)   (t: [Mrows, Oo] fp32) -> out fp32
// ---------------------------------------------------------------------------
__global__ __launch_bounds__(256)
void agg2x_kernel(const float* __restrict__ w, const float* __restrict__ t,
                  const float* __restrict__ bg2, const int* __restrict__ ridx,
                  float* __restrict__ out)
{
    __shared__ float4 ts[Gg][Oo / 4];
    __shared__ float  ww[Gg * Gg];
    __shared__ int    ch[Gg];

    const int tid = threadIdx.x;
    const int blk = blockIdx.x;
    const int b   = blk >> 3;
    const int r   = blk & 7;

    if (tid < Gg) ch[tid] = ridx[r * Gg + tid];
    if (tid >= 64 && tid < 128) ww[tid - 64] = w[(size_t)blk * 64 + (tid - 64)];
    __syncthreads();

    #pragma unroll
    for (int u = 0; u < 2; u++) {
        int id = tid + 256 * u;
        int j = id >> 6, d4 = id & 63;
        ts[j][d4] = ((const float4*)(t + (size_t)(b * Cc + ch[j]) * Oo))[d4];
    }
    __syncthreads();

    #pragma unroll
    for (int u = 0; u < 2; u++) {
        int id = tid + 256 * u;
        int i = id >> 6, d4 = id & 63;
        float wi[Gg];
        #pragma unroll
        for (int j = 0; j < Gg; j++) wi[j] = ww[i * Gg + j];
        float4 acc = make_float4(0.f, 0.f, 0.f, 0.f);
        #pragma unroll
        for (int j = 0; j < Gg; j++) {
            float4 tv = ts[j][d4];
            acc.x = fmaf(wi[j], tv.x, acc.x);
            acc.y = fmaf(wi[j], tv.y, acc.y);
            acc.z = fmaf(wi[j], tv.z, acc.z);
            acc.w = fmaf(wi[j], tv.w, acc.w);
        }
        float4 bv = ((const float4*)bg2)[d4];
        float v0 = acc.x + bv.x, v1 = acc.y + bv.y;
        float v2 = acc.z + bv.z, v3 = acc.w + bv.w;
        v0 = (v0 >= 0.f) ? v0 : 0.2f * v0;
        v1 = (v1 >= 0.f) ? v1 : 0.2f * v1;
        v2 = (v2 >= 0.f) ? v2 : 0.2f * v2;
        v3 = (v3 >= 0.f) ? v3 : 0.2f * v3;
        ((float4*)(out + (size_t)(b * Cc + ch[i]) * Oo))[d4] = make_float4(v0, v1, v2, v3);
    }
}

// ---------------------------------------------------------------------------
extern "C" void kernel_launch(void* const* d_in, const int* in_sizes, int n_in,
                              void* d_out, int out_size)
{
    const float* x    = (const float*)d_in[0];
    const float* W1   = (const float*)d_in[1];
    const float* b1   = (const float*)d_in[2];
    const float* W2   = (const float*)d_in[3];
    const float* b2   = (const float*)d_in[4];
    const float* Wg1  = (const float*)d_in[5];
    const float* bg1  = (const float*)d_in[6];
    const float* Wg2  = (const float*)d_in[7];
    const float* bg2  = (const float*)d_in[8];
    const int*   ridx = (const int*)d_in[9];
    float* out = (float*)d_out;

    float *ga, *gbp, *gy1, *gt, *gw;
    __half *xh, *x1h, *wbth, *wbtl, *wg2th, *wg2tl;
    cudaGetSymbolAddress((void**)&ga,    g_a);
    cudaGetSymbolAddress((void**)&gbp,   g_bp);
    cudaGetSymbolAddress((void**)&gy1,   g_y1);
    cudaGetSymbolAddress((void**)&gt,    g_t);
    cudaGetSymbolAddress((void**)&gw,    g_w);
    cudaGetSymbolAddress((void**)&xh,    g_xh);
    cudaGetSymbolAddress((void**)&x1h,   g_x1h);
    cudaGetSymbolAddress((void**)&wbth,  g_wbt_hi);
    cudaGetSymbolAddress((void**)&wbtl,  g_wbt_lo);
    cudaGetSymbolAddress((void**)&wg2th, g_wg2t_hi);
    cudaGetSymbolAddress((void**)&wg2tl, g_wg2t_lo);

    const int SMEM128 = 3 * (128 * 40 + 2 * 64 * 40) * (int)sizeof(__half);  // 61440
    const int SMEM64  = 3 * ( 64 * 40 + 2 * 64 * 40) * (int)sizeof(__half);  // 46080
    cudaFuncSetAttribute(mgemm_kernel<4,128>, cudaFuncAttributeMaxDynamicSharedMemorySize, SMEM128);
    cudaFuncSetAttribute(mgemm_kernel<0,64>,  cudaFuncAttributeMaxDynamicSharedMemorySize, SMEM64);

    prep_kernel<<<1024, 256>>>(x, W1, Wg1, Wg2, xh, wbth, wbtl, wg2th, wg2tl);

    // G1': [a | bp | y1] = x @ [W1a | W1b | Wg1]  (N=1536)
    {
        dim3 grid(3 * Dd / 64, Mrows / 128);   // 24 x 32 = 768 CTAs
        mgemm_kernel<4,128><<<grid, 256, SMEM128>>>(xh, wbth, wbtl, b1,
                                                    ga, gbp, gy1, 3 * Dd, Dd);
    }
    attn_kernel<<<Bb * NREG, 256>>>(ga, gbp, W2, b2, ridx, gw);
    // x1 = 0.5*leaky(adj@y1 + bg1) + 0.5*x  (fp16)
    {
        dim3 grid(Bb * NREG, 2);
        agg1x_kernel<<<grid, 256>>>(gw, gy1, x, bg1, ridx, x1h);
    }
    // G3': t = x1 @ Wg2
    {
        dim3 grid(Oo / 64, Mrows / 64);        // 4 x 64 = 256 CTAs
        mgemm_kernel<0,64><<<grid, 256, SMEM64>>>(x1h, wg2th, wg2tl, nullptr,
                                                  gt, nullptr, nullptr, Oo, Dd);
    }
    // out = leaky(adj@t + bg2)
    agg2x_kernel<<<Bb * NREG, 256>>>(gw, gt, bg2, ridx, out);
}

// round 10
// speedup vs baseline: 5.8288x; 1.3277x over previous
#include <cuda_runtime.h>
#include <cuda_fp16.h>
#include <math.h>

#define Bb 64
#define Cc 64
#define Dd 512
#define Oo 256
#define NREG 8
#define Gg 8
#define Mrows (Bb*Cc)   // 4096

// ---------------- Scratch (device globals) ----------------
__device__ float g_a [Mrows*Dd];        // x @ W1a
__device__ float g_bp[Mrows*Dd];        // x @ W1b + b1
__device__ float g_y1[Mrows*Dd];        // x @ Wg1
__device__ float g_t [Mrows*Oo];        // x1 @ Wg2
__device__ float g_w [Bb*NREG*Gg*Gg];

__device__ __half g_xh [Mrows*Dd];      // x  (fp16)
__device__ __half g_x1h[Mrows*Dd];      // x1 (fp16)
__device__ __half g_wbt [3*Dd*Dd];      // [W1a^T; W1b^T; Wg1^T]  [n][k] fp16
__device__ __half g_wg2t[Oo*Dd];        // Wg2^T fp16

// ---------------- async / ldmatrix helpers ----------------
__device__ __forceinline__ void cpasync16(void* smem, const void* g)
{
    unsigned sa = (unsigned)__cvta_generic_to_shared(smem);
    asm volatile("cp.async.cg.shared.global [%0], [%1], 16;" :: "r"(sa), "l"(g));
}
__device__ __forceinline__ void cp_commit() { asm volatile("cp.async.commit_group;"); }
template<int N> __device__ __forceinline__ void cp_wait()
{
    asm volatile("cp.async.wait_group %0;" :: "n"(N));
}
__device__ __forceinline__ void ldmx4(unsigned& r0, unsigned& r1, unsigned& r2,
                                      unsigned& r3, const void* p)
{
    unsigned a = (unsigned)__cvta_generic_to_shared(p);
    asm volatile("ldmatrix.sync.aligned.m8n8.x4.shared.b16 {%0,%1,%2,%3}, [%4];"
        : "=r"(r0), "=r"(r1), "=r"(r2), "=r"(r3) : "r"(a));
}
__device__ __forceinline__ void mma_f16(float c[4],
    unsigned a0, unsigned a1, unsigned a2, unsigned a3,
    unsigned b0, unsigned b1)
{
    asm volatile(
        "mma.sync.aligned.m16n8k16.row.col.f32.f16.f16.f32 "
        "{%0,%1,%2,%3}, {%4,%5,%6,%7}, {%8,%9}, {%0,%1,%2,%3};\n"
        : "+f"(c[0]), "+f"(c[1]), "+f"(c[2]), "+f"(c[3])
        : "r"(a0), "r"(a1), "r"(a2), "r"(a3), "r"(b0), "r"(b1));
}
__device__ __forceinline__ unsigned pack_half2(float a, float b)
{
    __half2 h = __halves2half2(__float2half_rn(a), __float2half_rn(b));
    return *(unsigned*)&h;
}

// ---------------- Combined prep kernel ----------------
// Transpose fp32 [K][N] -> fp16 [N][K]
__device__ __forceinline__ void transpose_tile(
    const float* __restrict__ src, __half* __restrict__ dst,
    int K, int N, int tn, int tk)
{
    __shared__ float tile[32][33];
    const int tid = threadIdx.x;
    const int k0 = tk * 32, n0 = tn * 32;
    const int tx = tid & 31, ty = tid >> 5;
    #pragma unroll
    for (int i = 0; i < 4; i++)
        tile[ty + 8 * i][tx] = src[(size_t)(k0 + ty + 8 * i) * N + n0 + tx];
    __syncthreads();
    const int nr = tid >> 4;
    const int kp = tid & 15;
    #pragma unroll
    for (int i = 0; i < 2; i++) {
        int n = n0 + nr + 16 * i;
        float v0 = tile[2 * kp    ][nr + 16 * i];
        float v1 = tile[2 * kp + 1][nr + 16 * i];
        *(unsigned*)&dst[(size_t)n * K + k0 + 2 * kp] = pack_half2(v0, v1);
    }
}

__global__ __launch_bounds__(256)
void prep_kernel(const float* __restrict__ x, const float* __restrict__ W1,
                 const float* __restrict__ Wg1, const float* __restrict__ Wg2,
                 __half* __restrict__ xh,
                 __half* __restrict__ wbt, __half* __restrict__ wg2t)
{
    int b = blockIdx.x;
    if (b < 256) {
        transpose_tile(W1, wbt, Dd, Dd, b & 15, b >> 4);
    } else if (b < 512) {
        b -= 256;
        transpose_tile(W1 + (size_t)Dd * Dd, wbt + (size_t)Dd * Dd, Dd, Dd, b & 15, b >> 4);
    } else if (b < 768) {
        b -= 512;
        transpose_tile(Wg1, wbt + 2 * (size_t)Dd * Dd, Dd, Dd, b & 15, b >> 4);
    } else if (b < 896) {
        b -= 768;
        transpose_tile(Wg2, wg2t, Dd, Oo, b & 7, b >> 3);
    } else {
        b -= 896;   // 128 blocks: x -> fp16
        const float4* src = (const float4*)x;
        uint2* dh = (uint2*)xh;
        const int n4 = Mrows * Dd / 4;
        for (int i = b * 256 + threadIdx.x; i < n4; i += 128 * 256) {
            float4 v = src[i];
            dh[i] = make_uint2(pack_half2(v.x, v.y), pack_half2(v.z, v.w));
        }
    }
}

// ---------------- fp16 single-term tensor-core GEMM ----------------
// BN=64, BK=32, 3-stage cp.async, ldmatrix. Template BM in {128, 64}.
// MODE 0: raw (+bias if non-null)
// MODE 4: triple route: col<512 -> C raw; 512..1023 -> C2 + bias; >=1024 -> C3 raw
template<int MODE, int BM>
__global__ __launch_bounds__(256, 2)
void mgemm_kernel(const __half* __restrict__ A, const __half* __restrict__ Bt,
                  const float* __restrict__ bias,
                  float* __restrict__ C, float* __restrict__ C2,
                  float* __restrict__ C3, int N, int K)
{
    constexpr int BN = 64, BK = 32, LDT = 40, STAGES = 3;
    constexpr int WROWS = BM / 32;
    constexpr int NT = WROWS;
    constexpr int P  = (WROWS / 2) ? WROWS / 2 : 1;
    constexpr int WCOLS = 8 * NT;
    constexpr int A_SZ = BM * LDT;
    constexpr int B_SZ = BN * LDT;
    constexpr int STG  = A_SZ + B_SZ;
    constexpr int ACH  = BM / 64;
    extern __shared__ __half dsm[];

    const int tid  = threadIdx.x;
    const int wid  = tid >> 5;
    const int lane = tid & 31;
    const int wm   = wid % WROWS;
    const int wn   = wid / WROWS;
    const int row0 = blockIdx.y * BM;
    const int col0 = blockIdx.x * BN;
    const int g = lane >> 2;
    const int t = lane & 3;
    const int lq = lane >> 3, li = lane & 7;
    const int fr_off = (lq & 1) * 8 + li;
    const int fk_off = (lq >> 1) * 8;

    float acc[2][NT][4];
    #pragma unroll
    for (int mt = 0; mt < 2; mt++)
        #pragma unroll
        for (int nt = 0; nt < NT; nt++)
            #pragma unroll
            for (int q = 0; q < 4; q++) acc[mt][nt][q] = 0.f;

    auto load_stage = [&](int st, int kt) {
        __half* sA = dsm + st * STG;
        __half* sB = sA + A_SZ;
        #pragma unroll
        for (int i = 0; i < ACH; i++) {
            int id = tid * ACH + i;
            int r = id >> 2, c = (id & 3) * 8;
            cpasync16(sA + r * LDT + c, A + (size_t)(row0 + r) * K + kt + c);
        }
        {
            int r = tid >> 2, c = (tid & 3) * 8;
            cpasync16(sB + r * LDT + c, Bt + (size_t)(col0 + r) * K + kt + c);
        }
    };

    const int nk = K / BK;
    load_stage(0, 0); cp_commit();
    load_stage(1, BK); cp_commit();

    for (int s = 0; s < nk; s++) {
        if (s + 2 < nk) { load_stage((s + 2) % STAGES, (s + 2) * BK); cp_commit(); cp_wait<2>(); }
        else if (s + 1 < nk) { cp_wait<1>(); }
        else { cp_wait<0>(); }
        __syncthreads();

        const int st = s % STAGES;
        __half* sA = dsm + st * STG;
        __half* sB = sA + A_SZ;

        #pragma unroll
        for (int kk = 0; kk < BK; kk += 16) {
            unsigned ah[2][4], bv[P][4];
            #pragma unroll
            for (int mt = 0; mt < 2; mt++) {
                const __half* pa = sA + (wm * 32 + mt * 16 + fr_off) * LDT + kk + fk_off;
                ldmx4(ah[mt][0], ah[mt][1], ah[mt][2], ah[mt][3], pa);
            }
            #pragma unroll
            for (int p = 0; p < P; p++) {
                const __half* pb = sB + (wn * WCOLS + p * 16 + fr_off) * LDT + kk + fk_off;
                ldmx4(bv[p][0], bv[p][1], bv[p][2], bv[p][3], pb);
            }
            #pragma unroll
            for (int mt = 0; mt < 2; mt++)
                #pragma unroll
                for (int nt = 0; nt < NT; nt++) {
                    const int p = nt >> 1, o = nt & 1;
                    mma_f16(acc[mt][nt], ah[mt][0], ah[mt][1], ah[mt][2], ah[mt][3],
                            bv[p][o], bv[p][2 + o]);
                }
        }
        __syncthreads();
    }

    #pragma unroll
    for (int mt = 0; mt < 2; mt++) {
        int rbase = row0 + wm * 32 + mt * 16;
        #pragma unroll
        for (int nt = 0; nt < NT; nt++) {
            int cb = col0 + wn * WCOLS + nt * 8 + 2 * t;
            #pragma unroll
            for (int h = 0; h < 2; h++) {
                int r = rbase + g + 8 * h;
                float v0 = acc[mt][nt][2*h];
                float v1 = acc[mt][nt][2*h + 1];
                if (MODE == 4) {
                    if (cb < Dd) {
                        *(float2*)(C + (size_t)r * Dd + cb) = make_float2(v0, v1);
                    } else if (cb < 2 * Dd) {
                        int c2 = cb - Dd;
                        v0 += bias[c2]; v1 += bias[c2 + 1];
                        *(float2*)(C2 + (size_t)r * Dd + c2) = make_float2(v0, v1);
                    } else {
                        int c3 = cb - 2 * Dd;
                        *(float2*)(C3 + (size_t)r * Dd + c3) = make_float2(v0, v1);
                    }
                } else {
                    if (bias) { v0 += bias[cb]; v1 += bias[cb + 1]; }
                    *(float2*)(C + (size_t)r * N + cb) = make_float2(v0, v1);
                }
            }
        }
    }
}

// ---------------------------------------------------------------------------
// Attention: vectorized float4 tile loads
// ---------------------------------------------------------------------------
__global__ __launch_bounds__(256)
void attn_kernel(const float* __restrict__ a, const float* __restrict__ bp,
                 const float* __restrict__ W2, const float* __restrict__ b2,
                 const int* __restrict__ ridx, float* __restrict__ wout)
{
    __shared__ float sa[Gg][Dd];
    __shared__ float sb[Gg][Dd];
    __shared__ float sw2[Dd];
    __shared__ float ssc[Gg][Gg];
    __shared__ int   ch[Gg];

    const int tid  = threadIdx.x;
    const int blk  = blockIdx.x;
    const int b    = blk >> 3;
    const int r    = blk & 7;

    if (tid < Gg) ch[tid] = ridx[r * Gg + tid];
    __syncthreads();

    {
        // 8 rows x 128 float4 for a and bp: 4 f4 per thread each
        #pragma unroll
        for (int u = 0; u < 4; u++) {
            int id = tid + 256 * u;
            int j = id >> 7, d4 = id & 127;
            size_t roff = (size_t)(b * Cc + ch[j]) * Dd;
            ((float4*)sa[j])[d4] = ((const float4*)(a  + roff))[d4];
            ((float4*)sb[j])[d4] = ((const float4*)(bp + roff))[d4];
        }
        if (tid < 128) ((float4*)sw2)[tid] = ((const float4*)W2)[tid];
    }
    __syncthreads();

    const int wid  = tid >> 5;
    const int lane = tid & 31;
    float accq[Gg];
    #pragma unroll
    for (int q = 0; q < Gg; q++) accq[q] = 0.f;
    for (int t = lane; t < Dd; t += 32) {
        float av = sa[wid][t];
        float wv = sw2[t];
        #pragma unroll
        for (int q = 0; q < Gg; q++) {
            float v = av + sb[q][t];
            v = fmaxf(v, 0.f);
            accq[q] = fmaf(v, wv, accq[q]);
        }
    }
    #pragma unroll
    for (int q = 0; q < Gg; q++) {
        #pragma unroll
        for (int off = 16; off > 0; off >>= 1)
            accq[q] += __shfl_xor_sync(0xffffffffu, accq[q], off);
    }
    if (lane == 0) {
        float bb2 = b2[0];
        #pragma unroll
        for (int q = 0; q < Gg; q++) ssc[wid][q] = accq[q] + bb2;
    }
    __syncthreads();

    if (tid < Gg) {
        int i = tid;
        float mx = -1e30f;
        #pragma unroll
        for (int j = 0; j < Gg; j++)
            if (j != i) mx = fmaxf(mx, ssc[i][j]);
        float e[Gg]; float s = 0.f;
        #pragma unroll
        for (int j = 0; j < Gg; j++) {
            e[j] = (j == i) ? 0.f : __expf(ssc[i][j] - mx);
            s += e[j];
        }
        float inv = 1.f / s;
        float* wrow = wout + ((size_t)blk * Gg + i) * Gg;
        #pragma unroll
        for (int j = 0; j < Gg; j++) wrow[j] = e[j] * inv;
    }
}

// ---------------------------------------------------------------------------
// agg1x: x1 = 0.5*leaky(adj @ y1 + bg1) + 0.5*x  -> single fp16
// grid (512, 2): D split in halves
// ---------------------------------------------------------------------------
__global__ __launch_bounds__(256)
void agg1x_kernel(const float* __restrict__ w, const float* __restrict__ y1,
                  const float* __restrict__ x, const float* __restrict__ bg1,
                  const int* __restrict__ ridx, __half* __restrict__ x1h)
{
    __shared__ float4 ys[Gg][64];
    __shared__ float  ww[Gg * Gg];
    __shared__ int    ch[Gg];

    const int tid = threadIdx.x;
    const int blk = blockIdx.x;
    const int b   = blk >> 3;
    const int r   = blk & 7;
    const int d0  = blockIdx.y * 64;

    if (tid < Gg) ch[tid] = ridx[r * Gg + tid];
    if (tid >= 64 && tid < 128) ww[tid - 64] = w[(size_t)blk * 64 + (tid - 64)];
    __syncthreads();

    #pragma unroll
    for (int u = 0; u < 2; u++) {
        int id = tid + 256 * u;
        int j = id >> 6, d4 = id & 63;
        ys[j][d4] = ((const float4*)(y1 + (size_t)(b * Cc + ch[j]) * Dd))[d0 + d4];
    }
    __syncthreads();

    #pragma unroll
    for (int u = 0; u < 2; u++) {
        int id = tid + 256 * u;
        int i = id >> 6, d4 = id & 63;
        float wi[Gg];
        #pragma unroll
        for (int j = 0; j < Gg; j++) wi[j] = ww[i * Gg + j];
        float4 acc = make_float4(0.f, 0.f, 0.f, 0.f);
        #pragma unroll
        for (int j = 0; j < Gg; j++) {
            float4 yv = ys[j][d4];
            acc.x = fmaf(wi[j], yv.x, acc.x);
            acc.y = fmaf(wi[j], yv.y, acc.y);
            acc.z = fmaf(wi[j], yv.z, acc.z);
            acc.w = fmaf(wi[j], yv.w, acc.w);
        }
        size_t rowoff = (size_t)(b * Cc + ch[i]) * Dd;
        float4 bv = ((const float4*)bg1)[d0 + d4];
        float4 xv = ((const float4*)(x + rowoff))[d0 + d4];
        float z0 = acc.x + bv.x, z1 = acc.y + bv.y, z2 = acc.z + bv.z, z3 = acc.w + bv.w;
        z0 = (z0 >= 0.f) ? z0 : 0.2f * z0;
        z1 = (z1 >= 0.f) ? z1 : 0.2f * z1;
        z2 = (z2 >= 0.f) ? z2 : 0.2f * z2;
        z3 = (z3 >= 0.f) ? z3 : 0.2f * z3;
        float v0 = 0.5f * z0 + 0.5f * xv.x;
        float v1 = 0.5f * z1 + 0.5f * xv.y;
        float v2 = 0.5f * z2 + 0.5f * xv.z;
        float v3 = 0.5f * z3 + 0.5f * xv.w;
        ((uint2*)(x1h + rowoff))[d0 + d4] =
            make_uint2(pack_half2(v0, v1), pack_half2(v2, v3));
    }
}

// ---------------------------------------------------------------------------
// agg2x: out = leaky(adj @ t + bg2)
// ---------------------------------------------------------------------------
__global__ __launch_bounds__(256)
void agg2x_kernel(const float* __restrict__ w, const float* __restrict__ t,
                  const float* __restrict__ bg2, const int* __restrict__ ridx,
                  float* __restrict__ out)
{
    __shared__ float4 ts[Gg][Oo / 4];
    __shared__ float  ww[Gg * Gg];
    __shared__ int    ch[Gg];

    const int tid = threadIdx.x;
    const int blk = blockIdx.x;
    const int b   = blk >> 3;
    const int r   = blk & 7;

    if (tid < Gg) ch[tid] = ridx[r * Gg + tid];
    if (tid >= 64 && tid < 128) ww[tid - 64] = w[(size_t)blk * 64 + (tid - 64)];
    __syncthreads();

    #pragma unroll
    for (int u = 0; u < 2; u++) {
        int id = tid + 256 * u;
        int j = id >> 6, d4 = id & 63;
        ts[j][d4] = ((const float4*)(t + (size_t)(b * Cc + ch[j]) * Oo))[d4];
    }
    __syncthreads();

    #pragma unroll
    for (int u = 0; u < 2; u++) {
        int id = tid + 256 * u;
        int i = id >> 6, d4 = id & 63;
        float wi[Gg];
        #pragma unroll
        for (int j = 0; j < Gg; j++) wi[j] = ww[i * Gg + j];
        float4 acc = make_float4(0.f, 0.f, 0.f, 0.f);
        #pragma unroll
        for (int j = 0; j < Gg; j++) {
            float4 tv = ts[j][d4];
            acc.x = fmaf(wi[j], tv.x, acc.x);
            acc.y = fmaf(wi[j], tv.y, acc.y);
            acc.z = fmaf(wi[j], tv.z, acc.z);
            acc.w = fmaf(wi[j], tv.w, acc.w);
        }
        float4 bv = ((const float4*)bg2)[d4];
        float v0 = acc.x + bv.x, v1 = acc.y + bv.y;
        float v2 = acc.z + bv.z, v3 = acc.w + bv.w;
        v0 = (v0 >= 0.f) ? v0 : 0.2f * v0;
        v1 = (v1 >= 0.f) ? v1 : 0.2f * v1;
        v2 = (v2 >= 0.f) ? v2 : 0.2f * v2;
        v3 = (v3 >= 0.f) ? v3 : 0.2f * v3;
        ((float4*)(out + (size_t)(b * Cc + ch[i]) * Oo))[d4] = make_float4(v0, v1, v2, v3);
    }
}

// ---------------------------------------------------------------------------
extern "C" void kernel_launch(void* const* d_in, const int* in_sizes, int n_in,
                              void* d_out, int out_size)
{
    const float* x    = (const float*)d_in[0];
    const float* W1   = (const float*)d_in[1];
    const float* b1   = (const float*)d_in[2];
    const float* W2   = (const float*)d_in[3];
    const float* b2   = (const float*)d_in[4];
    const float* Wg1  = (const float*)d_in[5];
    const float* bg1  = (const float*)d_in[6];
    const float* Wg2  = (const float*)d_in[7];
    const float* bg2  = (const float*)d_in[8];
    const int*   ridx = (const int*)d_in[9];
    float* out = (float*)d_out;

    float *ga, *gbp, *gy1, *gt, *gw;
    __half *xh, *x1h, *wbt, *wg2t;
    cudaGetSymbolAddress((void**)&ga,   g_a);
    cudaGetSymbolAddress((void**)&gbp,  g_bp);
    cudaGetSymbolAddress((void**)&gy1,  g_y1);
    cudaGetSymbolAddress((void**)&gt,   g_t);
    cudaGetSymbolAddress((void**)&gw,   g_w);
    cudaGetSymbolAddress((void**)&xh,   g_xh);
    cudaGetSymbolAddress((void**)&x1h,  g_x1h);
    cudaGetSymbolAddress((void**)&wbt,  g_wbt);
    cudaGetSymbolAddress((void**)&wg2t, g_wg2t);

    const int SMEM128 = 3 * (128 * 40 + 64 * 40) * (int)sizeof(__half);  // 46080
    const int SMEM64  = 3 * ( 64 * 40 + 64 * 40) * (int)sizeof(__half);  // 30720
    cudaFuncSetAttribute(mgemm_kernel<4,128>, cudaFuncAttributeMaxDynamicSharedMemorySize, SMEM128);
    cudaFuncSetAttribute(mgemm_kernel<0,64>,  cudaFuncAttributeMaxDynamicSharedMemorySize, SMEM64);

    prep_kernel<<<1024, 256>>>(x, W1, Wg1, Wg2, xh, wbt, wg2t);

    // G1': [a | bp | y1] = x @ [W1a | W1b | Wg1]  (N=1536)
    {
        dim3 grid(3 * Dd / 64, Mrows / 128);   // 24 x 32 = 768 CTAs
        mgemm_kernel<4,128><<<grid, 256, SMEM128>>>(xh, wbt, b1,
                                                    ga, gbp, gy1, 3 * Dd, Dd);
    }
    attn_kernel<<<Bb * NREG, 256>>>(ga, gbp, W2, b2, ridx, gw);
    // x1 = 0.5*leaky(adj@y1 + bg1) + 0.5*x  (fp16)
    {
        dim3 grid(Bb * NREG, 2);
        agg1x_kernel<<<grid, 256>>>(gw, gy1, x, bg1, ridx, x1h);
    }
    // G3': t = x1 @ Wg2
    {
        dim3 grid(Oo / 64, Mrows / 64);        // 4 x 64 = 256 CTAs
        mgemm_kernel<0,64><<<grid, 256, SMEM64>>>(x1h, wg2t, nullptr,
                                                  gt, nullptr, nullptr, Oo, Dd);
    }
    // out = leaky(adj@t + bg2)
    agg2x_kernel<<<Bb * NREG, 256>>>(gw, gt, bg2, ridx, out);
}

// round 11
// speedup vs baseline: 6.0042x; 1.0301x over previous
#include <cuda_runtime.h>
#include <cuda_fp16.h>
#include <math.h>

#define Bb 64
#define Cc 64
#define Dd 512
#define Oo 256
#define NREG 8
#define Gg 8
#define Mrows (Bb*Cc)   // 4096

// ---------------- Scratch (device globals) ----------------
__device__ float  g_t [Mrows*Oo];       // x1 @ Wg2 (fp32)
__device__ __half g_ah [Mrows*Dd];      // x @ W1a (fp16)
__device__ __half g_bph[Mrows*Dd];      // x @ W1b + b1 (fp16)
__device__ __half g_y1h[Mrows*Dd];      // x @ Wg1 (fp16)
__device__ __half g_xh [Mrows*Dd];      // x  (fp16)
__device__ __half g_x1h[Mrows*Dd];      // x1 (fp16)
__device__ __half g_wbt [3*Dd*Dd];      // [W1a^T; W1b^T; Wg1^T]  [n][k] fp16
__device__ __half g_wg2t[Oo*Dd];        // Wg2^T fp16

// ---------------- async / ldmatrix helpers ----------------
__device__ __forceinline__ void cpasync16(void* smem, const void* g)
{
    unsigned sa = (unsigned)__cvta_generic_to_shared(smem);
    asm volatile("cp.async.cg.shared.global [%0], [%1], 16;" :: "r"(sa), "l"(g));
}
__device__ __forceinline__ void cp_commit() { asm volatile("cp.async.commit_group;"); }
template<int N> __device__ __forceinline__ void cp_wait()
{
    asm volatile("cp.async.wait_group %0;" :: "n"(N));
}
__device__ __forceinline__ void ldmx4(unsigned& r0, unsigned& r1, unsigned& r2,
                                      unsigned& r3, const void* p)
{
    unsigned a = (unsigned)__cvta_generic_to_shared(p);
    asm volatile("ldmatrix.sync.aligned.m8n8.x4.shared.b16 {%0,%1,%2,%3}, [%4];"
        : "=r"(r0), "=r"(r1), "=r"(r2), "=r"(r3) : "r"(a));
}
__device__ __forceinline__ void mma_f16(float c[4],
    unsigned a0, unsigned a1, unsigned a2, unsigned a3,
    unsigned b0, unsigned b1)
{
    asm volatile(
        "mma.sync.aligned.m16n8k16.row.col.f32.f16.f16.f32 "
        "{%0,%1,%2,%3}, {%4,%5,%6,%7}, {%8,%9}, {%0,%1,%2,%3};\n"
        : "+f"(c[0]), "+f"(c[1]), "+f"(c[2]), "+f"(c[3])
        : "r"(a0), "r"(a1), "r"(a2), "r"(a3), "r"(b0), "r"(b1));
}
__device__ __forceinline__ unsigned pack_half2(float a, float b)
{
    __half2 h = __halves2half2(__float2half_rn(a), __float2half_rn(b));
    return *(unsigned*)&h;
}

// ---------------- Combined prep kernel ----------------
__device__ __forceinline__ void transpose_tile(
    const float* __restrict__ src, __half* __restrict__ dst,
    int K, int N, int tn, int tk)
{
    __shared__ float tile[32][33];
    const int tid = threadIdx.x;
    const int k0 = tk * 32, n0 = tn * 32;
    const int tx = tid & 31, ty = tid >> 5;
    #pragma unroll
    for (int i = 0; i < 4; i++)
        tile[ty + 8 * i][tx] = src[(size_t)(k0 + ty + 8 * i) * N + n0 + tx];
    __syncthreads();
    const int nr = tid >> 4;
    const int kp = tid & 15;
    #pragma unroll
    for (int i = 0; i < 2; i++) {
        int n = n0 + nr + 16 * i;
        float v0 = tile[2 * kp    ][nr + 16 * i];
        float v1 = tile[2 * kp + 1][nr + 16 * i];
        *(unsigned*)&dst[(size_t)n * K + k0 + 2 * kp] = pack_half2(v0, v1);
    }
}

__global__ __launch_bounds__(256)
void prep_kernel(const float* __restrict__ x, const float* __restrict__ W1,
                 const float* __restrict__ Wg1, const float* __restrict__ Wg2,
                 __half* __restrict__ xh,
                 __half* __restrict__ wbt, __half* __restrict__ wg2t)
{
    int b = blockIdx.x;
    if (b < 256) {
        transpose_tile(W1, wbt, Dd, Dd, b & 15, b >> 4);
    } else if (b < 512) {
        b -= 256;
        transpose_tile(W1 + (size_t)Dd * Dd, wbt + (size_t)Dd * Dd, Dd, Dd, b & 15, b >> 4);
    } else if (b < 768) {
        b -= 512;
        transpose_tile(Wg1, wbt + 2 * (size_t)Dd * Dd, Dd, Dd, b & 15, b >> 4);
    } else if (b < 896) {
        b -= 768;
        transpose_tile(Wg2, wg2t, Dd, Oo, b & 7, b >> 3);
    } else {
        b -= 896;
        const float4* src = (const float4*)x;
        uint2* dh = (uint2*)xh;
        const int n4 = Mrows * Dd / 4;
        for (int i = b * 256 + threadIdx.x; i < n4; i += 128 * 256) {
            float4 v = src[i];
            dh[i] = make_uint2(pack_half2(v.x, v.y), pack_half2(v.z, v.w));
        }
    }
}

// ---------------- fp16 tensor-core GEMM ----------------
// MODE 0: fp32 out (+bias if non-null)
// MODE 5: triple fp16 route: col<512 -> Ch raw; 512..1023 -> C2h + bias; >=1024 -> C3h raw
template<int MODE, int BM>
__global__ __launch_bounds__(256, 2)
void mgemm_kernel(const __half* __restrict__ A, const __half* __restrict__ Bt,
                  const float* __restrict__ bias,
                  float* __restrict__ C,
                  __half* __restrict__ Ch, __half* __restrict__ C2h,
                  __half* __restrict__ C3h, int N, int K)
{
    constexpr int BN = 64, BK = 32, LDT = 40, STAGES = 3;
    constexpr int WROWS = BM / 32;
    constexpr int NT = WROWS;
    constexpr int P  = (WROWS / 2) ? WROWS / 2 : 1;
    constexpr int WCOLS = 8 * NT;
    constexpr int A_SZ = BM * LDT;
    constexpr int B_SZ = BN * LDT;
    constexpr int STG  = A_SZ + B_SZ;
    constexpr int ACH  = BM / 64;
    extern __shared__ __half dsm[];

    const int tid  = threadIdx.x;
    const int wid  = tid >> 5;
    const int lane = tid & 31;
    const int wm   = wid % WROWS;
    const int wn   = wid / WROWS;
    const int row0 = blockIdx.y * BM;
    const int col0 = blockIdx.x * BN;
    const int g = lane >> 2;
    const int t = lane & 3;
    const int lq = lane >> 3, li = lane & 7;
    const int fr_off = (lq & 1) * 8 + li;
    const int fk_off = (lq >> 1) * 8;

    float acc[2][NT][4];
    #pragma unroll
    for (int mt = 0; mt < 2; mt++)
        #pragma unroll
        for (int nt = 0; nt < NT; nt++)
            #pragma unroll
            for (int q = 0; q < 4; q++) acc[mt][nt][q] = 0.f;

    auto load_stage = [&](int st, int kt) {
        __half* sA = dsm + st * STG;
        __half* sB = sA + A_SZ;
        #pragma unroll
        for (int i = 0; i < ACH; i++) {
            int id = tid * ACH + i;
            int r = id >> 2, c = (id & 3) * 8;
            cpasync16(sA + r * LDT + c, A + (size_t)(row0 + r) * K + kt + c);
        }
        {
            int r = tid >> 2, c = (tid & 3) * 8;
            cpasync16(sB + r * LDT + c, Bt + (size_t)(col0 + r) * K + kt + c);
        }
    };

    const int nk = K / BK;
    load_stage(0, 0); cp_commit();
    load_stage(1, BK); cp_commit();

    for (int s = 0; s < nk; s++) {
        if (s + 2 < nk) { load_stage((s + 2) % STAGES, (s + 2) * BK); cp_commit(); cp_wait<2>(); }
        else if (s + 1 < nk) { cp_wait<1>(); }
        else { cp_wait<0>(); }
        __syncthreads();

        const int st = s % STAGES;
        __half* sA = dsm + st * STG;
        __half* sB = sA + A_SZ;

        #pragma unroll
        for (int kk = 0; kk < BK; kk += 16) {
            unsigned ah[2][4], bv[P][4];
            #pragma unroll
            for (int mt = 0; mt < 2; mt++) {
                const __half* pa = sA + (wm * 32 + mt * 16 + fr_off) * LDT + kk + fk_off;
                ldmx4(ah[mt][0], ah[mt][1], ah[mt][2], ah[mt][3], pa);
            }
            #pragma unroll
            for (int p = 0; p < P; p++) {
                const __half* pb = sB + (wn * WCOLS + p * 16 + fr_off) * LDT + kk + fk_off;
                ldmx4(bv[p][0], bv[p][1], bv[p][2], bv[p][3], pb);
            }
            #pragma unroll
            for (int mt = 0; mt < 2; mt++)
                #pragma unroll
                for (int nt = 0; nt < NT; nt++) {
                    const int p = nt >> 1, o = nt & 1;
                    mma_f16(acc[mt][nt], ah[mt][0], ah[mt][1], ah[mt][2], ah[mt][3],
                            bv[p][o], bv[p][2 + o]);
                }
        }
        __syncthreads();
    }

    #pragma unroll
    for (int mt = 0; mt < 2; mt++) {
        int rbase = row0 + wm * 32 + mt * 16;
        #pragma unroll
        for (int nt = 0; nt < NT; nt++) {
            int cb = col0 + wn * WCOLS + nt * 8 + 2 * t;
            #pragma unroll
            for (int h = 0; h < 2; h++) {
                int r = rbase + g + 8 * h;
                float v0 = acc[mt][nt][2*h];
                float v1 = acc[mt][nt][2*h + 1];
                if (MODE == 5) {
                    if (cb < Dd) {
                        *(unsigned*)&Ch[(size_t)r * Dd + cb] = pack_half2(v0, v1);
                    } else if (cb < 2 * Dd) {
                        int c2 = cb - Dd;
                        v0 += bias[c2]; v1 += bias[c2 + 1];
                        *(unsigned*)&C2h[(size_t)r * Dd + c2] = pack_half2(v0, v1);
                    } else {
                        int c3 = cb - 2 * Dd;
                        *(unsigned*)&C3h[(size_t)r * Dd + c3] = pack_half2(v0, v1);
                    }
                } else {
                    if (bias) { v0 += bias[cb]; v1 += bias[cb + 1]; }
                    *(float2*)(C + (size_t)r * N + cb) = make_float2(v0, v1);
                }
            }
        }
    }
}

// ---------------------------------------------------------------------------
// Fused attention + agg1: per (b, r) block.
// Phase 1: scores from fp16 a/bp, softmax -> ww (shared, never hits DRAM).
// Phase 2: x1 = 0.5*leaky(adj @ y1 + bg1) + 0.5*x  -> fp16
// ---------------------------------------------------------------------------
__global__ __launch_bounds__(256)
void attnagg_kernel(const __half* __restrict__ ah, const __half* __restrict__ bph,
                    const float* __restrict__ W2, const float* __restrict__ b2,
                    const __half* __restrict__ y1h, const __half* __restrict__ xh,
                    const float* __restrict__ bg1, const int* __restrict__ ridx,
                    __half* __restrict__ x1h)
{
    __shared__ float sa[Gg][Dd];     // 16 KB
    __shared__ float sb[Gg][Dd];     // 16 KB
    __shared__ float sw2[Dd];        // 2 KB
    __shared__ float ssc[Gg][Gg];
    __shared__ float ww[Gg * Gg];
    __shared__ int   ch[Gg];

    const int tid  = threadIdx.x;
    const int blk  = blockIdx.x;
    const int b    = blk >> 3;
    const int r    = blk & 7;

    if (tid < Gg) ch[tid] = ridx[r * Gg + tid];
    __syncthreads();

    // Load fp16 a/bp rows, convert to fp32 shared. 8 rows x 64 uint4 (8 halves)
    // = 512 chunks per tensor; 2 chunks/thread.
    #pragma unroll
    for (int u = 0; u < 2; u++) {
        int id = tid + 256 * u;          // 0..511
        int j = id >> 6, c8 = id & 63;   // row, 8-half chunk
        size_t roff = (size_t)(b * Cc + ch[j]) * Dd;
        uint4 va = ((const uint4*)(ah  + roff))[c8];
        uint4 vb = ((const uint4*)(bph + roff))[c8];
        const unsigned* pa = &va.x;
        const unsigned* pb = &vb.x;
        #pragma unroll
        for (int q = 0; q < 4; q++) {
            __half2 ha = *(__half2*)&pa[q];
            __half2 hb = *(__half2*)&pb[q];
            float2 fa = __half22float2(ha);
            float2 fb = __half22float2(hb);
            sa[j][c8 * 8 + 2 * q]     = fa.x;
            sa[j][c8 * 8 + 2 * q + 1] = fa.y;
            sb[j][c8 * 8 + 2 * q]     = fb.x;
            sb[j][c8 * 8 + 2 * q + 1] = fb.y;
        }
    }
    if (tid < 128) ((float4*)sw2)[tid] = ((const float4*)W2)[tid];
    __syncthreads();

    // Scores: warp i computes row i vs all 8 columns
    const int wid  = tid >> 5;
    const int lane = tid & 31;
    {
        float accq[Gg];
        #pragma unroll
        for (int q = 0; q < Gg; q++) accq[q] = 0.f;
        for (int t = lane; t < Dd; t += 32) {
            float av = sa[wid][t];
            float wv = sw2[t];
            #pragma unroll
            for (int q = 0; q < Gg; q++) {
                float v = av + sb[q][t];
                v = fmaxf(v, 0.f);
                accq[q] = fmaf(v, wv, accq[q]);
            }
        }
        #pragma unroll
        for (int q = 0; q < Gg; q++) {
            #pragma unroll
            for (int off = 16; off > 0; off >>= 1)
                accq[q] += __shfl_xor_sync(0xffffffffu, accq[q], off);
        }
        if (lane == 0) {
            float bb2 = b2[0];
            #pragma unroll
            for (int q = 0; q < Gg; q++) ssc[wid][q] = accq[q] + bb2;
        }
    }
    __syncthreads();

    // Softmax per row (exclude diagonal) -> ww
    if (tid < Gg) {
        int i = tid;
        float mx = -1e30f;
        #pragma unroll
        for (int j = 0; j < Gg; j++)
            if (j != i) mx = fmaxf(mx, ssc[i][j]);
        float e[Gg]; float s = 0.f;
        #pragma unroll
        for (int j = 0; j < Gg; j++) {
            e[j] = (j == i) ? 0.f : __expf(ssc[i][j] - mx);
            s += e[j];
        }
        float inv = 1.f / s;
        #pragma unroll
        for (int j = 0; j < Gg; j++) ww[i * Gg + j] = e[j] * inv;
    }

    // Phase 2: reuse sa as y1 staging (fp32)
    __syncthreads();
    #pragma unroll
    for (int u = 0; u < 2; u++) {
        int id = tid + 256 * u;
        int j = id >> 6, c8 = id & 63;
        size_t roff = (size_t)(b * Cc + ch[j]) * Dd;
        uint4 vy = ((const uint4*)(y1h + roff))[c8];
        const unsigned* py = &vy.x;
        #pragma unroll
        for (int q = 0; q < 4; q++) {
            float2 fy = __half22float2(*(__half2*)&py[q]);
            sa[j][c8 * 8 + 2 * q]     = fy.x;
            sa[j][c8 * 8 + 2 * q + 1] = fy.y;
        }
    }
    __syncthreads();

    // x1 rows: 8 x 512 = 4096 elems; 4 elems/thread x 4 iters
    #pragma unroll
    for (int u = 0; u < 4; u++) {
        int id = tid + 256 * u;          // 0..1023
        int i = id >> 7, d4 = id & 127;  // row, float4-group
        float wi[Gg];
        #pragma unroll
        for (int j = 0; j < Gg; j++) wi[j] = ww[i * Gg + j];
        float a0 = 0.f, a1 = 0.f, a2 = 0.f, a3 = 0.f;
        #pragma unroll
        for (int j = 0; j < Gg; j++) {
            const float* yr = &sa[j][d4 * 4];
            a0 = fmaf(wi[j], yr[0], a0);
            a1 = fmaf(wi[j], yr[1], a1);
            a2 = fmaf(wi[j], yr[2], a2);
            a3 = fmaf(wi[j], yr[3], a3);
        }
        size_t rowoff = (size_t)(b * Cc + ch[i]) * Dd;
        float4 bv = ((const float4*)bg1)[d4];
        uint2 xv = ((const uint2*)(xh + rowoff))[d4];
        float2 x01 = __half22float2(*(__half2*)&xv.x);
        float2 x23 = __half22float2(*(__half2*)&xv.y);
        float z0 = a0 + bv.x, z1 = a1 + bv.y, z2 = a2 + bv.z, z3 = a3 + bv.w;
        z0 = (z0 >= 0.f) ? z0 : 0.2f * z0;
        z1 = (z1 >= 0.f) ? z1 : 0.2f * z1;
        z2 = (z2 >= 0.f) ? z2 : 0.2f * z2;
        z3 = (z3 >= 0.f) ? z3 : 0.2f * z3;
        float v0 = 0.5f * z0 + 0.5f * x01.x;
        float v1 = 0.5f * z1 + 0.5f * x01.y;
        float v2 = 0.5f * z2 + 0.5f * x23.x;
        float v3 = 0.5f * z3 + 0.5f * x23.y;
        ((uint2*)(x1h + rowoff))[d4] = make_uint2(pack_half2(v0, v1), pack_half2(v2, v3));
    }

    // Export adj weights for agg2x (tiny)
    if (tid < 64)
        ((float*)ssc)[tid] = 0.f;  // (unused; keep ssc alive)
}

// ---------------------------------------------------------------------------
// agg2x needs adj — recompute path avoided by storing ww to global from fused
// kernel would add traffic; instead agg2x gets w from a second tiny output.
// Simpler: fused kernel ALSO writes ww to g_w (2 KB total traffic — negligible).
// ---------------------------------------------------------------------------
__device__ float g_w[Bb * NREG * Gg * Gg];

__global__ __launch_bounds__(256)
void agg2x_kernel(const float* __restrict__ w, const float* __restrict__ t,
                  const float* __restrict__ bg2, const int* __restrict__ ridx,
                  float* __restrict__ out)
{
    __shared__ float4 ts[Gg][Oo / 4];
    __shared__ float  ww[Gg * Gg];
    __shared__ int    ch[Gg];

    const int tid = threadIdx.x;
    const int blk = blockIdx.x;
    const int b   = blk >> 3;
    const int r   = blk & 7;

    if (tid < Gg) ch[tid] = ridx[r * Gg + tid];
    if (tid >= 64 && tid < 128) ww[tid - 64] = w[(size_t)blk * 64 + (tid - 64)];
    __syncthreads();

    #pragma unroll
    for (int u = 0; u < 2; u++) {
        int id = tid + 256 * u;
        int j = id >> 6, d4 = id & 63;
        ts[j][d4] = ((const float4*)(t + (size_t)(b * Cc + ch[j]) * Oo))[d4];
    }
    __syncthreads();

    #pragma unroll
    for (int u = 0; u < 2; u++) {
        int id = tid + 256 * u;
        int i = id >> 6, d4 = id & 63;
        float wi[Gg];
        #pragma unroll
        for (int j = 0; j < Gg; j++) wi[j] = ww[i * Gg + j];
        float4 acc = make_float4(0.f, 0.f, 0.f, 0.f);
        #pragma unroll
        for (int j = 0; j < Gg; j++) {
            float4 tv = ts[j][d4];
            acc.x = fmaf(wi[j], tv.x, acc.x);
            acc.y = fmaf(wi[j], tv.y, acc.y);
            acc.z = fmaf(wi[j], tv.z, acc.z);
            acc.w = fmaf(wi[j], tv.w, acc.w);
        }
        float4 bv = ((const float4*)bg2)[d4];
        float v0 = acc.x + bv.x, v1 = acc.y + bv.y;
        float v2 = acc.z + bv.z, v3 = acc.w + bv.w;
        v0 = (v0 >= 0.f) ? v0 : 0.2f * v0;
        v1 = (v1 >= 0.f) ? v1 : 0.2f * v1;
        v2 = (v2 >= 0.f) ? v2 : 0.2f * v2;
        v3 = (v3 >= 0.f) ? v3 : 0.2f * v3;
        ((float4*)(out + (size_t)(b * Cc + ch[i]) * Oo))[d4] = make_float4(v0, v1, v2, v3);
    }
}

// Variant of attnagg that also exports ww to global for agg2x.
__global__ __launch_bounds__(256)
void attnagg_export_kernel(const __half* __restrict__ ah, const __half* __restrict__ bph,
                           const float* __restrict__ W2, const float* __restrict__ b2,
                           const __half* __restrict__ y1h, const __half* __restrict__ xh,
                           const float* __restrict__ bg1, const int* __restrict__ ridx,
                           __half* __restrict__ x1h, float* __restrict__ wout)
{
    __shared__ float sa[Gg][Dd];
    __shared__ float sb[Gg][Dd];
    __shared__ float sw2[Dd];
    __shared__ float ssc[Gg][Gg];
    __shared__ float ww[Gg * Gg];
    __shared__ int   ch[Gg];

    const int tid  = threadIdx.x;
    const int blk  = blockIdx.x;
    const int b    = blk >> 3;
    const int r    = blk & 7;

    if (tid < Gg) ch[tid] = ridx[r * Gg + tid];
    __syncthreads();

    #pragma unroll
    for (int u = 0; u < 2; u++) {
        int id = tid + 256 * u;
        int j = id >> 6, c8 = id & 63;
        size_t roff = (size_t)(b * Cc + ch[j]) * Dd;
        uint4 va = ((const uint4*)(ah  + roff))[c8];
        uint4 vb = ((const uint4*)(bph + roff))[c8];
        const unsigned* pa = &va.x;
        const unsigned* pb = &vb.x;
        #pragma unroll
        for (int q = 0; q < 4; q++) {
            float2 fa = __half22float2(*(__half2*)&pa[q]);
            float2 fb = __half22float2(*(__half2*)&pb[q]);
            sa[j][c8 * 8 + 2 * q]     = fa.x;
            sa[j][c8 * 8 + 2 * q + 1] = fa.y;
            sb[j][c8 * 8 + 2 * q]     = fb.x;
            sb[j][c8 * 8 + 2 * q + 1] = fb.y;
        }
    }
    if (tid < 128) ((float4*)sw2)[tid] = ((const float4*)W2)[tid];
    __syncthreads();

    const int wid  = tid >> 5;
    const int lane = tid & 31;
    {
        float accq[Gg];
        #pragma unroll
        for (int q = 0; q < Gg; q++) accq[q] = 0.f;
        for (int t = lane; t < Dd; t += 32) {
            float av = sa[wid][t];
            float wv = sw2[t];
            #pragma unroll
            for (int q = 0; q < Gg; q++) {
                float v = av + sb[q][t];
                v = fmaxf(v, 0.f);
                accq[q] = fmaf(v, wv, accq[q]);
            }
        }
        #pragma unroll
        for (int q = 0; q < Gg; q++) {
            #pragma unroll
            for (int off = 16; off > 0; off >>= 1)
                accq[q] += __shfl_xor_sync(0xffffffffu, accq[q], off);
        }
        if (lane == 0) {
            float bb2 = b2[0];
            #pragma unroll
            for (int q = 0; q < Gg; q++) ssc[wid][q] = accq[q] + bb2;
        }
    }
    __syncthreads();

    if (tid < Gg) {
        int i = tid;
        float mx = -1e30f;
        #pragma unroll
        for (int j = 0; j < Gg; j++)
            if (j != i) mx = fmaxf(mx, ssc[i][j]);
        float e[Gg]; float s = 0.f;
        #pragma unroll
        for (int j = 0; j < Gg; j++) {
            e[j] = (j == i) ? 0.f : __expf(ssc[i][j] - mx);
            s += e[j];
        }
        float inv = 1.f / s;
        #pragma unroll
        for (int j = 0; j < Gg; j++) ww[i * Gg + j] = e[j] * inv;
    }
    __syncthreads();
    if (tid < 64) wout[(size_t)blk * 64 + tid] = ww[tid];

    // Phase 2: reuse sa for y1
    #pragma unroll
    for (int u = 0; u < 2; u++) {
        int id = tid + 256 * u;
        int j = id >> 6, c8 = id & 63;
        size_t roff = (size_t)(b * Cc + ch[j]) * Dd;
        uint4 vy = ((const uint4*)(y1h + roff))[c8];
        const unsigned* py = &vy.x;
        #pragma unroll
        for (int q = 0; q < 4; q++) {
            float2 fy = __half22float2(*(__half2*)&py[q]);
            sa[j][c8 * 8 + 2 * q]     = fy.x;
            sa[j][c8 * 8 + 2 * q + 1] = fy.y;
        }
    }
    __syncthreads();

    #pragma unroll
    for (int u = 0; u < 4; u++) {
        int id = tid + 256 * u;
        int i = id >> 7, d4 = id & 127;
        float wi[Gg];
        #pragma unroll
        for (int j = 0; j < Gg; j++) wi[j] = ww[i * Gg + j];
        float a0 = 0.f, a1 = 0.f, a2 = 0.f, a3 = 0.f;
        #pragma unroll
        for (int j = 0; j < Gg; j++) {
            const float* yr = &sa[j][d4 * 4];
            a0 = fmaf(wi[j], yr[0], a0);
            a1 = fmaf(wi[j], yr[1], a1);
            a2 = fmaf(wi[j], yr[2], a2);
            a3 = fmaf(wi[j], yr[3], a3);
        }
        size_t rowoff = (size_t)(b * Cc + ch[i]) * Dd;
        float4 bv = ((const float4*)bg1)[d4];
        uint2 xv = ((const uint2*)(xh + rowoff))[d4];
        float2 x01 = __half22float2(*(__half2*)&xv.x);
        float2 x23 = __half22float2(*(__half2*)&xv.y);
        float z0 = a0 + bv.x, z1 = a1 + bv.y, z2 = a2 + bv.z, z3 = a3 + bv.w;
        z0 = (z0 >= 0.f) ? z0 : 0.2f * z0;
        z1 = (z1 >= 0.f) ? z1 : 0.2f * z1;
        z2 = (z2 >= 0.f) ? z2 : 0.2f * z2;
        z3 = (z3 >= 0.f) ? z3 : 0.2f * z3;
        float v0 = 0.5f * z0 + 0.5f * x01.x;
        float v1 = 0.5f * z1 + 0.5f * x01.y;
        float v2 = 0.5f * z2 + 0.5f * x23.x;
        float v3 = 0.5f * z3 + 0.5f * x23.y;
        ((uint2*)(x1h + rowoff))[d4] = make_uint2(pack_half2(v0, v1), pack_half2(v2, v3));
    }
}

// ---------------------------------------------------------------------------
extern "C" void kernel_launch(void* const* d_in, const int* in_sizes, int n_in,
                              void* d_out, int out_size)
{
    const float* x    = (const float*)d_in[0];
    const float* W1   = (const float*)d_in[1];
    const float* b1   = (const float*)d_in[2];
    const float* W2   = (const float*)d_in[3];
    const float* b2   = (const float*)d_in[4];
    const float* Wg1  = (const float*)d_in[5];
    const float* bg1  = (const float*)d_in[6];
    const float* Wg2  = (const float*)d_in[7];
    const float* bg2  = (const float*)d_in[8];
    const int*   ridx = (const int*)d_in[9];
    float* out = (float*)d_out;

    float *gt, *gw;
    __half *xh, *x1h, *ahp, *bphp, *y1hp, *wbt, *wg2t;
    cudaGetSymbolAddress((void**)&gt,    g_t);
    cudaGetSymbolAddress((void**)&gw,    g_w);
    cudaGetSymbolAddress((void**)&xh,    g_xh);
    cudaGetSymbolAddress((void**)&x1h,   g_x1h);
    cudaGetSymbolAddress((void**)&ahp,   g_ah);
    cudaGetSymbolAddress((void**)&bphp,  g_bph);
    cudaGetSymbolAddress((void**)&y1hp,  g_y1h);
    cudaGetSymbolAddress((void**)&wbt,   g_wbt);
    cudaGetSymbolAddress((void**)&wg2t,  g_wg2t);

    const int SMEM128 = 3 * (128 * 40 + 64 * 40) * (int)sizeof(__half);  // 46080
    const int SMEM64  = 3 * ( 64 * 40 + 64 * 40) * (int)sizeof(__half);  // 30720
    cudaFuncSetAttribute(mgemm_kernel<5,128>, cudaFuncAttributeMaxDynamicSharedMemorySize, SMEM128);
    cudaFuncSetAttribute(mgemm_kernel<0,64>,  cudaFuncAttributeMaxDynamicSharedMemorySize, SMEM64);

    prep_kernel<<<1024, 256>>>(x, W1, Wg1, Wg2, xh, wbt, wg2t);

    // G1': [a | bp | y1] = x @ [W1a | W1b | Wg1]  -> fp16 outputs
    {
        dim3 grid(3 * Dd / 64, Mrows / 128);
        mgemm_kernel<5,128><<<grid, 256, SMEM128>>>(xh, wbt, b1, nullptr,
                                                    ahp, bphp, y1hp, 3 * Dd, Dd);
    }
    // Fused attention + agg1 (also exports adj for agg2x)
    attnagg_export_kernel<<<Bb * NREG, 256>>>(ahp, bphp, W2, b2, y1hp, xh,
                                              bg1, ridx, x1h, gw);
    // G3': t = x1 @ Wg2
    {
        dim3 grid(Oo / 64, Mrows / 64);
        mgemm_kernel<0,64><<<grid, 256, SMEM64>>>(x1h, wg2t, nullptr, gt,
                                                  nullptr, nullptr, nullptr, Oo, Dd);
    }
    // out = leaky(adj@t + bg2)
    agg2x_kernel<<<Bb * NREG, 256>>>(gw, gt, bg2, ridx, out);
}

// round 12
// speedup vs baseline: 6.1875x; 1.0305x over previous
#include <cuda_runtime.h>
#include <cuda_fp16.h>
#include <math.h>

#define Bb 64
#define Cc 64
#define Dd 512
#define Oo 256
#define NREG 8
#define Gg 8
#define Mrows (Bb*Cc)   // 4096

// ---------------- Scratch (device globals) ----------------
__device__ __half g_ah [Mrows*Dd];      // x @ W1a (fp16)
__device__ __half g_bph[Mrows*Dd];      // x @ W1b + b1 (fp16)
__device__ __half g_y1h[Mrows*Dd];      // x @ Wg1 (fp16)
__device__ __half g_xh [Mrows*Dd];      // x  (fp16)
__device__ __half g_m2h[Mrows*Dd];      // m2 = adj @ x1 (fp16)
__device__ __half g_wbt [3*Dd*Dd];      // [W1a^T; W1b^T; Wg1^T]  [n][k] fp16
__device__ __half g_wg2t[Oo*Dd];        // Wg2^T fp16

// ---------------- async / ldmatrix helpers ----------------
__device__ __forceinline__ void cpasync16(void* smem, const void* g)
{
    unsigned sa = (unsigned)__cvta_generic_to_shared(smem);
    asm volatile("cp.async.cg.shared.global [%0], [%1], 16;" :: "r"(sa), "l"(g));
}
__device__ __forceinline__ void cp_commit() { asm volatile("cp.async.commit_group;"); }
template<int N> __device__ __forceinline__ void cp_wait()
{
    asm volatile("cp.async.wait_group %0;" :: "n"(N));
}
__device__ __forceinline__ void ldmx4(unsigned& r0, unsigned& r1, unsigned& r2,
                                      unsigned& r3, const void* p)
{
    unsigned a = (unsigned)__cvta_generic_to_shared(p);
    asm volatile("ldmatrix.sync.aligned.m8n8.x4.shared.b16 {%0,%1,%2,%3}, [%4];"
        : "=r"(r0), "=r"(r1), "=r"(r2), "=r"(r3) : "r"(a));
}
__device__ __forceinline__ void mma_f16(float c[4],
    unsigned a0, unsigned a1, unsigned a2, unsigned a3,
    unsigned b0, unsigned b1)
{
    asm volatile(
        "mma.sync.aligned.m16n8k16.row.col.f32.f16.f16.f32 "
        "{%0,%1,%2,%3}, {%4,%5,%6,%7}, {%8,%9}, {%0,%1,%2,%3};\n"
        : "+f"(c[0]), "+f"(c[1]), "+f"(c[2]), "+f"(c[3])
        : "r"(a0), "r"(a1), "r"(a2), "r"(a3), "r"(b0), "r"(b1));
}
__device__ __forceinline__ unsigned pack_half2(float a, float b)
{
    __half2 h = __halves2half2(__float2half_rn(a), __float2half_rn(b));
    return *(unsigned*)&h;
}

// ---------------- Combined prep kernel ----------------
__device__ __forceinline__ void transpose_tile(
    const float* __restrict__ src, __half* __restrict__ dst,
    int K, int N, int tn, int tk)
{
    __shared__ float tile[32][33];
    const int tid = threadIdx.x;
    const int k0 = tk * 32, n0 = tn * 32;
    const int tx = tid & 31, ty = tid >> 5;
    #pragma unroll
    for (int i = 0; i < 4; i++)
        tile[ty + 8 * i][tx] = src[(size_t)(k0 + ty + 8 * i) * N + n0 + tx];
    __syncthreads();
    const int nr = tid >> 4;
    const int kp = tid & 15;
    #pragma unroll
    for (int i = 0; i < 2; i++) {
        int n = n0 + nr + 16 * i;
        float v0 = tile[2 * kp    ][nr + 16 * i];
        float v1 = tile[2 * kp + 1][nr + 16 * i];
        *(unsigned*)&dst[(size_t)n * K + k0 + 2 * kp] = pack_half2(v0, v1);
    }
}

__global__ __launch_bounds__(256)
void prep_kernel(const float* __restrict__ x, const float* __restrict__ W1,
                 const float* __restrict__ Wg1, const float* __restrict__ Wg2,
                 __half* __restrict__ xh,
                 __half* __restrict__ wbt, __half* __restrict__ wg2t)
{
    int b = blockIdx.x;
    if (b < 256) {
        transpose_tile(W1, wbt, Dd, Dd, b & 15, b >> 4);
    } else if (b < 512) {
        b -= 256;
        transpose_tile(W1 + (size_t)Dd * Dd, wbt + (size_t)Dd * Dd, Dd, Dd, b & 15, b >> 4);
    } else if (b < 768) {
        b -= 512;
        transpose_tile(Wg1, wbt + 2 * (size_t)Dd * Dd, Dd, Dd, b & 15, b >> 4);
    } else if (b < 896) {
        b -= 768;
        transpose_tile(Wg2, wg2t, Dd, Oo, b & 7, b >> 3);
    } else {
        b -= 896;
        const float4* src = (const float4*)x;
        uint2* dh = (uint2*)xh;
        const int n4 = Mrows * Dd / 4;
        for (int i = b * 256 + threadIdx.x; i < n4; i += 128 * 256) {
            float4 v = src[i];
            dh[i] = make_uint2(pack_half2(v.x, v.y), pack_half2(v.z, v.w));
        }
    }
}

// ---------------- fp16 tensor-core GEMM ----------------
// MODE 1: fp32 out, leaky(z + bias)
// MODE 5: triple fp16 route: col<512 -> Ch raw; 512..1023 -> C2h + bias; >=1024 -> C3h raw
template<int MODE, int BM>
__global__ __launch_bounds__(256, 2)
void mgemm_kernel(const __half* __restrict__ A, const __half* __restrict__ Bt,
                  const float* __restrict__ bias,
                  float* __restrict__ C,
                  __half* __restrict__ Ch, __half* __restrict__ C2h,
                  __half* __restrict__ C3h, int N, int K)
{
    constexpr int BN = 64, BK = 32, LDT = 40, STAGES = 3;
    constexpr int WROWS = BM / 32;
    constexpr int NT = WROWS;
    constexpr int P  = (WROWS / 2) ? WROWS / 2 : 1;
    constexpr int WCOLS = 8 * NT;
    constexpr int A_SZ = BM * LDT;
    constexpr int B_SZ = BN * LDT;
    constexpr int STG  = A_SZ + B_SZ;
    constexpr int ACH  = BM / 64;
    extern __shared__ __half dsm[];

    const int tid  = threadIdx.x;
    const int wid  = tid >> 5;
    const int lane = tid & 31;
    const int wm   = wid % WROWS;
    const int wn   = wid / WROWS;
    const int row0 = blockIdx.y * BM;
    const int col0 = blockIdx.x * BN;
    const int g = lane >> 2;
    const int t = lane & 3;
    const int lq = lane >> 3, li = lane & 7;
    const int fr_off = (lq & 1) * 8 + li;
    const int fk_off = (lq >> 1) * 8;

    float acc[2][NT][4];
    #pragma unroll
    for (int mt = 0; mt < 2; mt++)
        #pragma unroll
        for (int nt = 0; nt < NT; nt++)
            #pragma unroll
            for (int q = 0; q < 4; q++) acc[mt][nt][q] = 0.f;

    auto load_stage = [&](int st, int kt) {
        __half* sA = dsm + st * STG;
        __half* sB = sA + A_SZ;
        #pragma unroll
        for (int i = 0; i < ACH; i++) {
            int id = tid * ACH + i;
            int r = id >> 2, c = (id & 3) * 8;
            cpasync16(sA + r * LDT + c, A + (size_t)(row0 + r) * K + kt + c);
        }
        {
            int r = tid >> 2, c = (tid & 3) * 8;
            cpasync16(sB + r * LDT + c, Bt + (size_t)(col0 + r) * K + kt + c);
        }
    };

    const int nk = K / BK;
    load_stage(0, 0); cp_commit();
    load_stage(1, BK); cp_commit();

    for (int s = 0; s < nk; s++) {
        if (s + 2 < nk) { load_stage((s + 2) % STAGES, (s + 2) * BK); cp_commit(); cp_wait<2>(); }
        else if (s + 1 < nk) { cp_wait<1>(); }
        else { cp_wait<0>(); }
        __syncthreads();

        const int st = s % STAGES;
        __half* sA = dsm + st * STG;
        __half* sB = sA + A_SZ;

        #pragma unroll
        for (int kk = 0; kk < BK; kk += 16) {
            unsigned ah[2][4], bv[P][4];
            #pragma unroll
            for (int mt = 0; mt < 2; mt++) {
                const __half* pa = sA + (wm * 32 + mt * 16 + fr_off) * LDT + kk + fk_off;
                ldmx4(ah[mt][0], ah[mt][1], ah[mt][2], ah[mt][3], pa);
            }
            #pragma unroll
            for (int p = 0; p < P; p++) {
                const __half* pb = sB + (wn * WCOLS + p * 16 + fr_off) * LDT + kk + fk_off;
                ldmx4(bv[p][0], bv[p][1], bv[p][2], bv[p][3], pb);
            }
            #pragma unroll
            for (int mt = 0; mt < 2; mt++)
                #pragma unroll
                for (int nt = 0; nt < NT; nt++) {
                    const int p = nt >> 1, o = nt & 1;
                    mma_f16(acc[mt][nt], ah[mt][0], ah[mt][1], ah[mt][2], ah[mt][3],
                            bv[p][o], bv[p][2 + o]);
                }
        }
        __syncthreads();
    }

    #pragma unroll
    for (int mt = 0; mt < 2; mt++) {
        int rbase = row0 + wm * 32 + mt * 16;
        #pragma unroll
        for (int nt = 0; nt < NT; nt++) {
            int cb = col0 + wn * WCOLS + nt * 8 + 2 * t;
            #pragma unroll
            for (int h = 0; h < 2; h++) {
                int r = rbase + g + 8 * h;
                float v0 = acc[mt][nt][2*h];
                float v1 = acc[mt][nt][2*h + 1];
                if (MODE == 5) {
                    if (cb < Dd) {
                        *(unsigned*)&Ch[(size_t)r * Dd + cb] = pack_half2(v0, v1);
                    } else if (cb < 2 * Dd) {
                        int c2 = cb - Dd;
                        v0 += bias[c2]; v1 += bias[c2 + 1];
                        *(unsigned*)&C2h[(size_t)r * Dd + c2] = pack_half2(v0, v1);
                    } else {
                        int c3 = cb - 2 * Dd;
                        *(unsigned*)&C3h[(size_t)r * Dd + c3] = pack_half2(v0, v1);
                    }
                } else {
                    v0 += bias[cb]; v1 += bias[cb + 1];
                    v0 = (v0 >= 0.f) ? v0 : 0.2f * v0;
                    v1 = (v1 >= 0.f) ? v1 : 0.2f * v1;
                    *(float2*)(C + (size_t)r * N + cb) = make_float2(v0, v1);
                }
            }
        }
    }
}

// ---------------------------------------------------------------------------
// Fused attention + BOTH aggregations: per (b, r) block.
// Phase 1: scores from fp16 a/bp, softmax -> ww (shared only).
// Phase 2: x1 = 0.5*leaky(adj @ y1 + bg1) + 0.5*x  (fp32, in shared sb)
// Phase 3: m2 = adj @ x1 -> fp16 global
// ---------------------------------------------------------------------------
__global__ __launch_bounds__(256)
void attnagg2_kernel(const __half* __restrict__ ah, const __half* __restrict__ bph,
                     const float* __restrict__ W2, const float* __restrict__ b2,
                     const __half* __restrict__ y1h, const __half* __restrict__ xh,
                     const float* __restrict__ bg1, const int* __restrict__ ridx,
                     __half* __restrict__ m2h)
{
    __shared__ float sa[Gg][Dd];     // a, then y1
    __shared__ float sb[Gg][Dd];     // bp, then x1
    __shared__ float sw2[Dd];
    __shared__ float ssc[Gg][Gg];
    __shared__ float ww[Gg * Gg];
    __shared__ int   ch[Gg];

    const int tid  = threadIdx.x;
    const int blk  = blockIdx.x;
    const int b    = blk >> 3;
    const int r    = blk & 7;

    if (tid < Gg) ch[tid] = ridx[r * Gg + tid];
    __syncthreads();

    // Phase 1 load: fp16 a/bp -> fp32 shared (8 rows x 64 8-half chunks each)
    #pragma unroll
    for (int u = 0; u < 2; u++) {
        int id = tid + 256 * u;
        int j = id >> 6, c8 = id & 63;
        size_t roff = (size_t)(b * Cc + ch[j]) * Dd;
        uint4 va = ((const uint4*)(ah  + roff))[c8];
        uint4 vb = ((const uint4*)(bph + roff))[c8];
        const unsigned* pa = &va.x;
        const unsigned* pb = &vb.x;
        #pragma unroll
        for (int q = 0; q < 4; q++) {
            float2 fa = __half22float2(*(__half2*)&pa[q]);
            float2 fb = __half22float2(*(__half2*)&pb[q]);
            sa[j][c8 * 8 + 2 * q]     = fa.x;
            sa[j][c8 * 8 + 2 * q + 1] = fa.y;
            sb[j][c8 * 8 + 2 * q]     = fb.x;
            sb[j][c8 * 8 + 2 * q + 1] = fb.y;
        }
    }
    if (tid < 128) ((float4*)sw2)[tid] = ((const float4*)W2)[tid];
    __syncthreads();

    // Scores: warp i vs all 8 columns
    const int wid  = tid >> 5;
    const int lane = tid & 31;
    {
        float accq[Gg];
        #pragma unroll
        for (int q = 0; q < Gg; q++) accq[q] = 0.f;
        for (int t = lane; t < Dd; t += 32) {
            float av = sa[wid][t];
            float wv = sw2[t];
            #pragma unroll
            for (int q = 0; q < Gg; q++) {
                float v = av + sb[q][t];
                v = fmaxf(v, 0.f);
                accq[q] = fmaf(v, wv, accq[q]);
            }
        }
        #pragma unroll
        for (int q = 0; q < Gg; q++) {
            #pragma unroll
            for (int off = 16; off > 0; off >>= 1)
                accq[q] += __shfl_xor_sync(0xffffffffu, accq[q], off);
        }
        if (lane == 0) {
            float bb2 = b2[0];
            #pragma unroll
            for (int q = 0; q < Gg; q++) ssc[wid][q] = accq[q] + bb2;
        }
    }
    __syncthreads();

    // Softmax (exclude diagonal) -> ww
    if (tid < Gg) {
        int i = tid;
        float mx = -1e30f;
        #pragma unroll
        for (int j = 0; j < Gg; j++)
            if (j != i) mx = fmaxf(mx, ssc[i][j]);
        float e[Gg]; float s = 0.f;
        #pragma unroll
        for (int j = 0; j < Gg; j++) {
            e[j] = (j == i) ? 0.f : __expf(ssc[i][j] - mx);
            s += e[j];
        }
        float inv = 1.f / s;
        #pragma unroll
        for (int j = 0; j < Gg; j++) ww[i * Gg + j] = e[j] * inv;
    }
    __syncthreads();

    // Phase 2 load: y1 -> sa (overwrite a; scores complete)
    #pragma unroll
    for (int u = 0; u < 2; u++) {
        int id = tid + 256 * u;
        int j = id >> 6, c8 = id & 63;
        size_t roff = (size_t)(b * Cc + ch[j]) * Dd;
        uint4 vy = ((const uint4*)(y1h + roff))[c8];
        const unsigned* py = &vy.x;
        #pragma unroll
        for (int q = 0; q < 4; q++) {
            float2 fy = __half22float2(*(__half2*)&py[q]);
            sa[j][c8 * 8 + 2 * q]     = fy.x;
            sa[j][c8 * 8 + 2 * q + 1] = fy.y;
        }
    }
    __syncthreads();

    // x1 = 0.5*leaky(adj@y1 + bg1) + 0.5*x  -> sb (overwrite bp)
    #pragma unroll
    for (int u = 0; u < 4; u++) {
        int id = tid + 256 * u;
        int i = id >> 7, d4 = id & 127;
        float wi[Gg];
        #pragma unroll
        for (int j = 0; j < Gg; j++) wi[j] = ww[i * Gg + j];
        float a0 = 0.f, a1 = 0.f, a2 = 0.f, a3 = 0.f;
        #pragma unroll
        for (int j = 0; j < Gg; j++) {
            const float* yr = &sa[j][d4 * 4];
            a0 = fmaf(wi[j], yr[0], a0);
            a1 = fmaf(wi[j], yr[1], a1);
            a2 = fmaf(wi[j], yr[2], a2);
            a3 = fmaf(wi[j], yr[3], a3);
        }
        float4 bv = ((const float4*)bg1)[d4];
        uint2 xv = ((const uint2*)(xh + (size_t)(b * Cc + ch[i]) * Dd))[d4];
        float2 x01 = __half22float2(*(__half2*)&xv.x);
        float2 x23 = __half22float2(*(__half2*)&xv.y);
        float z0 = a0 + bv.x, z1 = a1 + bv.y, z2 = a2 + bv.z, z3 = a3 + bv.w;
        z0 = (z0 >= 0.f) ? z0 : 0.2f * z0;
        z1 = (z1 >= 0.f) ? z1 : 0.2f * z1;
        z2 = (z2 >= 0.f) ? z2 : 0.2f * z2;
        z3 = (z3 >= 0.f) ? z3 : 0.2f * z3;
        sb[i][d4 * 4    ] = 0.5f * z0 + 0.5f * x01.x;
        sb[i][d4 * 4 + 1] = 0.5f * z1 + 0.5f * x01.y;
        sb[i][d4 * 4 + 2] = 0.5f * z2 + 0.5f * x23.x;
        sb[i][d4 * 4 + 3] = 0.5f * z3 + 0.5f * x23.y;
    }
    __syncthreads();

    // Phase 3: m2 = adj @ x1 -> fp16 global
    #pragma unroll
    for (int u = 0; u < 4; u++) {
        int id = tid + 256 * u;
        int i = id >> 7, d4 = id & 127;
        float wi[Gg];
        #pragma unroll
        for (int j = 0; j < Gg; j++) wi[j] = ww[i * Gg + j];
        float a0 = 0.f, a1 = 0.f, a2 = 0.f, a3 = 0.f;
        #pragma unroll
        for (int j = 0; j < Gg; j++) {
            const float* xr = &sb[j][d4 * 4];
            a0 = fmaf(wi[j], xr[0], a0);
            a1 = fmaf(wi[j], xr[1], a1);
            a2 = fmaf(wi[j], xr[2], a2);
            a3 = fmaf(wi[j], xr[3], a3);
        }
        size_t rowoff = (size_t)(b * Cc + ch[i]) * Dd;
        ((uint2*)(m2h + rowoff))[d4] = make_uint2(pack_half2(a0, a1), pack_half2(a2, a3));
    }
}

// ---------------------------------------------------------------------------
extern "C" void kernel_launch(void* const* d_in, const int* in_sizes, int n_in,
                              void* d_out, int out_size)
{
    const float* x    = (const float*)d_in[0];
    const float* W1   = (const float*)d_in[1];
    const float* b1   = (const float*)d_in[2];
    const float* W2   = (const float*)d_in[3];
    const float* b2   = (const float*)d_in[4];
    const float* Wg1  = (const float*)d_in[5];
    const float* bg1  = (const float*)d_in[6];
    const float* Wg2  = (const float*)d_in[7];
    const float* bg2  = (const float*)d_in[8];
    const int*   ridx = (const int*)d_in[9];
    float* out = (float*)d_out;

    __half *xh, *ahp, *bphp, *y1hp, *m2h, *wbt, *wg2t;
    cudaGetSymbolAddress((void**)&xh,    g_xh);
    cudaGetSymbolAddress((void**)&ahp,   g_ah);
    cudaGetSymbolAddress((void**)&bphp,  g_bph);
    cudaGetSymbolAddress((void**)&y1hp,  g_y1h);
    cudaGetSymbolAddress((void**)&m2h,   g_m2h);
    cudaGetSymbolAddress((void**)&wbt,   g_wbt);
    cudaGetSymbolAddress((void**)&wg2t,  g_wg2t);

    const int SMEM128 = 3 * (128 * 40 + 64 * 40) * (int)sizeof(__half);  // 46080
    cudaFuncSetAttribute(mgemm_kernel<5,128>, cudaFuncAttributeMaxDynamicSharedMemorySize, SMEM128);
    cudaFuncSetAttribute(mgemm_kernel<1,128>, cudaFuncAttributeMaxDynamicSharedMemorySize, SMEM128);

    prep_kernel<<<1024, 256>>>(x, W1, Wg1, Wg2, xh, wbt, wg2t);

    // G1': [a | bp | y1] = x @ [W1a | W1b | Wg1]  -> fp16 outputs
    {
        dim3 grid(3 * Dd / 64, Mrows / 128);
        mgemm_kernel<5,128><<<grid, 256, SMEM128>>>(xh, wbt, b1, nullptr,
                                                    ahp, bphp, y1hp, 3 * Dd, Dd);
    }
    // Fused attention + agg1 + agg2 -> m2 fp16
    attnagg2_kernel<<<Bb * NREG, 256>>>(ahp, bphp, W2, b2, y1hp, xh,
                                        bg1, ridx, m2h);
    // out = leaky(m2 @ Wg2 + bg2)
    {
        dim3 grid(Oo / 64, Mrows / 128);   // 4 x 32 = 128 CTAs
        mgemm_kernel<1,128><<<grid, 256, SMEM128>>>(m2h, wg2t, bg2, out,
                                                    nullptr, nullptr, nullptr, Oo, Dd);
    }
}